// round 2
// baseline (speedup 1.0000x reference)
#include <cuda_runtime.h>
#include <cstdint>

#define Nn 1024
#define Tt 512
#define Hh 128
#define Gg 512
#define NTT (Nn*Tt)

// ---------------- device scratch ----------------
__device__ float g_xg[(size_t)NTT * Gg];      // 1 GB: feat @ w_ih^T
__device__ float g_h[2][(size_t)NTT * Hh];    // h_fw, h_bw  [n*T+t][128]
__device__ float g_whh_t[Hh * Gg];            // [k][j]
__device__ float g_wih_t[Hh * Gg];            // [k][j]
__device__ float g_enc2t[Hh * Hh];            // [k][o]
__device__ float g_dec1t[2 * Hh * Hh];        // [k(256)][o(128)]

__device__ __forceinline__ float sigm(float x) { return 1.f / (1.f + __expf(-x)); }

__device__ __forceinline__ void cp16(void* smem_dst, const void* gsrc) {
    unsigned s = (unsigned)__cvta_generic_to_shared(smem_dst);
    asm volatile("cp.async.ca.shared.global [%0], [%1], 16;" :: "r"(s), "l"(gsrc));
}
__device__ __forceinline__ void cp_commit() { asm volatile("cp.async.commit_group;"); }
__device__ __forceinline__ void cp_wait1()  { asm volatile("cp.async.wait_group 1;"); }
__device__ __forceinline__ void cp_wait0()  { asm volatile("cp.async.wait_group 0;"); }

// ---------------- K0: weight transposes ----------------
__global__ void prep_kernel(const float* __restrict__ wih, const float* __restrict__ whh,
                            const float* __restrict__ enc2, const float* __restrict__ dec1) {
    int i = blockIdx.x * blockDim.x + threadIdx.x;
    if (i < Hh * Gg) {
        int k = i / Gg, j = i % Gg;
        g_wih_t[i] = wih[j * Hh + k];
        g_whh_t[i] = whh[j * Hh + k];
    }
    if (i < Hh * Hh) {
        int k = i / Hh, o = i % Hh;
        g_enc2t[i] = enc2[o * Hh + k];
    }
    if (i < 2 * Hh * Hh) {
        int k = i / Hh, o = i % Hh;
        g_dec1t[i] = dec1[o * 2 * Hh + k];
    }
}

// ---------------- K1: encoder + input projection ----------------
// 64 rows/block (row = n*T+t). F1(relu) -> F2(+b2) -> XG = F2 @ w_ih^T
#define ENC_SMEM ((128*64 + 128*64 + 128*128) * 4)
__global__ __launch_bounds__(256, 1) void encoder_kernel(
    const float* __restrict__ x, const float* __restrict__ e1w,
    const float* __restrict__ e1b, const float* __restrict__ e2b) {
    extern __shared__ float smem[];
    float* sA  = smem;                 // [128][64]  F1^T
    float* sA2 = smem + 128 * 64;      // [128][64]  F2^T
    float* sW  = smem + 2 * 128 * 64;  // [128][128]
    __shared__ float sX[64][2];

    int tid = threadIdx.x;
    int row0 = blockIdx.x * 64;

    if (tid < 64) {
        sX[tid][0] = x[(size_t)(row0 + tid) * 2];
        sX[tid][1] = x[(size_t)(row0 + tid) * 2 + 1];
    }
    __syncthreads();

    // Phase A: F1^T[h][r]
#pragma unroll
    for (int it = 0; it < 32; it++) {
        int idx = it * 256 + tid;
        int h = idx >> 6, r = idx & 63;
        float v = e1w[2 * h] * sX[r][0] + e1w[2 * h + 1] * sX[r][1] + e1b[h];
        sA[h * 64 + r] = fmaxf(v, 0.f);
    }
#pragma unroll
    for (int it = 0; it < 16; it++) {
        int f4 = it * 256 + tid;
        ((float4*)sW)[f4] = ((const float4*)g_enc2t)[f4];
    }
    __syncthreads();

    // Phase B: F2^T[o][r] = sum_k enc2t[k][o]*F1t[k][r] + b2[o]
    {
        int tro = tid >> 4, tcr = tid & 15;
        float acc[8][4];
#pragma unroll
        for (int a = 0; a < 8; a++)
#pragma unroll
            for (int b = 0; b < 4; b++) acc[a][b] = 0.f;
#pragma unroll 4
        for (int k = 0; k < 128; k++) {
            float4 a0 = *(const float4*)&sW[k * 128 + tro * 8];
            float4 a1 = *(const float4*)&sW[k * 128 + tro * 8 + 4];
            float4 bb = *(const float4*)&sA[k * 64 + tcr * 4];
            float av[8] = {a0.x, a0.y, a0.z, a0.w, a1.x, a1.y, a1.z, a1.w};
            float bv[4] = {bb.x, bb.y, bb.z, bb.w};
#pragma unroll
            for (int a = 0; a < 8; a++)
#pragma unroll
                for (int b = 0; b < 4; b++) acc[a][b] += av[a] * bv[b];
        }
        __syncthreads();  // done reading sA/sW before overwrite below
#pragma unroll
        for (int a = 0; a < 8; a++) {
            int o = tro * 8 + a;
            float bo = e2b[o];
            *(float4*)&sA2[o * 64 + tcr * 4] =
                make_float4(acc[a][0] + bo, acc[a][1] + bo, acc[a][2] + bo, acc[a][3] + bo);
        }
        __syncthreads();
    }

    // Phase C: XG[r][j] = sum_o F2t[o][r]*wih_t[o][j], 4 chunks of 128 j
    int trr = tid >> 4, tcj = tid & 15;
    for (int ch = 0; ch < 4; ch++) {
#pragma unroll
        for (int it = 0; it < 16; it++) {
            int f4 = it * 256 + tid;
            int k = f4 >> 5, j4 = f4 & 31;
            ((float4*)&sW[k * 128])[j4] = ((const float4*)(g_wih_t + k * 512 + ch * 128))[j4];
        }
        __syncthreads();

        float acc[4][8];
#pragma unroll
        for (int a = 0; a < 4; a++)
#pragma unroll
            for (int b = 0; b < 8; b++) acc[a][b] = 0.f;
#pragma unroll 4
        for (int k = 0; k < 128; k++) {
            float4 aa = *(const float4*)&sA2[k * 64 + trr * 4];
            float4 b0 = *(const float4*)&sW[k * 128 + tcj * 8];
            float4 b1 = *(const float4*)&sW[k * 128 + tcj * 8 + 4];
            float av[4] = {aa.x, aa.y, aa.z, aa.w};
            float bv[8] = {b0.x, b0.y, b0.z, b0.w, b1.x, b1.y, b1.z, b1.w};
#pragma unroll
            for (int a = 0; a < 4; a++)
#pragma unroll
                for (int b = 0; b < 8; b++) acc[a][b] += av[a] * bv[b];
        }
#pragma unroll
        for (int a = 0; a < 4; a++) {
            size_t row = row0 + trr * 4 + a;
            float* dst = &g_xg[row * 512 + ch * 128 + tcj * 8];
            *(float4*)dst       = make_float4(acc[a][0], acc[a][1], acc[a][2], acc[a][3]);
            *(float4*)(dst + 4) = make_float4(acc[a][4], acc[a][5], acc[a][6], acc[a][7]);
        }
        __syncthreads();
    }
}

// ---------------- K2: bidirectional LSTM ----------------
#define REC_SW (128 * 128)
#define REC_HT (128 * 20)
#define REC_G  (16 * 512)
#define REC_SMEM ((2 * REC_SW + REC_HT + REC_G) * 4)

__device__ __forceinline__ void rec_load_chunk(float* buf, int ch, int tid) {
#pragma unroll
    for (int it = 0; it < 32; it++) {
        int f4 = it * 128 + tid;
        int k = f4 >> 5, j4 = f4 & 31;
        cp16(&buf[k * 128 + j4 * 4], g_whh_t + k * 512 + ch * 128 + j4 * 4);
    }
}

__global__ __launch_bounds__(128, 1) void lstm_kernel() {
    extern __shared__ float smem[];
    float* sW  = smem;                       // 2 x [128][128]
    float* sHt = smem + 2 * REC_SW;          // [128][20] h^T
    float* sG  = smem + 2 * REC_SW + REC_HT; // [16][512]

    int tid = threadIdx.x;
    int dir = blockIdx.x & 1;
    int n0 = (blockIdx.x >> 1) * 16;
    int trm = tid >> 5, tcj = tid & 31;

    for (int i = tid; i < REC_HT; i += 128) sHt[i] = 0.f;
    float c_reg[16];
#pragma unroll
    for (int i = 0; i < 16; i++) c_reg[i] = 0.f;
    __syncthreads();

    rec_load_chunk(sW, 0, tid);
    cp_commit();

    for (int cc = 0; cc < 512 * 4; cc++) {
        int ch = cc & 3;
        float* cw = sW + (cc & 1) * REC_SW;
        if (cc + 1 < 512 * 4) {
            rec_load_chunk(sW + ((cc + 1) & 1) * REC_SW, (cc + 1) & 3, tid);
            cp_commit();
            cp_wait1();
        } else {
            cp_wait0();
        }
        __syncthreads();

        float acc[4][4];
#pragma unroll
        for (int a = 0; a < 4; a++)
#pragma unroll
            for (int b = 0; b < 4; b++) acc[a][b] = 0.f;
#pragma unroll 4
        for (int k = 0; k < 128; k++) {
            float4 aa = *(const float4*)&sHt[k * 20 + trm * 4];
            float4 bb = *(const float4*)&cw[k * 128 + tcj * 4];
            acc[0][0] += aa.x*bb.x; acc[0][1] += aa.x*bb.y; acc[0][2] += aa.x*bb.z; acc[0][3] += aa.x*bb.w;
            acc[1][0] += aa.y*bb.x; acc[1][1] += aa.y*bb.y; acc[1][2] += aa.y*bb.z; acc[1][3] += aa.y*bb.w;
            acc[2][0] += aa.z*bb.x; acc[2][1] += aa.z*bb.y; acc[2][2] += aa.z*bb.z; acc[2][3] += aa.z*bb.w;
            acc[3][0] += aa.w*bb.x; acc[3][1] += aa.w*bb.y; acc[3][2] += aa.w*bb.z; acc[3][3] += aa.w*bb.w;
        }
#pragma unroll
        for (int a = 0; a < 4; a++)
            *(float4*)&sG[(trm * 4 + a) * 512 + ch * 128 + tcj * 4] =
                make_float4(acc[a][0], acc[a][1], acc[a][2], acc[a][3]);
        __syncthreads();

        if (ch == 3) {
            int step = cc >> 2;
            int t = dir ? (511 - step) : step;
#pragma unroll
            for (int i = 0; i < 16; i++) {
                size_t row = (size_t)(n0 + i) * Tt + t;
                const float* xgr = g_xg + row * 512;
                int k = tid;
                float gi = sG[i * 512 + k]       + xgr[k];
                float gf = sG[i * 512 + 128 + k] + xgr[128 + k];
                float gg = sG[i * 512 + 256 + k] + xgr[256 + k];
                float go = sG[i * 512 + 384 + k] + xgr[384 + k];
                float c = sigm(gf) * c_reg[i] + sigm(gi) * tanhf(gg);
                c_reg[i] = c;
                float h = sigm(go) * tanhf(c);
                sHt[k * 20 + i] = h;
                g_h[dir][row * 128 + k] = h;
            }
            __syncthreads();
        }
    }
}

// ---------------- K3: decoder ----------------
#define DEC_HC (256 * 68)
#define DEC_WD (256 * 128)
#define DEC_SMEM ((DEC_HC + DEC_WD + 64 * 16) * 4)
__global__ __launch_bounds__(256, 1) void decoder_kernel(
    const float* __restrict__ d1b, const float* __restrict__ d2w,
    const float* __restrict__ d2b, float* __restrict__ out) {
    extern __shared__ float smem[];
    float* sHc = smem;                 // [256][68] relu(hcat)^T
    float* sWd = smem + DEC_HC;        // [256][128] dec1^T
    float* sPart = smem + DEC_HC + DEC_WD;  // [64][16]

    int tid = threadIdx.x;
    int row0 = blockIdx.x * 64;

#pragma unroll
    for (int it = 0; it < 32; it++) {
        int f4 = it * 256 + tid;
        ((float4*)sWd)[f4] = ((const float4*)g_dec1t)[f4];
    }
    for (int d = 0; d < 2; d++) {
#pragma unroll
        for (int it = 0; it < 32; it++) {
            int idx = it * 256 + tid;
            int r = idx >> 7, k = idx & 127;
            sHc[(d * 128 + k) * 68 + r] = fmaxf(g_h[d][(size_t)(row0 + r) * 128 + k], 0.f);
        }
    }
    __syncthreads();

    int tro = tid >> 4, tcr = tid & 15;
    float acc[8][4];
#pragma unroll
    for (int a = 0; a < 8; a++)
#pragma unroll
        for (int b = 0; b < 4; b++) acc[a][b] = 0.f;
#pragma unroll 4
    for (int k = 0; k < 256; k++) {
        float4 a0 = *(const float4*)&sWd[k * 128 + tro * 8];
        float4 a1 = *(const float4*)&sWd[k * 128 + tro * 8 + 4];
        float4 bb = *(const float4*)&sHc[k * 68 + tcr * 4];
        float av[8] = {a0.x, a0.y, a0.z, a0.w, a1.x, a1.y, a1.z, a1.w};
        float bv[4] = {bb.x, bb.y, bb.z, bb.w};
#pragma unroll
        for (int a = 0; a < 8; a++)
#pragma unroll
            for (int b = 0; b < 4; b++) acc[a][b] += av[a] * bv[b];
    }
    float p[4] = {0.f, 0.f, 0.f, 0.f};
#pragma unroll
    for (int a = 0; a < 8; a++) {
        int o = tro * 8 + a;
        float bo = d1b[o], w2 = d2w[o];
#pragma unroll
        for (int b = 0; b < 4; b++) p[b] += fmaxf(acc[a][b] + bo, 0.f) * w2;
    }
#pragma unroll
    for (int b = 0; b < 4; b++) sPart[(tcr * 4 + b) * 16 + tro] = p[b];
    __syncthreads();

    if (tid < 64) {
        float s = 0.f;
#pragma unroll
        for (int g = 0; g < 16; g++) s += sPart[tid * 16 + g];
        out[row0 + tid] = s + d2b[0];
    }
}

// ---------------- launch ----------------
extern "C" void kernel_launch(void* const* d_in, const int* in_sizes, int n_in,
                              void* d_out, int out_size) {
    (void)in_sizes; (void)n_in; (void)out_size;
    const float* x    = (const float*)d_in[0];
    const float* e1w  = (const float*)d_in[1];
    const float* e1b  = (const float*)d_in[2];
    const float* e2w  = (const float*)d_in[3];
    const float* e2b  = (const float*)d_in[4];
    const float* wih  = (const float*)d_in[5];
    const float* whh  = (const float*)d_in[6];
    const float* d1w  = (const float*)d_in[7];
    const float* d1b  = (const float*)d_in[8];
    const float* d2w  = (const float*)d_in[9];
    const float* d2b  = (const float*)d_in[10];
    float* out = (float*)d_out;

    static bool attr_done = false;
    if (!attr_done) {
        cudaFuncSetAttribute(encoder_kernel, cudaFuncAttributeMaxDynamicSharedMemorySize, ENC_SMEM);
        cudaFuncSetAttribute(lstm_kernel, cudaFuncAttributeMaxDynamicSharedMemorySize, REC_SMEM);
        cudaFuncSetAttribute(decoder_kernel, cudaFuncAttributeMaxDynamicSharedMemorySize, DEC_SMEM);
        attr_done = true;
    }

    prep_kernel<<<256, 256>>>(wih, whh, e2w, d1w);
    encoder_kernel<<<NTT / 64, 256, ENC_SMEM>>>(x, e1w, e1b, e2b);
    lstm_kernel<<<128, 128, REC_SMEM>>>();
    decoder_kernel<<<NTT / 64, 256, DEC_SMEM>>>(d1b, d2w, d2b, out);
}

// round 3
// speedup vs baseline: 2.5392x; 2.5392x over previous
#include <cuda_runtime.h>
#include <cuda_fp16.h>
#include <cstdint>

#define Nn 1024
#define Tt 512
#define Hh 128
#define Gg 512
#define NTT (Nn*Tt)
#define WPAD 136
#define SGS 516

// ---------------- device scratch ----------------
__device__ float g_xg[(size_t)NTT * Gg];      // 1 GB: feat @ w_ih^T
__device__ float g_h[2][(size_t)NTT * Hh];    // h_fw, h_bw  [n*T+t][128]
__device__ __half g_whh_h[512 * WPAD];        // fp16 w_hh padded [j][k]
__device__ float g_wih_t[Hh * Gg];            // [k][j]
__device__ float g_enc2t[Hh * Hh];            // [k][o]
__device__ float g_dec1t[2 * Hh * Hh];        // [k(256)][o(128)]

__device__ __forceinline__ float sigm(float x) { return __fdividef(1.f, 1.f + __expf(-x)); }
__device__ __forceinline__ float tanh_f(float x) {
    return 1.f - __fdividef(2.f, __expf(2.f * x) + 1.f);
}

__device__ __forceinline__ void cp16(void* smem_dst, const void* gsrc) {
    unsigned s = (unsigned)__cvta_generic_to_shared(smem_dst);
    asm volatile("cp.async.ca.shared.global [%0], [%1], 16;" :: "r"(s), "l"(gsrc));
}
__device__ __forceinline__ void cp_commit() { asm volatile("cp.async.commit_group;"); }
__device__ __forceinline__ void cp_wait0()  { asm volatile("cp.async.wait_group 0;"); }

__device__ __forceinline__ void ldsm4(uint32_t addr, uint32_t& r0, uint32_t& r1,
                                      uint32_t& r2, uint32_t& r3) {
    asm volatile("ldmatrix.sync.aligned.m8n8.x4.shared.b16 {%0,%1,%2,%3}, [%4];"
                 : "=r"(r0), "=r"(r1), "=r"(r2), "=r"(r3) : "r"(addr));
}
__device__ __forceinline__ void mma16816(float* d, uint32_t a0, uint32_t a1, uint32_t a2,
                                         uint32_t a3, uint32_t b0, uint32_t b1) {
    asm volatile(
        "mma.sync.aligned.m16n8k16.row.col.f32.f16.f16.f32 "
        "{%0,%1,%2,%3}, {%4,%5,%6,%7}, {%8,%9}, {%0,%1,%2,%3};"
        : "+f"(d[0]), "+f"(d[1]), "+f"(d[2]), "+f"(d[3])
        : "r"(a0), "r"(a1), "r"(a2), "r"(a3), "r"(b0), "r"(b1));
}

// ---------------- K0: weight prep ----------------
__global__ void prep_kernel(const float* __restrict__ wih, const float* __restrict__ whh,
                            const float* __restrict__ enc2, const float* __restrict__ dec1) {
    int i = blockIdx.x * blockDim.x + threadIdx.x;
    if (i < Hh * Gg) {
        int k = i / Gg, j = i % Gg;
        g_wih_t[i] = wih[j * Hh + k];
    }
    if (i < 512 * WPAD) {
        int j = i / WPAD, k = i % WPAD;
        g_whh_h[i] = (k < 128) ? __float2half(whh[j * 128 + k]) : __float2half(0.f);
    }
    if (i < Hh * Hh) {
        int k = i / Hh, o = i % Hh;
        g_enc2t[i] = enc2[o * Hh + k];
    }
    if (i < 2 * Hh * Hh) {
        int k = i / Hh, o = i % Hh;
        g_dec1t[i] = dec1[o * 2 * Hh + k];
    }
}

// ---------------- K1: encoder + input projection (unchanged, passing) ----------------
#define ENC_SMEM ((128*64 + 128*64 + 128*128) * 4)
__global__ __launch_bounds__(256, 1) void encoder_kernel(
    const float* __restrict__ x, const float* __restrict__ e1w,
    const float* __restrict__ e1b, const float* __restrict__ e2b) {
    extern __shared__ float smem[];
    float* sA  = smem;
    float* sA2 = smem + 128 * 64;
    float* sW  = smem + 2 * 128 * 64;
    __shared__ float sX[64][2];

    int tid = threadIdx.x;
    int row0 = blockIdx.x * 64;

    if (tid < 64) {
        sX[tid][0] = x[(size_t)(row0 + tid) * 2];
        sX[tid][1] = x[(size_t)(row0 + tid) * 2 + 1];
    }
    __syncthreads();

#pragma unroll
    for (int it = 0; it < 32; it++) {
        int idx = it * 256 + tid;
        int h = idx >> 6, r = idx & 63;
        float v = e1w[2 * h] * sX[r][0] + e1w[2 * h + 1] * sX[r][1] + e1b[h];
        sA[h * 64 + r] = fmaxf(v, 0.f);
    }
#pragma unroll
    for (int it = 0; it < 16; it++) {
        int f4 = it * 256 + tid;
        ((float4*)sW)[f4] = ((const float4*)g_enc2t)[f4];
    }
    __syncthreads();

    {
        int tro = tid >> 4, tcr = tid & 15;
        float acc[8][4];
#pragma unroll
        for (int a = 0; a < 8; a++)
#pragma unroll
            for (int b = 0; b < 4; b++) acc[a][b] = 0.f;
#pragma unroll 4
        for (int k = 0; k < 128; k++) {
            float4 a0 = *(const float4*)&sW[k * 128 + tro * 8];
            float4 a1 = *(const float4*)&sW[k * 128 + tro * 8 + 4];
            float4 bb = *(const float4*)&sA[k * 64 + tcr * 4];
            float av[8] = {a0.x, a0.y, a0.z, a0.w, a1.x, a1.y, a1.z, a1.w};
            float bv[4] = {bb.x, bb.y, bb.z, bb.w};
#pragma unroll
            for (int a = 0; a < 8; a++)
#pragma unroll
                for (int b = 0; b < 4; b++) acc[a][b] += av[a] * bv[b];
        }
        __syncthreads();
#pragma unroll
        for (int a = 0; a < 8; a++) {
            int o = tro * 8 + a;
            float bo = e2b[o];
            *(float4*)&sA2[o * 64 + tcr * 4] =
                make_float4(acc[a][0] + bo, acc[a][1] + bo, acc[a][2] + bo, acc[a][3] + bo);
        }
        __syncthreads();
    }

    int trr = tid >> 4, tcj = tid & 15;
    for (int ch = 0; ch < 4; ch++) {
#pragma unroll
        for (int it = 0; it < 16; it++) {
            int f4 = it * 256 + tid;
            int k = f4 >> 5, j4 = f4 & 31;
            ((float4*)&sW[k * 128])[j4] = ((const float4*)(g_wih_t + k * 512 + ch * 128))[j4];
        }
        __syncthreads();

        float acc[4][8];
#pragma unroll
        for (int a = 0; a < 4; a++)
#pragma unroll
            for (int b = 0; b < 8; b++) acc[a][b] = 0.f;
#pragma unroll 4
        for (int k = 0; k < 128; k++) {
            float4 aa = *(const float4*)&sA2[k * 64 + trr * 4];
            float4 b0 = *(const float4*)&sW[k * 128 + tcj * 8];
            float4 b1 = *(const float4*)&sW[k * 128 + tcj * 8 + 4];
            float av[4] = {aa.x, aa.y, aa.z, aa.w};
            float bv[8] = {b0.x, b0.y, b0.z, b0.w, b1.x, b1.y, b1.z, b1.w};
#pragma unroll
            for (int a = 0; a < 4; a++)
#pragma unroll
                for (int b = 0; b < 8; b++) acc[a][b] += av[a] * bv[b];
        }
#pragma unroll
        for (int a = 0; a < 4; a++) {
            size_t row = row0 + trr * 4 + a;
            float* dst = &g_xg[row * 512 + ch * 128 + tcj * 8];
            *(float4*)dst       = make_float4(acc[a][0], acc[a][1], acc[a][2], acc[a][3]);
            *(float4*)(dst + 4) = make_float4(acc[a][4], acc[a][5], acc[a][6], acc[a][7]);
        }
        __syncthreads();
    }
}

// ---------------- K2: bidirectional LSTM via mma.sync fp16 (2-MMA h-split) ----------------
// smem layout (bytes):
//   sW   [512][136] half : 139264
//   sHhi [16][136] half  :   4352
//   sHlo [16][136] half  :   4352
//   sG   [16][516] float :  33024
//   sXG  [16][516] float :  33024
#define OFF_HHI 139264
#define OFF_HLO 143616
#define OFF_G   147968
#define OFF_XG  180992
#define REC_SMEM (OFF_XG + 33024)

__global__ __launch_bounds__(128, 1) void lstm_kernel() {
    extern __shared__ char smraw[];
    __half* sW   = (__half*)smraw;
    __half* sHhi = (__half*)(smraw + OFF_HHI);
    __half* sHlo = (__half*)(smraw + OFF_HLO);
    float*  sG   = (float*)(smraw + OFF_G);
    float*  sXG  = (float*)(smraw + OFF_XG);

    int tid = threadIdx.x;
    int w = tid >> 5, l = tid & 31;
    int dir = blockIdx.x & 1;
    int n0 = (blockIdx.x >> 1) * 16;

    // load W_hh fp16 (139264 B = 8704 uint4)
    {
        const uint4* src = (const uint4*)g_whh_h;
        uint4* dst = (uint4*)sW;
        for (int i = tid; i < 8704; i += 128) dst[i] = src[i];
    }
    // zero h_hi / h_lo (2 * 4352 B = 2176 u32, contiguous)
    for (int i = tid; i < 2176; i += 128) ((uint32_t*)sHhi)[i] = 0u;

    float c[16];
#pragma unroll
    for (int i = 0; i < 16; i++) c[i] = 0.f;

    const int lrow = (l & 7) + ((l >> 3) & 1) * 8;
    const int lcol = (l >> 4) * 8;
    const int jw = w * 128;
    const int m_act = tid >> 3;
    const int kc = (tid & 7) * 16;

    uint32_t sWb   = (uint32_t)__cvta_generic_to_shared(sW);
    uint32_t sHhib = (uint32_t)__cvta_generic_to_shared(sHhi);
    uint32_t sHlob = (uint32_t)__cvta_generic_to_shared(sHlo);

    __syncthreads();

    for (int step = 0; step < 512; step++) {
        int t = dir ? (511 - step) : step;

        // prefetch xg for this step into sXG (hidden under MMA)
#pragma unroll
        for (int it = 0; it < 16; it++) {
            int idx = it * 128 + tid;
            int m = idx >> 7, q = idx & 127;
            const float* src = g_xg + ((size_t)(n0 + m) * Tt + t) * 512 + q * 4;
            cp16(sXG + m * SGS + q * 4, src);
        }
        cp_commit();

        // gates = h_hi @ W^T + h_lo @ W^T
        float d[16][4];
#pragma unroll
        for (int nt = 0; nt < 16; nt++)
#pragma unroll
            for (int e = 0; e < 4; e++) d[nt][e] = 0.f;

#pragma unroll
        for (int ks = 0; ks < 8; ks++) {
            int k0 = ks * 16;
            uint32_t aoff = (uint32_t)((lrow * WPAD + k0 + lcol) << 1);
            uint32_t ah0, ah1, ah2, ah3, al0, al1, al2, al3;
            ldsm4(sHhib + aoff, ah0, ah1, ah2, ah3);
            ldsm4(sHlob + aoff, al0, al1, al2, al3);
#pragma unroll
            for (int np = 0; np < 8; np++) {
                int j0 = jw + np * 16;
                uint32_t b0, b1, b2, b3;
                ldsm4(sWb + (uint32_t)(((j0 + lrow) * WPAD + k0 + lcol) << 1), b0, b1, b2, b3);
                mma16816(d[2 * np],     ah0, ah1, ah2, ah3, b0, b2);
                mma16816(d[2 * np],     al0, al1, al2, al3, b0, b2);
                mma16816(d[2 * np + 1], ah0, ah1, ah2, ah3, b1, b3);
                mma16816(d[2 * np + 1], al0, al1, al2, al3, b1, b3);
            }
        }

        // fragments -> sG
        int g = l >> 2, tg = l & 3;
#pragma unroll
        for (int nt = 0; nt < 16; nt++) {
            int col = jw + nt * 8 + 2 * tg;
            *(float2*)&sG[g * SGS + col]       = make_float2(d[nt][0], d[nt][1]);
            *(float2*)&sG[(g + 8) * SGS + col] = make_float2(d[nt][2], d[nt][3]);
        }
        cp_wait0();
        __syncthreads();

        // activation: thread -> chain m_act, hidden cols [kc, kc+16)
        {
            size_t row = (size_t)(n0 + m_act) * Tt + t;
            float* gh = &g_h[dir][row * 128 + kc];
            const float* xb = &sXG[m_act * SGS];
            const float* gb = &sG[m_act * SGS];
#pragma unroll
            for (int q = 0; q < 4; q++) {
                int k = kc + q * 4;
                float4 xi = *(const float4*)&xb[k];
                float4 xf = *(const float4*)&xb[128 + k];
                float4 xg4 = *(const float4*)&xb[256 + k];
                float4 xo = *(const float4*)&xb[384 + k];
                float4 ri = *(const float4*)&gb[k];
                float4 rf = *(const float4*)&gb[128 + k];
                float4 rg = *(const float4*)&gb[256 + k];
                float4 ro = *(const float4*)&gb[384 + k];
                float iv[4] = {ri.x + xi.x, ri.y + xi.y, ri.z + xi.z, ri.w + xi.w};
                float fv[4] = {rf.x + xf.x, rf.y + xf.y, rf.z + xf.z, rf.w + xf.w};
                float gv[4] = {rg.x + xg4.x, rg.y + xg4.y, rg.z + xg4.z, rg.w + xg4.w};
                float ov[4] = {ro.x + xo.x, ro.y + xo.y, ro.z + xo.z, ro.w + xo.w};
                float hv[4];
#pragma unroll
                for (int e = 0; e < 4; e++) {
                    float cn = sigm(fv[e]) * c[q * 4 + e] + sigm(iv[e]) * tanh_f(gv[e]);
                    c[q * 4 + e] = cn;
                    hv[e] = sigm(ov[e]) * tanh_f(cn);
                }
                *(float4*)&gh[q * 4] = make_float4(hv[0], hv[1], hv[2], hv[3]);
                __half2 p0 = __floats2half2_rn(hv[0], hv[1]);
                __half2 p1 = __floats2half2_rn(hv[2], hv[3]);
                *(__half2*)&sHhi[m_act * WPAD + k]     = p0;
                *(__half2*)&sHhi[m_act * WPAD + k + 2] = p1;
                __half2 q0 = __floats2half2_rn(hv[0] - __low2float(p0), hv[1] - __high2float(p0));
                __half2 q1 = __floats2half2_rn(hv[2] - __low2float(p1), hv[3] - __high2float(p1));
                *(__half2*)&sHlo[m_act * WPAD + k]     = q0;
                *(__half2*)&sHlo[m_act * WPAD + k + 2] = q1;
            }
        }
        __syncthreads();
    }
}

// ---------------- K3: decoder (unchanged, passing) ----------------
#define DEC_HC (256 * 68)
#define DEC_WD (256 * 128)
#define DEC_SMEM ((DEC_HC + DEC_WD + 64 * 16) * 4)
__global__ __launch_bounds__(256, 1) void decoder_kernel(
    const float* __restrict__ d1b, const float* __restrict__ d2w,
    const float* __restrict__ d2b, float* __restrict__ out) {
    extern __shared__ float smem[];
    float* sHc = smem;
    float* sWd = smem + DEC_HC;
    float* sPart = smem + DEC_HC + DEC_WD;

    int tid = threadIdx.x;
    int row0 = blockIdx.x * 64;

#pragma unroll
    for (int it = 0; it < 32; it++) {
        int f4 = it * 256 + tid;
        ((float4*)sWd)[f4] = ((const float4*)g_dec1t)[f4];
    }
    for (int d = 0; d < 2; d++) {
#pragma unroll
        for (int it = 0; it < 32; it++) {
            int idx = it * 256 + tid;
            int r = idx >> 7, k = idx & 127;
            sHc[(d * 128 + k) * 68 + r] = fmaxf(g_h[d][(size_t)(row0 + r) * 128 + k], 0.f);
        }
    }
    __syncthreads();

    int tro = tid >> 4, tcr = tid & 15;
    float acc[8][4];
#pragma unroll
    for (int a = 0; a < 8; a++)
#pragma unroll
        for (int b = 0; b < 4; b++) acc[a][b] = 0.f;
#pragma unroll 4
    for (int k = 0; k < 256; k++) {
        float4 a0 = *(const float4*)&sWd[k * 128 + tro * 8];
        float4 a1 = *(const float4*)&sWd[k * 128 + tro * 8 + 4];
        float4 bb = *(const float4*)&sHc[k * 68 + tcr * 4];
        float av[8] = {a0.x, a0.y, a0.z, a0.w, a1.x, a1.y, a1.z, a1.w};
        float bv[4] = {bb.x, bb.y, bb.z, bb.w};
#pragma unroll
        for (int a = 0; a < 8; a++)
#pragma unroll
            for (int b = 0; b < 4; b++) acc[a][b] += av[a] * bv[b];
    }
    float p[4] = {0.f, 0.f, 0.f, 0.f};
#pragma unroll
    for (int a = 0; a < 8; a++) {
        int o = tro * 8 + a;
        float bo = d1b[o], w2 = d2w[o];
#pragma unroll
        for (int b = 0; b < 4; b++) p[b] += fmaxf(acc[a][b] + bo, 0.f) * w2;
    }
#pragma unroll
    for (int b = 0; b < 4; b++) sPart[(tcr * 4 + b) * 16 + tro] = p[b];
    __syncthreads();

    if (tid < 64) {
        float s = 0.f;
#pragma unroll
        for (int g = 0; g < 16; g++) s += sPart[tid * 16 + g];
        out[row0 + tid] = s + d2b[0];
    }
}

// ---------------- launch ----------------
extern "C" void kernel_launch(void* const* d_in, const int* in_sizes, int n_in,
                              void* d_out, int out_size) {
    (void)in_sizes; (void)n_in; (void)out_size;
    const float* x    = (const float*)d_in[0];
    const float* e1w  = (const float*)d_in[1];
    const float* e1b  = (const float*)d_in[2];
    const float* e2w  = (const float*)d_in[3];
    const float* e2b  = (const float*)d_in[4];
    const float* wih  = (const float*)d_in[5];
    const float* whh  = (const float*)d_in[6];
    const float* d1w  = (const float*)d_in[7];
    const float* d1b  = (const float*)d_in[8];
    const float* d2w  = (const float*)d_in[9];
    const float* d2b  = (const float*)d_in[10];
    float* out = (float*)d_out;

    static bool attr_done = false;
    if (!attr_done) {
        cudaFuncSetAttribute(encoder_kernel, cudaFuncAttributeMaxDynamicSharedMemorySize, ENC_SMEM);
        cudaFuncSetAttribute(lstm_kernel, cudaFuncAttributeMaxDynamicSharedMemorySize, REC_SMEM);
        cudaFuncSetAttribute(decoder_kernel, cudaFuncAttributeMaxDynamicSharedMemorySize, DEC_SMEM);
        attr_done = true;
    }

    prep_kernel<<<384, 256>>>(wih, whh, e2w, d1w);
    encoder_kernel<<<NTT / 64, 256, ENC_SMEM>>>(x, e1w, e1b, e2b);
    lstm_kernel<<<128, 128, REC_SMEM>>>();
    decoder_kernel<<<NTT / 64, 256, DEC_SMEM>>>(d1b, d2w, d2b, out);
}

// round 4
// speedup vs baseline: 4.0765x; 1.6055x over previous
#include <cuda_runtime.h>
#include <cuda_fp16.h>
#include <cstdint>

#define Nn 1024
#define Tt 512
#define Hh 128
#define Gg 512
#define NTT (Nn*Tt)
#define WPAD 136
#define SGS 516

// ---------------- device scratch ----------------
__device__ float g_xg[(size_t)NTT * Gg];      // 1 GB: xg = F1 @ M^T + bxg
__device__ float g_h[2][(size_t)NTT * Hh];    // h_fw, h_bw  [n*T+t][128]
__device__ __half g_whh_h[512 * WPAD];        // fp16 w_hh [j][k] padded
__device__ __half g_M_h[512 * WPAD];          // fp16 M = wih@e2w  [j][h] padded
__device__ float  g_bxg[512];                 // wih @ b2
__device__ __half g_dec1h[128 * 264];         // fp16 dec1 [o][k] padded (k stride 264)

__device__ __forceinline__ float sigm(float x) { return __fdividef(1.f, 1.f + __expf(-x)); }
__device__ __forceinline__ float tanh_f(float x) {
    return 1.f - __fdividef(2.f, __expf(2.f * x) + 1.f);
}

__device__ __forceinline__ void cp16(void* smem_dst, const void* gsrc) {
    unsigned s = (unsigned)__cvta_generic_to_shared(smem_dst);
    asm volatile("cp.async.ca.shared.global [%0], [%1], 16;" :: "r"(s), "l"(gsrc));
}
__device__ __forceinline__ void cp_commit() { asm volatile("cp.async.commit_group;"); }
__device__ __forceinline__ void cp_wait0()  { asm volatile("cp.async.wait_group 0;"); }

__device__ __forceinline__ void ldsm4(uint32_t addr, uint32_t& r0, uint32_t& r1,
                                      uint32_t& r2, uint32_t& r3) {
    asm volatile("ldmatrix.sync.aligned.m8n8.x4.shared.b16 {%0,%1,%2,%3}, [%4];"
                 : "=r"(r0), "=r"(r1), "=r"(r2), "=r"(r3) : "r"(addr));
}
__device__ __forceinline__ void mma16816(float* d, uint32_t a0, uint32_t a1, uint32_t a2,
                                         uint32_t a3, uint32_t b0, uint32_t b1) {
    asm volatile(
        "mma.sync.aligned.m16n8k16.row.col.f32.f16.f16.f32 "
        "{%0,%1,%2,%3}, {%4,%5,%6,%7}, {%8,%9}, {%0,%1,%2,%3};"
        : "+f"(d[0]), "+f"(d[1]), "+f"(d[2]), "+f"(d[3])
        : "r"(a0), "r"(a1), "r"(a2), "r"(a3), "r"(b0), "r"(b1));
}

// ---------------- K0: weight prep ----------------
// i <  65536           : M[j,h] = sum_o wih[j,o]*e2w[o,h]  -> fp16 [j*136+h]
// 65536  .. 66048      : bxg[j] = sum_o e2b[o]*wih[j,o]
// 66048  .. 135680     : whh fp16 padded (512*136)
// 135680 .. 169472     : dec1 fp16 padded (128*264)
__global__ void prep_kernel(const float* __restrict__ wih, const float* __restrict__ whh,
                            const float* __restrict__ e2w, const float* __restrict__ e2b,
                            const float* __restrict__ dec1) {
    int i = blockIdx.x * blockDim.x + threadIdx.x;
    if (i < 65536) {
        int j = i >> 7, h = i & 127;
        float s = 0.f;
#pragma unroll 4
        for (int o = 0; o < 128; o++) s += wih[j * 128 + o] * e2w[o * 128 + h];
        g_M_h[j * WPAD + h] = __float2half(s);
    } else if (i < 66048) {
        int j = i - 65536;
        float s = 0.f;
#pragma unroll 4
        for (int o = 0; o < 128; o++) s += e2b[o] * wih[j * 128 + o];
        g_bxg[j] = s;
    } else if (i < 135680) {
        int p = i - 66048;
        int j = p / WPAD, k = p % WPAD;
        g_whh_h[p] = (k < 128) ? __float2half(whh[j * 128 + k]) : __float2half(0.f);
    } else if (i < 169472) {
        int p = i - 135680;
        int j = p / 264, k = p % 264;
        g_dec1h[p] = (k < 256) ? __float2half(dec1[j * 256 + k]) : __float2half(0.f);
    }
}

// ---------------- K1: encoder (persistent, tensor-core) ----------------
// xg[r,j] = F1[r,:] @ M[j,:] + bxg[j],  F1 split hi/lo fp16, M fp16.
#define ENC_OFF_AHI 139264
#define ENC_OFF_ALO 156672
#define ENC_OFF_BXG 174080
#define ENC_OFF_E1W 176128
#define ENC_OFF_E1B 177152
#define ENC_SMEM    177664
__global__ __launch_bounds__(128, 1) void encoder_kernel(
    const float* __restrict__ x, const float* __restrict__ e1w,
    const float* __restrict__ e1b) {
    extern __shared__ char smraw[];
    __half* sM   = (__half*)smraw;
    __half* sAhi = (__half*)(smraw + ENC_OFF_AHI);
    __half* sAlo = (__half*)(smraw + ENC_OFF_ALO);
    float*  sBxg = (float*)(smraw + ENC_OFF_BXG);
    float*  sE1w = (float*)(smraw + ENC_OFF_E1W);
    float*  sE1b = (float*)(smraw + ENC_OFF_E1B);

    int tid = threadIdx.x, w = tid >> 5, l = tid & 31;

    for (int i = tid; i < 8704; i += 128) cp16(((uint4*)sM) + i, ((const uint4*)g_M_h) + i);
    cp_commit();
    for (int i = tid; i < 512; i += 128) sBxg[i] = g_bxg[i];
    for (int i = tid; i < 256; i += 128) sE1w[i] = e1w[i];
    if (tid < 128) sE1b[tid] = e1b[tid];
    cp_wait0();
    __syncthreads();

    const int lrow = (l & 7) + ((l >> 3) & 1) * 8;
    const int lcol = (l >> 4) * 8;
    const int jw = w * 128;
    const int g = l >> 2, tg = l & 3;
    uint32_t sMb   = (uint32_t)__cvta_generic_to_shared(sM);
    uint32_t sAhib = (uint32_t)__cvta_generic_to_shared(sAhi);
    uint32_t sAlob = (uint32_t)__cvta_generic_to_shared(sAlo);

    const int fr = tid >> 1, fh0 = (tid & 1) * 64;

    for (int blk = blockIdx.x; blk < NTT / 64; blk += gridDim.x) {
        int row0 = blk * 64;
        // F1 for 64 rows
        float x0 = x[(size_t)(row0 + fr) * 2];
        float x1 = x[(size_t)(row0 + fr) * 2 + 1];
#pragma unroll
        for (int hh = 0; hh < 64; hh += 2) {
            int h = fh0 + hh;
            float v0 = fmaxf(sE1w[2 * h]     * x0 + sE1w[2 * h + 1] * x1 + sE1b[h], 0.f);
            float v1 = fmaxf(sE1w[2 * h + 2] * x0 + sE1w[2 * h + 3] * x1 + sE1b[h + 1], 0.f);
            __half2 p = __floats2half2_rn(v0, v1);
            *(__half2*)&sAhi[fr * WPAD + h] = p;
            __half2 q = __floats2half2_rn(v0 - __low2float(p), v1 - __high2float(p));
            *(__half2*)&sAlo[fr * WPAD + h] = q;
        }
        __syncthreads();

#pragma unroll
        for (int mt = 0; mt < 4; mt++) {
            float d[16][4];
#pragma unroll
            for (int nt = 0; nt < 16; nt++)
#pragma unroll
                for (int e = 0; e < 4; e++) d[nt][e] = 0.f;
#pragma unroll
            for (int ks = 0; ks < 8; ks++) {
                uint32_t aoff = (uint32_t)(((mt * 16 + lrow) * WPAD + ks * 16 + lcol) << 1);
                uint32_t ah0, ah1, ah2, ah3, al0, al1, al2, al3;
                ldsm4(sAhib + aoff, ah0, ah1, ah2, ah3);
                ldsm4(sAlob + aoff, al0, al1, al2, al3);
#pragma unroll
                for (int np = 0; np < 8; np++) {
                    uint32_t boff = (uint32_t)(((jw + np * 16 + lrow) * WPAD + ks * 16 + lcol) << 1);
                    uint32_t b0, b1, b2, b3;
                    ldsm4(sMb + boff, b0, b1, b2, b3);
                    mma16816(d[2 * np],     ah0, ah1, ah2, ah3, b0, b2);
                    mma16816(d[2 * np],     al0, al1, al2, al3, b0, b2);
                    mma16816(d[2 * np + 1], ah0, ah1, ah2, ah3, b1, b3);
                    mma16816(d[2 * np + 1], al0, al1, al2, al3, b1, b3);
                }
            }
            size_t rb0 = (size_t)(row0 + mt * 16 + g) * 512;
            size_t rb1 = rb0 + (size_t)8 * 512;
#pragma unroll
            for (int nt = 0; nt < 16; nt++) {
                int col = jw + nt * 8 + 2 * tg;
                float b0v = sBxg[col], b1v = sBxg[col + 1];
                *(float2*)&g_xg[rb0 + col] = make_float2(d[nt][0] + b0v, d[nt][1] + b1v);
                *(float2*)&g_xg[rb1 + col] = make_float2(d[nt][2] + b0v, d[nt][3] + b1v);
            }
        }
        __syncthreads();
    }
}

// ---------------- K2: bidirectional LSTM (unchanged from R3, passing) ----------------
#define OFF_HHI 139264
#define OFF_HLO 143616
#define OFF_G   147968
#define OFF_XG  180992
#define REC_SMEM (OFF_XG + 33024)

__global__ __launch_bounds__(128, 1) void lstm_kernel() {
    extern __shared__ char smraw[];
    __half* sW   = (__half*)smraw;
    __half* sHhi = (__half*)(smraw + OFF_HHI);
    __half* sHlo = (__half*)(smraw + OFF_HLO);
    float*  sG   = (float*)(smraw + OFF_G);
    float*  sXG  = (float*)(smraw + OFF_XG);

    int tid = threadIdx.x;
    int w = tid >> 5, l = tid & 31;
    int dir = blockIdx.x & 1;
    int n0 = (blockIdx.x >> 1) * 16;

    {
        const uint4* src = (const uint4*)g_whh_h;
        uint4* dst = (uint4*)sW;
        for (int i = tid; i < 8704; i += 128) dst[i] = src[i];
    }
    for (int i = tid; i < 2176; i += 128) ((uint32_t*)sHhi)[i] = 0u;

    float c[16];
#pragma unroll
    for (int i = 0; i < 16; i++) c[i] = 0.f;

    const int lrow = (l & 7) + ((l >> 3) & 1) * 8;
    const int lcol = (l >> 4) * 8;
    const int jw = w * 128;
    const int m_act = tid >> 3;
    const int kc = (tid & 7) * 16;

    uint32_t sWb   = (uint32_t)__cvta_generic_to_shared(sW);
    uint32_t sHhib = (uint32_t)__cvta_generic_to_shared(sHhi);
    uint32_t sHlob = (uint32_t)__cvta_generic_to_shared(sHlo);

    __syncthreads();

    for (int step = 0; step < 512; step++) {
        int t = dir ? (511 - step) : step;

#pragma unroll
        for (int it = 0; it < 16; it++) {
            int idx = it * 128 + tid;
            int m = idx >> 7, q = idx & 127;
            const float* src = g_xg + ((size_t)(n0 + m) * Tt + t) * 512 + q * 4;
            cp16(sXG + m * SGS + q * 4, src);
        }
        cp_commit();

        float d[16][4];
#pragma unroll
        for (int nt = 0; nt < 16; nt++)
#pragma unroll
            for (int e = 0; e < 4; e++) d[nt][e] = 0.f;

#pragma unroll
        for (int ks = 0; ks < 8; ks++) {
            int k0 = ks * 16;
            uint32_t aoff = (uint32_t)((lrow * WPAD + k0 + lcol) << 1);
            uint32_t ah0, ah1, ah2, ah3, al0, al1, al2, al3;
            ldsm4(sHhib + aoff, ah0, ah1, ah2, ah3);
            ldsm4(sHlob + aoff, al0, al1, al2, al3);
#pragma unroll
            for (int np = 0; np < 8; np++) {
                int j0 = jw + np * 16;
                uint32_t b0, b1, b2, b3;
                ldsm4(sWb + (uint32_t)(((j0 + lrow) * WPAD + k0 + lcol) << 1), b0, b1, b2, b3);
                mma16816(d[2 * np],     ah0, ah1, ah2, ah3, b0, b2);
                mma16816(d[2 * np],     al0, al1, al2, al3, b0, b2);
                mma16816(d[2 * np + 1], ah0, ah1, ah2, ah3, b1, b3);
                mma16816(d[2 * np + 1], al0, al1, al2, al3, b1, b3);
            }
        }

        int g = l >> 2, tg = l & 3;
#pragma unroll
        for (int nt = 0; nt < 16; nt++) {
            int col = jw + nt * 8 + 2 * tg;
            *(float2*)&sG[g * SGS + col]       = make_float2(d[nt][0], d[nt][1]);
            *(float2*)&sG[(g + 8) * SGS + col] = make_float2(d[nt][2], d[nt][3]);
        }
        cp_wait0();
        __syncthreads();

        {
            size_t row = (size_t)(n0 + m_act) * Tt + t;
            float* gh = &g_h[dir][row * 128 + kc];
            const float* xb = &sXG[m_act * SGS];
            const float* gb = &sG[m_act * SGS];
#pragma unroll
            for (int q = 0; q < 4; q++) {
                int k = kc + q * 4;
                float4 xi = *(const float4*)&xb[k];
                float4 xf = *(const float4*)&xb[128 + k];
                float4 xg4 = *(const float4*)&xb[256 + k];
                float4 xo = *(const float4*)&xb[384 + k];
                float4 ri = *(const float4*)&gb[k];
                float4 rf = *(const float4*)&gb[128 + k];
                float4 rg = *(const float4*)&gb[256 + k];
                float4 ro = *(const float4*)&gb[384 + k];
                float iv[4] = {ri.x + xi.x, ri.y + xi.y, ri.z + xi.z, ri.w + xi.w};
                float fv[4] = {rf.x + xf.x, rf.y + xf.y, rf.z + xf.z, rf.w + xf.w};
                float gv[4] = {rg.x + xg4.x, rg.y + xg4.y, rg.z + xg4.z, rg.w + xg4.w};
                float ov[4] = {ro.x + xo.x, ro.y + xo.y, ro.z + xo.z, ro.w + xo.w};
                float hv[4];
#pragma unroll
                for (int e = 0; e < 4; e++) {
                    float cn = sigm(fv[e]) * c[q * 4 + e] + sigm(iv[e]) * tanh_f(gv[e]);
                    c[q * 4 + e] = cn;
                    hv[e] = sigm(ov[e]) * tanh_f(cn);
                }
                *(float4*)&gh[q * 4] = make_float4(hv[0], hv[1], hv[2], hv[3]);
                __half2 p0 = __floats2half2_rn(hv[0], hv[1]);
                __half2 p1 = __floats2half2_rn(hv[2], hv[3]);
                *(__half2*)&sHhi[m_act * WPAD + k]     = p0;
                *(__half2*)&sHhi[m_act * WPAD + k + 2] = p1;
                __half2 q0 = __floats2half2_rn(hv[0] - __low2float(p0), hv[1] - __high2float(p0));
                __half2 q1 = __floats2half2_rn(hv[2] - __low2float(p1), hv[3] - __high2float(p1));
                *(__half2*)&sHlo[m_act * WPAD + k]     = q0;
                *(__half2*)&sHlo[m_act * WPAD + k + 2] = q1;
            }
        }
        __syncthreads();
    }
}

// ---------------- K3: decoder (persistent, tensor-core) ----------------
// q1 = relu(relu(hcat) @ dec1^T + b1); out = q1 . d2w + b2
#define DEC_OFF_AHI 67584
#define DEC_OFF_ALO 101376
#define DEC_OFF_PART 135168
#define DEC_SMEM (DEC_OFF_PART + 64 * 17 * 4)
__global__ __launch_bounds__(128, 1) void decoder_kernel(
    const float* __restrict__ d1b, const float* __restrict__ d2w,
    const float* __restrict__ d2b, float* __restrict__ out) {
    extern __shared__ char smraw[];
    __half* sB   = (__half*)smraw;                    // [128][264] dec1 fp16
    __half* sAhi = (__half*)(smraw + DEC_OFF_AHI);    // [64][264]
    __half* sAlo = (__half*)(smraw + DEC_OFF_ALO);    // [64][264]
    float*  sPart = (float*)(smraw + DEC_OFF_PART);   // [64][17]

    int tid = threadIdx.x, w = tid >> 5, l = tid & 31;

    for (int i = tid; i < 4224; i += 128) cp16(((uint4*)sB) + i, ((const uint4*)g_dec1h) + i);
    cp_commit();

    const int lrow = (l & 7) + ((l >> 3) & 1) * 8;
    const int lcol = (l >> 4) * 8;
    const int jw = w * 32;
    const int g = l >> 2, tg = l & 3;
    uint32_t sBb   = (uint32_t)__cvta_generic_to_shared(sB);
    uint32_t sAhib = (uint32_t)__cvta_generic_to_shared(sAhi);
    uint32_t sAlob = (uint32_t)__cvta_generic_to_shared(sAlo);

    // per-thread bias/output-weight for its 8 columns
    float b1v[4][2], w2v[4][2];
#pragma unroll
    for (int nt = 0; nt < 4; nt++)
#pragma unroll
        for (int e = 0; e < 2; e++) {
            int col = jw + nt * 8 + 2 * tg + e;
            b1v[nt][e] = d1b[col];
            w2v[nt][e] = d2w[col];
        }
    float outb = d2b[0];

    cp_wait0();
    __syncthreads();

    for (int blk = blockIdx.x; blk < NTT / 64; blk += gridDim.x) {
        int row0 = blk * 64;
        // A = relu(hcat) split hi/lo
#pragma unroll
        for (int dd = 0; dd < 2; dd++)
#pragma unroll
            for (int it = 0; it < 16; it++) {
                int idx = it * 128 + tid;
                int r = idx >> 5, k4 = idx & 31;
                float4 v = *(const float4*)&g_h[dd][(size_t)(row0 + r) * 128 + k4 * 4];
                float v0 = fmaxf(v.x, 0.f), v1 = fmaxf(v.y, 0.f);
                float v2 = fmaxf(v.z, 0.f), v3 = fmaxf(v.w, 0.f);
                int kb = dd * 128 + k4 * 4;
                __half2 p0 = __floats2half2_rn(v0, v1);
                __half2 p1 = __floats2half2_rn(v2, v3);
                *(__half2*)&sAhi[r * 264 + kb]     = p0;
                *(__half2*)&sAhi[r * 264 + kb + 2] = p1;
                __half2 q0 = __floats2half2_rn(v0 - __low2float(p0), v1 - __high2float(p0));
                __half2 q1 = __floats2half2_rn(v2 - __low2float(p1), v3 - __high2float(p1));
                *(__half2*)&sAlo[r * 264 + kb]     = q0;
                *(__half2*)&sAlo[r * 264 + kb + 2] = q1;
            }
        __syncthreads();

#pragma unroll
        for (int mt = 0; mt < 4; mt++) {
            float d[4][4];
#pragma unroll
            for (int nt = 0; nt < 4; nt++)
#pragma unroll
                for (int e = 0; e < 4; e++) d[nt][e] = 0.f;
#pragma unroll
            for (int ks = 0; ks < 16; ks++) {
                uint32_t aoff = (uint32_t)(((mt * 16 + lrow) * 264 + ks * 16 + lcol) << 1);
                uint32_t ah0, ah1, ah2, ah3, al0, al1, al2, al3;
                ldsm4(sAhib + aoff, ah0, ah1, ah2, ah3);
                ldsm4(sAlob + aoff, al0, al1, al2, al3);
#pragma unroll
                for (int np = 0; np < 2; np++) {
                    uint32_t boff = (uint32_t)(((jw + np * 16 + lrow) * 264 + ks * 16 + lcol) << 1);
                    uint32_t b0, b1, b2, b3;
                    ldsm4(sBb + boff, b0, b1, b2, b3);
                    mma16816(d[2 * np],     ah0, ah1, ah2, ah3, b0, b2);
                    mma16816(d[2 * np],     al0, al1, al2, al3, b0, b2);
                    mma16816(d[2 * np + 1], ah0, ah1, ah2, ah3, b1, b3);
                    mma16816(d[2 * np + 1], al0, al1, al2, al3, b1, b3);
                }
            }
            float p0 = 0.f, p1 = 0.f;
#pragma unroll
            for (int nt = 0; nt < 4; nt++) {
                p0 += fmaxf(d[nt][0] + b1v[nt][0], 0.f) * w2v[nt][0];
                p0 += fmaxf(d[nt][1] + b1v[nt][1], 0.f) * w2v[nt][1];
                p1 += fmaxf(d[nt][2] + b1v[nt][0], 0.f) * w2v[nt][0];
                p1 += fmaxf(d[nt][3] + b1v[nt][1], 0.f) * w2v[nt][1];
            }
            sPart[(mt * 16 + g) * 17 + w * 4 + tg]     = p0;
            sPart[(mt * 16 + g + 8) * 17 + w * 4 + tg] = p1;
        }
        __syncthreads();

        if (tid < 64) {
            float s = 0.f;
#pragma unroll
            for (int q = 0; q < 16; q++) s += sPart[tid * 17 + q];
            out[row0 + tid] = s + outb;
        }
        __syncthreads();
    }
}

// ---------------- launch ----------------
extern "C" void kernel_launch(void* const* d_in, const int* in_sizes, int n_in,
                              void* d_out, int out_size) {
    (void)in_sizes; (void)n_in; (void)out_size;
    const float* x    = (const float*)d_in[0];
    const float* e1w  = (const float*)d_in[1];
    const float* e1b  = (const float*)d_in[2];
    const float* e2w  = (const float*)d_in[3];
    const float* e2b  = (const float*)d_in[4];
    const float* wih  = (const float*)d_in[5];
    const float* whh  = (const float*)d_in[6];
    const float* d1w  = (const float*)d_in[7];
    const float* d1b  = (const float*)d_in[8];
    const float* d2w  = (const float*)d_in[9];
    const float* d2b  = (const float*)d_in[10];
    float* out = (float*)d_out;

    static bool attr_done = false;
    if (!attr_done) {
        cudaFuncSetAttribute(encoder_kernel, cudaFuncAttributeMaxDynamicSharedMemorySize, ENC_SMEM);
        cudaFuncSetAttribute(lstm_kernel, cudaFuncAttributeMaxDynamicSharedMemorySize, REC_SMEM);
        cudaFuncSetAttribute(decoder_kernel, cudaFuncAttributeMaxDynamicSharedMemorySize, DEC_SMEM);
        attr_done = true;
    }

    prep_kernel<<<662, 256>>>(wih, whh, e2w, e2b, d1w);
    encoder_kernel<<<148, 128, ENC_SMEM>>>(x, e1w, e1b);
    lstm_kernel<<<128, 128, REC_SMEM>>>();
    decoder_kernel<<<148, 128, DEC_SMEM>>>(d1b, d2w, d2b, out);
}

// round 5
// speedup vs baseline: 4.5526x; 1.1168x over previous
#include <cuda_runtime.h>
#include <cuda_fp16.h>
#include <cstdint>

#define Nn 1024
#define Tt 512
#define Hh 128
#define Gg 512
#define NTT (Nn*Tt)
#define WPAD 136

// ---------------- device scratch ----------------
__device__ float g_xg[(size_t)NTT * Gg];      // 1 GB: xg = F1 @ M^T + bxg
__device__ float g_h[2][(size_t)NTT * Hh];    // h_fw, h_bw  [n*T+t][128]
__device__ __half g_whh_h[512 * WPAD];        // fp16 w_hh [j][k] padded
__device__ __half g_M_h[512 * WPAD];          // fp16 M = wih@e2w  [j][h] padded
__device__ float  g_bxg[512];                 // wih @ b2
__device__ __half g_dec1h[128 * 264];         // fp16 dec1 [o][k] padded (k stride 264)

__device__ __forceinline__ float sigm(float x) { return __fdividef(1.f, 1.f + __expf(-x)); }
__device__ __forceinline__ float tanh_f(float x) {
    return 1.f - __fdividef(2.f, __expf(2.f * x) + 1.f);
}

__device__ __forceinline__ void cp16(void* smem_dst, const void* gsrc) {
    unsigned s = (unsigned)__cvta_generic_to_shared(smem_dst);
    asm volatile("cp.async.ca.shared.global [%0], [%1], 16;" :: "r"(s), "l"(gsrc));
}
__device__ __forceinline__ void cp_commit() { asm volatile("cp.async.commit_group;"); }
__device__ __forceinline__ void cp_wait0()  { asm volatile("cp.async.wait_group 0;"); }

__device__ __forceinline__ void ldsm4(uint32_t addr, uint32_t& r0, uint32_t& r1,
                                      uint32_t& r2, uint32_t& r3) {
    asm volatile("ldmatrix.sync.aligned.m8n8.x4.shared.b16 {%0,%1,%2,%3}, [%4];"
                 : "=r"(r0), "=r"(r1), "=r"(r2), "=r"(r3) : "r"(addr));
}
__device__ __forceinline__ void mma16816(float* d, uint32_t a0, uint32_t a1, uint32_t a2,
                                         uint32_t a3, uint32_t b0, uint32_t b1) {
    asm volatile(
        "mma.sync.aligned.m16n8k16.row.col.f32.f16.f16.f32 "
        "{%0,%1,%2,%3}, {%4,%5,%6,%7}, {%8,%9}, {%0,%1,%2,%3};"
        : "+f"(d[0]), "+f"(d[1]), "+f"(d[2]), "+f"(d[3])
        : "r"(a0), "r"(a1), "r"(a2), "r"(a3), "r"(b0), "r"(b1));
}

// ---------------- K0: weight prep ----------------
__global__ void prep_kernel(const float* __restrict__ wih, const float* __restrict__ whh,
                            const float* __restrict__ e2w, const float* __restrict__ e2b,
                            const float* __restrict__ dec1) {
    int i = blockIdx.x * blockDim.x + threadIdx.x;
    if (i < 65536) {
        int j = i >> 7, h = i & 127;
        float s = 0.f;
#pragma unroll 4
        for (int o = 0; o < 128; o++) s += wih[j * 128 + o] * e2w[o * 128 + h];
        g_M_h[j * WPAD + h] = __float2half(s);
    } else if (i < 66048) {
        int j = i - 65536;
        float s = 0.f;
#pragma unroll 4
        for (int o = 0; o < 128; o++) s += e2b[o] * wih[j * 128 + o];
        g_bxg[j] = s;
    } else if (i < 135680) {
        int p = i - 66048;
        int j = p / WPAD, k = p % WPAD;
        g_whh_h[p] = (k < 128) ? __float2half(whh[j * 128 + k]) : __float2half(0.f);
    } else if (i < 169472) {
        int p = i - 135680;
        int j = p / 264, k = p % 264;
        g_dec1h[p] = (k < 256) ? __float2half(dec1[j * 256 + k]) : __float2half(0.f);
    }
}

// ---------------- K1: encoder (persistent, tensor-core) — unchanged from R4 ----------------
#define ENC_OFF_AHI 139264
#define ENC_OFF_ALO 156672
#define ENC_OFF_BXG 174080
#define ENC_OFF_E1W 176128
#define ENC_OFF_E1B 177152
#define ENC_SMEM    177664
__global__ __launch_bounds__(128, 1) void encoder_kernel(
    const float* __restrict__ x, const float* __restrict__ e1w,
    const float* __restrict__ e1b) {
    extern __shared__ char smraw[];
    __half* sM   = (__half*)smraw;
    __half* sAhi = (__half*)(smraw + ENC_OFF_AHI);
    __half* sAlo = (__half*)(smraw + ENC_OFF_ALO);
    float*  sBxg = (float*)(smraw + ENC_OFF_BXG);
    float*  sE1w = (float*)(smraw + ENC_OFF_E1W);
    float*  sE1b = (float*)(smraw + ENC_OFF_E1B);

    int tid = threadIdx.x, w = tid >> 5, l = tid & 31;

    for (int i = tid; i < 8704; i += 128) cp16(((uint4*)sM) + i, ((const uint4*)g_M_h) + i);
    cp_commit();
    for (int i = tid; i < 512; i += 128) sBxg[i] = g_bxg[i];
    for (int i = tid; i < 256; i += 128) sE1w[i] = e1w[i];
    if (tid < 128) sE1b[tid] = e1b[tid];
    cp_wait0();
    __syncthreads();

    const int lrow = (l & 7) + ((l >> 3) & 1) * 8;
    const int lcol = (l >> 4) * 8;
    const int jw = w * 128;
    const int g = l >> 2, tg = l & 3;
    uint32_t sMb   = (uint32_t)__cvta_generic_to_shared(sM);
    uint32_t sAhib = (uint32_t)__cvta_generic_to_shared(sAhi);
    uint32_t sAlob = (uint32_t)__cvta_generic_to_shared(sAlo);

    const int fr = tid >> 1, fh0 = (tid & 1) * 64;

    for (int blk = blockIdx.x; blk < NTT / 64; blk += gridDim.x) {
        int row0 = blk * 64;
        float x0 = x[(size_t)(row0 + fr) * 2];
        float x1 = x[(size_t)(row0 + fr) * 2 + 1];
#pragma unroll
        for (int hh = 0; hh < 64; hh += 2) {
            int h = fh0 + hh;
            float v0 = fmaxf(sE1w[2 * h]     * x0 + sE1w[2 * h + 1] * x1 + sE1b[h], 0.f);
            float v1 = fmaxf(sE1w[2 * h + 2] * x0 + sE1w[2 * h + 3] * x1 + sE1b[h + 1], 0.f);
            __half2 p = __floats2half2_rn(v0, v1);
            *(__half2*)&sAhi[fr * WPAD + h] = p;
            __half2 q = __floats2half2_rn(v0 - __low2float(p), v1 - __high2float(p));
            *(__half2*)&sAlo[fr * WPAD + h] = q;
        }
        __syncthreads();

#pragma unroll
        for (int mt = 0; mt < 4; mt++) {
            float d[16][4];
#pragma unroll
            for (int nt = 0; nt < 16; nt++)
#pragma unroll
                for (int e = 0; e < 4; e++) d[nt][e] = 0.f;
#pragma unroll
            for (int ks = 0; ks < 8; ks++) {
                uint32_t aoff = (uint32_t)(((mt * 16 + lrow) * WPAD + ks * 16 + lcol) << 1);
                uint32_t ah0, ah1, ah2, ah3, al0, al1, al2, al3;
                ldsm4(sAhib + aoff, ah0, ah1, ah2, ah3);
                ldsm4(sAlob + aoff, al0, al1, al2, al3);
#pragma unroll
                for (int np = 0; np < 8; np++) {
                    uint32_t boff = (uint32_t)(((jw + np * 16 + lrow) * WPAD + ks * 16 + lcol) << 1);
                    uint32_t b0, b1, b2, b3;
                    ldsm4(sMb + boff, b0, b1, b2, b3);
                    mma16816(d[2 * np],     ah0, ah1, ah2, ah3, b0, b2);
                    mma16816(d[2 * np],     al0, al1, al2, al3, b0, b2);
                    mma16816(d[2 * np + 1], ah0, ah1, ah2, ah3, b1, b3);
                    mma16816(d[2 * np + 1], al0, al1, al2, al3, b1, b3);
                }
            }
            size_t rb0 = (size_t)(row0 + mt * 16 + g) * 512;
            size_t rb1 = rb0 + (size_t)8 * 512;
#pragma unroll
            for (int nt = 0; nt < 16; nt++) {
                int col = jw + nt * 8 + 2 * tg;
                float b0v = sBxg[col], b1v = sBxg[col + 1];
                *(float2*)&g_xg[rb0 + col] = make_float2(d[nt][0] + b0v, d[nt][1] + b1v);
                *(float2*)&g_xg[rb1 + col] = make_float2(d[nt][2] + b0v, d[nt][3] + b1v);
            }
        }
        __syncthreads();
    }
}

// ---------------- K2: bidirectional LSTM — gate-banded N, in-register activation ----------------
// smem: sW [512][136] half (139264 B) | sHhi [16][136] half (4352 B) | sHlo (4352 B)
#define REC_OFF_HHI 139264
#define REC_OFF_HLO 143616
#define REC_SMEM    147968

__global__ __launch_bounds__(128, 1) void lstm_kernel() {
    extern __shared__ char smraw[];
    __half* sW   = (__half*)smraw;
    __half* sHhi = (__half*)(smraw + REC_OFF_HHI);
    __half* sHlo = (__half*)(smraw + REC_OFF_HLO);

    int tid = threadIdx.x;
    int w = tid >> 5, l = tid & 31;
    int dir = blockIdx.x & 1;
    int n0 = (blockIdx.x >> 1) * 16;

    // load W_hh fp16 (139264 B = 8704 uint4)
    {
        const uint4* src = (const uint4*)g_whh_h;
        uint4* dst = (uint4*)sW;
        for (int i = tid; i < 8704; i += 128) dst[i] = src[i];
    }
    // zero h_hi / h_lo (contiguous 8704 B = 2176 u32)
    for (int i = tid; i < 2176; i += 128) ((uint32_t*)sHhi)[i] = 0u;

    const int lrow = (l & 7) + ((l >> 3) & 1) * 8;
    const int lcol = (l >> 4) * 8;
    const int g = l >> 2, tg = l & 3;
    const int wband = w * 32;

    uint32_t sWb   = (uint32_t)__cvta_generic_to_shared(sW);
    uint32_t sHhib = (uint32_t)__cvta_generic_to_shared(sHhi);
    uint32_t sHlob = (uint32_t)__cvta_generic_to_shared(sHlo);

    float c[2][4][2];
#pragma unroll
    for (int r2 = 0; r2 < 2; r2++)
#pragma unroll
        for (int q = 0; q < 4; q++) { c[r2][q][0] = 0.f; c[r2][q][1] = 0.f; }

    __syncthreads();

    for (int step = 0; step < 512; step++) {
        int t = dir ? (511 - step) : step;

        // prefetch xg into registers: [r2][gate][q] float2 (cols 2tg,2tg+1 of band)
        float2 xg[2][4][4];
#pragma unroll
        for (int r2 = 0; r2 < 2; r2++) {
            size_t rowbase = ((size_t)(n0 + g + r2 * 8) * Tt + t) * 512;
#pragma unroll
            for (int gate = 0; gate < 4; gate++)
#pragma unroll
                for (int q = 0; q < 4; q++) {
                    int col = gate * 128 + wband + (q >> 1) * 16 + (q & 1) * 8 + 2 * tg;
                    xg[r2][gate][q] = *(const float2*)&g_xg[rowbase + col];
                }
        }

        // gates = (h_hi + h_lo) @ W^T  for this warp's (4 gates x 32 cols) band
        float d[4][4][4];
#pragma unroll
        for (int gate = 0; gate < 4; gate++)
#pragma unroll
            for (int q = 0; q < 4; q++)
#pragma unroll
                for (int e = 0; e < 4; e++) d[gate][q][e] = 0.f;

#pragma unroll
        for (int ks = 0; ks < 8; ks++) {
            int k0 = ks * 16;
            uint32_t aoff = (uint32_t)((lrow * WPAD + k0 + lcol) << 1);
            uint32_t ah0, ah1, ah2, ah3, al0, al1, al2, al3;
            ldsm4(sHhib + aoff, ah0, ah1, ah2, ah3);
            ldsm4(sHlob + aoff, al0, al1, al2, al3);
#pragma unroll
            for (int gate = 0; gate < 4; gate++)
#pragma unroll
                for (int nb = 0; nb < 2; nb++) {
                    int j0 = gate * 128 + wband + nb * 16;
                    uint32_t b0, b1, b2, b3;
                    ldsm4(sWb + (uint32_t)(((j0 + lrow) * WPAD + k0 + lcol) << 1), b0, b1, b2, b3);
                    mma16816(d[gate][nb * 2],     ah0, ah1, ah2, ah3, b0, b2);
                    mma16816(d[gate][nb * 2],     al0, al1, al2, al3, b0, b2);
                    mma16816(d[gate][nb * 2 + 1], ah0, ah1, ah2, ah3, b1, b3);
                    mma16816(d[gate][nb * 2 + 1], al0, al1, al2, al3, b1, b3);
                }
        }
        __syncthreads();  // all warps done reading sHhi/sHlo

        // in-register activation; write h to g_h + sHhi/sHlo
#pragma unroll
        for (int r2 = 0; r2 < 2; r2++) {
            int m = g + r2 * 8;
            size_t grow = ((size_t)(n0 + m) * Tt + t) * 128;
#pragma unroll
            for (int q = 0; q < 4; q++) {
                int col = wband + (q >> 1) * 16 + (q & 1) * 8 + 2 * tg;
                float hv[2];
#pragma unroll
                for (int e = 0; e < 2; e++) {
                    int fe = r2 * 2 + e;
                    float iv = d[0][q][fe] + ((const float*)&xg[r2][0][q])[e];
                    float fv = d[1][q][fe] + ((const float*)&xg[r2][1][q])[e];
                    float gv = d[2][q][fe] + ((const float*)&xg[r2][2][q])[e];
                    float ov = d[3][q][fe] + ((const float*)&xg[r2][3][q])[e];
                    float cn = sigm(fv) * c[r2][q][e] + sigm(iv) * tanh_f(gv);
                    c[r2][q][e] = cn;
                    hv[e] = sigm(ov) * tanh_f(cn);
                }
                *(float2*)&g_h[dir][grow + col] = make_float2(hv[0], hv[1]);
                __half2 p = __floats2half2_rn(hv[0], hv[1]);
                *(__half2*)&sHhi[m * WPAD + col] = p;
                __half2 qq = __floats2half2_rn(hv[0] - __low2float(p), hv[1] - __high2float(p));
                *(__half2*)&sHlo[m * WPAD + col] = qq;
            }
        }
        __syncthreads();  // h visible before next step's ldsm
    }
}

// ---------------- K3: decoder (persistent, tensor-core) — unchanged from R4 ----------------
#define DEC_OFF_AHI 67584
#define DEC_OFF_ALO 101376
#define DEC_OFF_PART 135168
#define DEC_SMEM (DEC_OFF_PART + 64 * 17 * 4)
__global__ __launch_bounds__(128, 1) void decoder_kernel(
    const float* __restrict__ d1b, const float* __restrict__ d2w,
    const float* __restrict__ d2b, float* __restrict__ out) {
    extern __shared__ char smraw[];
    __half* sB   = (__half*)smraw;
    __half* sAhi = (__half*)(smraw + DEC_OFF_AHI);
    __half* sAlo = (__half*)(smraw + DEC_OFF_ALO);
    float*  sPart = (float*)(smraw + DEC_OFF_PART);

    int tid = threadIdx.x, w = tid >> 5, l = tid & 31;

    for (int i = tid; i < 4224; i += 128) cp16(((uint4*)sB) + i, ((const uint4*)g_dec1h) + i);
    cp_commit();

    const int lrow = (l & 7) + ((l >> 3) & 1) * 8;
    const int lcol = (l >> 4) * 8;
    const int jw = w * 32;
    const int g = l >> 2, tg = l & 3;
    uint32_t sBb   = (uint32_t)__cvta_generic_to_shared(sB);
    uint32_t sAhib = (uint32_t)__cvta_generic_to_shared(sAhi);
    uint32_t sAlob = (uint32_t)__cvta_generic_to_shared(sAlo);

    float b1v[4][2], w2v[4][2];
#pragma unroll
    for (int nt = 0; nt < 4; nt++)
#pragma unroll
        for (int e = 0; e < 2; e++) {
            int col = jw + nt * 8 + 2 * tg + e;
            b1v[nt][e] = d1b[col];
            w2v[nt][e] = d2w[col];
        }
    float outb = d2b[0];

    cp_wait0();
    __syncthreads();

    for (int blk = blockIdx.x; blk < NTT / 64; blk += gridDim.x) {
        int row0 = blk * 64;
#pragma unroll
        for (int dd = 0; dd < 2; dd++)
#pragma unroll
            for (int it = 0; it < 16; it++) {
                int idx = it * 128 + tid;
                int r = idx >> 5, k4 = idx & 31;
                float4 v = *(const float4*)&g_h[dd][(size_t)(row0 + r) * 128 + k4 * 4];
                float v0 = fmaxf(v.x, 0.f), v1 = fmaxf(v.y, 0.f);
                float v2 = fmaxf(v.z, 0.f), v3 = fmaxf(v.w, 0.f);
                int kb = dd * 128 + k4 * 4;
                __half2 p0 = __floats2half2_rn(v0, v1);
                __half2 p1 = __floats2half2_rn(v2, v3);
                *(__half2*)&sAhi[r * 264 + kb]     = p0;
                *(__half2*)&sAhi[r * 264 + kb + 2] = p1;
                __half2 q0 = __floats2half2_rn(v0 - __low2float(p0), v1 - __high2float(p0));
                __half2 q1 = __floats2half2_rn(v2 - __low2float(p1), v3 - __high2float(p1));
                *(__half2*)&sAlo[r * 264 + kb]     = q0;
                *(__half2*)&sAlo[r * 264 + kb + 2] = q1;
            }
        __syncthreads();

#pragma unroll
        for (int mt = 0; mt < 4; mt++) {
            float d[4][4];
#pragma unroll
            for (int nt = 0; nt < 4; nt++)
#pragma unroll
                for (int e = 0; e < 4; e++) d[nt][e] = 0.f;
#pragma unroll
            for (int ks = 0; ks < 16; ks++) {
                uint32_t aoff = (uint32_t)(((mt * 16 + lrow) * 264 + ks * 16 + lcol) << 1);
                uint32_t ah0, ah1, ah2, ah3, al0, al1, al2, al3;
                ldsm4(sAhib + aoff, ah0, ah1, ah2, ah3);
                ldsm4(sAlob + aoff, al0, al1, al2, al3);
#pragma unroll
                for (int np = 0; np < 2; np++) {
                    uint32_t boff = (uint32_t)(((jw + np * 16 + lrow) * 264 + ks * 16 + lcol) << 1);
                    uint32_t b0, b1, b2, b3;
                    ldsm4(sBb + boff, b0, b1, b2, b3);
                    mma16816(d[2 * np],     ah0, ah1, ah2, ah3, b0, b2);
                    mma16816(d[2 * np],     al0, al1, al2, al3, b0, b2);
                    mma16816(d[2 * np + 1], ah0, ah1, ah2, ah3, b1, b3);
                    mma16816(d[2 * np + 1], al0, al1, al2, al3, b1, b3);
                }
            }
            float p0 = 0.f, p1 = 0.f;
#pragma unroll
            for (int nt = 0; nt < 4; nt++) {
                p0 += fmaxf(d[nt][0] + b1v[nt][0], 0.f) * w2v[nt][0];
                p0 += fmaxf(d[nt][1] + b1v[nt][1], 0.f) * w2v[nt][1];
                p1 += fmaxf(d[nt][2] + b1v[nt][0], 0.f) * w2v[nt][0];
                p1 += fmaxf(d[nt][3] + b1v[nt][1], 0.f) * w2v[nt][1];
            }
            sPart[(mt * 16 + g) * 17 + w * 4 + tg]     = p0;
            sPart[(mt * 16 + g + 8) * 17 + w * 4 + tg] = p1;
        }
        __syncthreads();

        if (tid < 64) {
            float s = 0.f;
#pragma unroll
            for (int q = 0; q < 16; q++) s += sPart[tid * 17 + q];
            out[row0 + tid] = s + outb;
        }
        __syncthreads();
    }
}

// ---------------- launch ----------------
extern "C" void kernel_launch(void* const* d_in, const int* in_sizes, int n_in,
                              void* d_out, int out_size) {
    (void)in_sizes; (void)n_in; (void)out_size;
    const float* x    = (const float*)d_in[0];
    const float* e1w  = (const float*)d_in[1];
    const float* e1b  = (const float*)d_in[2];
    const float* e2w  = (const float*)d_in[3];
    const float* e2b  = (const float*)d_in[4];
    const float* wih  = (const float*)d_in[5];
    const float* whh  = (const float*)d_in[6];
    const float* d1w  = (const float*)d_in[7];
    const float* d1b  = (const float*)d_in[8];
    const float* d2w  = (const float*)d_in[9];
    const float* d2b  = (const float*)d_in[10];
    float* out = (float*)d_out;

    static bool attr_done = false;
    if (!attr_done) {
        cudaFuncSetAttribute(encoder_kernel, cudaFuncAttributeMaxDynamicSharedMemorySize, ENC_SMEM);
        cudaFuncSetAttribute(lstm_kernel, cudaFuncAttributeMaxDynamicSharedMemorySize, REC_SMEM);
        cudaFuncSetAttribute(decoder_kernel, cudaFuncAttributeMaxDynamicSharedMemorySize, DEC_SMEM);
        attr_done = true;
    }

    prep_kernel<<<662, 256>>>(wih, whh, e2w, e2b, d1w);
    encoder_kernel<<<148, 128, ENC_SMEM>>>(x, e1w, e1b);
    lstm_kernel<<<128, 128, REC_SMEM>>>();
    decoder_kernel<<<148, 128, DEC_SMEM>>>(d1b, d2w, d2b, out);
}

// round 6
// speedup vs baseline: 4.6682x; 1.0254x over previous
#include <cuda_runtime.h>
#include <cuda_fp16.h>
#include <cstdint>

#define Nn 1024
#define Tt 512
#define Hh 128
#define Gg 512
#define NTT (Nn*Tt)
#define WPAD 136

// ---------------- device scratch ----------------
__device__ float g_xg[(size_t)NTT * Gg];      // 1 GB: xg = F1 @ M^T + bxg
__device__ float g_h[2][(size_t)NTT * Hh];    // h_fw, h_bw  [n*T+t][128]
__device__ __half g_whh_h[512 * WPAD];        // fp16 w_hh [j][k] padded
__device__ __half g_M_h[512 * WPAD];          // fp16 M = wih@e2w  [j][h] padded
__device__ float  g_bxg[512];                 // wih @ b2
__device__ __half g_dec1h[128 * 264];         // fp16 dec1 [o][k] padded (k stride 264)

__device__ __forceinline__ float sigm(float x) { return __fdividef(1.f, 1.f + __expf(-x)); }
__device__ __forceinline__ float tanh_f(float x) {
    return 1.f - __fdividef(2.f, __expf(2.f * x) + 1.f);
}

__device__ __forceinline__ void cp16(void* smem_dst, const void* gsrc) {
    unsigned s = (unsigned)__cvta_generic_to_shared(smem_dst);
    asm volatile("cp.async.ca.shared.global [%0], [%1], 16;" :: "r"(s), "l"(gsrc));
}
__device__ __forceinline__ void cp_commit() { asm volatile("cp.async.commit_group;"); }
__device__ __forceinline__ void cp_wait0()  { asm volatile("cp.async.wait_group 0;"); }

__device__ __forceinline__ void ldsm4(uint32_t addr, uint32_t& r0, uint32_t& r1,
                                      uint32_t& r2, uint32_t& r3) {
    asm volatile("ldmatrix.sync.aligned.m8n8.x4.shared.b16 {%0,%1,%2,%3}, [%4];"
                 : "=r"(r0), "=r"(r1), "=r"(r2), "=r"(r3) : "r"(addr));
}
__device__ __forceinline__ void mma16816(float* d, uint32_t a0, uint32_t a1, uint32_t a2,
                                         uint32_t a3, uint32_t b0, uint32_t b1) {
    asm volatile(
        "mma.sync.aligned.m16n8k16.row.col.f32.f16.f16.f32 "
        "{%0,%1,%2,%3}, {%4,%5,%6,%7}, {%8,%9}, {%0,%1,%2,%3};"
        : "+f"(d[0]), "+f"(d[1]), "+f"(d[2]), "+f"(d[3])
        : "r"(a0), "r"(a1), "r"(a2), "r"(a3), "r"(b0), "r"(b1));
}

// ---------------- K0: weight prep ----------------
__global__ void prep_kernel(const float* __restrict__ wih, const float* __restrict__ whh,
                            const float* __restrict__ e2w, const float* __restrict__ e2b,
                            const float* __restrict__ dec1) {
    int i = blockIdx.x * blockDim.x + threadIdx.x;
    if (i < 65536) {
        int j = i >> 7, h = i & 127;
        float s = 0.f;
#pragma unroll 4
        for (int o = 0; o < 128; o++) s += wih[j * 128 + o] * e2w[o * 128 + h];
        g_M_h[j * WPAD + h] = __float2half(s);
    } else if (i < 66048) {
        int j = i - 65536;
        float s = 0.f;
#pragma unroll 4
        for (int o = 0; o < 128; o++) s += e2b[o] * wih[j * 128 + o];
        g_bxg[j] = s;
    } else if (i < 135680) {
        int p = i - 66048;
        int j = p / WPAD, k = p % WPAD;
        g_whh_h[p] = (k < 128) ? __float2half(whh[j * 128 + k]) : __float2half(0.f);
    } else if (i < 169472) {
        int p = i - 135680;
        int j = p / 264, k = p % 264;
        g_dec1h[p] = (k < 256) ? __float2half(dec1[j * 256 + k]) : __float2half(0.f);
    }
}

// ---------------- K1: encoder (persistent, tensor-core, single fp16) ----------------
#define ENC_OFF_AHI 139264
#define ENC_OFF_BXG 156672
#define ENC_OFF_E1W 158720
#define ENC_OFF_E1B 159744
#define ENC_SMEM    160256
__global__ __launch_bounds__(128, 1) void encoder_kernel(
    const float* __restrict__ x, const float* __restrict__ e1w,
    const float* __restrict__ e1b) {
    extern __shared__ char smraw[];
    __half* sM   = (__half*)smraw;
    __half* sAhi = (__half*)(smraw + ENC_OFF_AHI);
    float*  sBxg = (float*)(smraw + ENC_OFF_BXG);
    float*  sE1w = (float*)(smraw + ENC_OFF_E1W);
    float*  sE1b = (float*)(smraw + ENC_OFF_E1B);

    int tid = threadIdx.x, w = tid >> 5, l = tid & 31;

    for (int i = tid; i < 8704; i += 128) cp16(((uint4*)sM) + i, ((const uint4*)g_M_h) + i);
    cp_commit();
    for (int i = tid; i < 512; i += 128) sBxg[i] = g_bxg[i];
    for (int i = tid; i < 256; i += 128) sE1w[i] = e1w[i];
    if (tid < 128) sE1b[tid] = e1b[tid];
    cp_wait0();
    __syncthreads();

    const int lrow = (l & 7) + ((l >> 3) & 1) * 8;
    const int lcol = (l >> 4) * 8;
    const int jw = w * 128;
    const int g = l >> 2, tg = l & 3;
    uint32_t sMb   = (uint32_t)__cvta_generic_to_shared(sM);
    uint32_t sAhib = (uint32_t)__cvta_generic_to_shared(sAhi);

    const int fr = tid >> 1, fh0 = (tid & 1) * 64;

    for (int blk = blockIdx.x; blk < NTT / 64; blk += gridDim.x) {
        int row0 = blk * 64;
        float x0 = x[(size_t)(row0 + fr) * 2];
        float x1 = x[(size_t)(row0 + fr) * 2 + 1];
#pragma unroll
        for (int hh = 0; hh < 64; hh += 2) {
            int h = fh0 + hh;
            float v0 = fmaxf(sE1w[2 * h]     * x0 + sE1w[2 * h + 1] * x1 + sE1b[h], 0.f);
            float v1 = fmaxf(sE1w[2 * h + 2] * x0 + sE1w[2 * h + 3] * x1 + sE1b[h + 1], 0.f);
            *(__half2*)&sAhi[fr * WPAD + h] = __floats2half2_rn(v0, v1);
        }
        __syncthreads();

#pragma unroll
        for (int mt = 0; mt < 4; mt++) {
            float d[16][4];
#pragma unroll
            for (int nt = 0; nt < 16; nt++)
#pragma unroll
                for (int e = 0; e < 4; e++) d[nt][e] = 0.f;
#pragma unroll
            for (int ks = 0; ks < 8; ks++) {
                uint32_t aoff = (uint32_t)(((mt * 16 + lrow) * WPAD + ks * 16 + lcol) << 1);
                uint32_t ah0, ah1, ah2, ah3;
                ldsm4(sAhib + aoff, ah0, ah1, ah2, ah3);
#pragma unroll
                for (int np = 0; np < 8; np++) {
                    uint32_t boff = (uint32_t)(((jw + np * 16 + lrow) * WPAD + ks * 16 + lcol) << 1);
                    uint32_t b0, b1, b2, b3;
                    ldsm4(sMb + boff, b0, b1, b2, b3);
                    mma16816(d[2 * np],     ah0, ah1, ah2, ah3, b0, b2);
                    mma16816(d[2 * np + 1], ah0, ah1, ah2, ah3, b1, b3);
                }
            }
            size_t rb0 = (size_t)(row0 + mt * 16 + g) * 512;
            size_t rb1 = rb0 + (size_t)8 * 512;
#pragma unroll
            for (int nt = 0; nt < 16; nt++) {
                int col = jw + nt * 8 + 2 * tg;
                float b0v = sBxg[col], b1v = sBxg[col + 1];
                *(float2*)&g_xg[rb0 + col] = make_float2(d[nt][0] + b0v, d[nt][1] + b1v);
                *(float2*)&g_xg[rb1 + col] = make_float2(d[nt][2] + b0v, d[nt][3] + b1v);
            }
        }
        __syncthreads();
    }
}

// ---------------- K2: bidirectional LSTM — single fp16 h, double-buffered ----------------
// smem: sW [512][136] half (139264 B) | sH[2] x [16][136] half (2 x 4352 B)
#define REC_OFF_H   139264
#define REC_HBUF    4352
#define REC_SMEM    (REC_OFF_H + 2 * REC_HBUF)

__global__ __launch_bounds__(128, 1) void lstm_kernel() {
    extern __shared__ char smraw[];
    __half* sW = (__half*)smraw;

    int tid = threadIdx.x;
    int w = tid >> 5, l = tid & 31;
    int dir = blockIdx.x & 1;
    int n0 = (blockIdx.x >> 1) * 16;

    {
        const uint4* src = (const uint4*)g_whh_h;
        uint4* dst = (uint4*)sW;
        for (int i = tid; i < 8704; i += 128) dst[i] = src[i];
    }
    // zero h buffer 0 (4352 B = 1088 u32)
    for (int i = tid; i < 1088; i += 128) ((uint32_t*)(smraw + REC_OFF_H))[i] = 0u;

    const int lrow = (l & 7) + ((l >> 3) & 1) * 8;
    const int lcol = (l >> 4) * 8;
    const int g = l >> 2, tg = l & 3;
    const int wband = w * 32;

    uint32_t sWb = (uint32_t)__cvta_generic_to_shared(sW);
    uint32_t sHb = (uint32_t)__cvta_generic_to_shared(smraw + REC_OFF_H);

    float c[2][4][2];
#pragma unroll
    for (int r2 = 0; r2 < 2; r2++)
#pragma unroll
        for (int q = 0; q < 4; q++) { c[r2][q][0] = 0.f; c[r2][q][1] = 0.f; }

    __syncthreads();

    for (int step = 0; step < 512; step++) {
        int t = dir ? (511 - step) : step;
        uint32_t hcur = sHb + (uint32_t)(step & 1) * REC_HBUF;
        __half* hnxt = (__half*)(smraw + REC_OFF_H + ((step + 1) & 1) * REC_HBUF);

        // prefetch xg into registers
        float2 xg[2][4][4];
#pragma unroll
        for (int r2 = 0; r2 < 2; r2++) {
            size_t rowbase = ((size_t)(n0 + g + r2 * 8) * Tt + t) * 512;
#pragma unroll
            for (int gate = 0; gate < 4; gate++)
#pragma unroll
                for (int q = 0; q < 4; q++) {
                    int col = gate * 128 + wband + (q >> 1) * 16 + (q & 1) * 8 + 2 * tg;
                    xg[r2][gate][q] = *(const float2*)&g_xg[rowbase + col];
                }
        }

        // gates = h @ W^T for this warp's (4 gates x 32 cols) band
        float d[4][4][4];
#pragma unroll
        for (int gate = 0; gate < 4; gate++)
#pragma unroll
            for (int q = 0; q < 4; q++)
#pragma unroll
                for (int e = 0; e < 4; e++) d[gate][q][e] = 0.f;

#pragma unroll
        for (int ks = 0; ks < 8; ks++) {
            int k0 = ks * 16;
            uint32_t ah0, ah1, ah2, ah3;
            ldsm4(hcur + (uint32_t)((lrow * WPAD + k0 + lcol) << 1), ah0, ah1, ah2, ah3);
#pragma unroll
            for (int gate = 0; gate < 4; gate++)
#pragma unroll
                for (int nb = 0; nb < 2; nb++) {
                    int j0 = gate * 128 + wband + nb * 16;
                    uint32_t b0, b1, b2, b3;
                    ldsm4(sWb + (uint32_t)(((j0 + lrow) * WPAD + k0 + lcol) << 1), b0, b1, b2, b3);
                    mma16816(d[gate][nb * 2],     ah0, ah1, ah2, ah3, b0, b2);
                    mma16816(d[gate][nb * 2 + 1], ah0, ah1, ah2, ah3, b1, b3);
                }
        }

        // in-register activation; write h to g_h + next h buffer
#pragma unroll
        for (int r2 = 0; r2 < 2; r2++) {
            int m = g + r2 * 8;
            size_t grow = ((size_t)(n0 + m) * Tt + t) * 128;
#pragma unroll
            for (int q = 0; q < 4; q++) {
                int col = wband + (q >> 1) * 16 + (q & 1) * 8 + 2 * tg;
                float hv[2];
#pragma unroll
                for (int e = 0; e < 2; e++) {
                    int fe = r2 * 2 + e;
                    float iv = d[0][q][fe] + ((const float*)&xg[r2][0][q])[e];
                    float fv = d[1][q][fe] + ((const float*)&xg[r2][1][q])[e];
                    float gv = d[2][q][fe] + ((const float*)&xg[r2][2][q])[e];
                    float ov = d[3][q][fe] + ((const float*)&xg[r2][3][q])[e];
                    float cn = sigm(fv) * c[r2][q][e] + sigm(iv) * tanh_f(gv);
                    c[r2][q][e] = cn;
                    hv[e] = sigm(ov) * tanh_f(cn);
                }
                *(float2*)&g_h[dir][grow + col] = make_float2(hv[0], hv[1]);
                *(__half2*)&hnxt[m * WPAD + col] = __floats2half2_rn(hv[0], hv[1]);
            }
        }
        __syncthreads();  // next-h buffer complete before next step's ldsm
    }
}

// ---------------- K3: decoder (persistent, tensor-core, single fp16) ----------------
#define DEC_OFF_AHI 67584
#define DEC_OFF_PART 101376
#define DEC_SMEM (DEC_OFF_PART + 64 * 17 * 4)
__global__ __launch_bounds__(128, 1) void decoder_kernel(
    const float* __restrict__ d1b, const float* __restrict__ d2w,
    const float* __restrict__ d2b, float* __restrict__ out) {
    extern __shared__ char smraw[];
    __half* sB   = (__half*)smraw;
    __half* sAhi = (__half*)(smraw + DEC_OFF_AHI);
    float*  sPart = (float*)(smraw + DEC_OFF_PART);

    int tid = threadIdx.x, w = tid >> 5, l = tid & 31;

    for (int i = tid; i < 4224; i += 128) cp16(((uint4*)sB) + i, ((const uint4*)g_dec1h) + i);
    cp_commit();

    const int lrow = (l & 7) + ((l >> 3) & 1) * 8;
    const int lcol = (l >> 4) * 8;
    const int jw = w * 32;
    const int g = l >> 2, tg = l & 3;
    uint32_t sBb   = (uint32_t)__cvta_generic_to_shared(sB);
    uint32_t sAhib = (uint32_t)__cvta_generic_to_shared(sAhi);

    float b1v[4][2], w2v[4][2];
#pragma unroll
    for (int nt = 0; nt < 4; nt++)
#pragma unroll
        for (int e = 0; e < 2; e++) {
            int col = jw + nt * 8 + 2 * tg + e;
            b1v[nt][e] = d1b[col];
            w2v[nt][e] = d2w[col];
        }
    float outb = d2b[0];

    cp_wait0();
    __syncthreads();

    for (int blk = blockIdx.x; blk < NTT / 64; blk += gridDim.x) {
        int row0 = blk * 64;
#pragma unroll
        for (int dd = 0; dd < 2; dd++)
#pragma unroll
            for (int it = 0; it < 16; it++) {
                int idx = it * 128 + tid;
                int r = idx >> 5, k4 = idx & 31;
                float4 v = *(const float4*)&g_h[dd][(size_t)(row0 + r) * 128 + k4 * 4];
                int kb = dd * 128 + k4 * 4;
                *(__half2*)&sAhi[r * 264 + kb]     = __floats2half2_rn(fmaxf(v.x, 0.f), fmaxf(v.y, 0.f));
                *(__half2*)&sAhi[r * 264 + kb + 2] = __floats2half2_rn(fmaxf(v.z, 0.f), fmaxf(v.w, 0.f));
            }
        __syncthreads();

#pragma unroll
        for (int mt = 0; mt < 4; mt++) {
            float d[4][4];
#pragma unroll
            for (int nt = 0; nt < 4; nt++)
#pragma unroll
                for (int e = 0; e < 4; e++) d[nt][e] = 0.f;
#pragma unroll
            for (int ks = 0; ks < 16; ks++) {
                uint32_t aoff = (uint32_t)(((mt * 16 + lrow) * 264 + ks * 16 + lcol) << 1);
                uint32_t ah0, ah1, ah2, ah3;
                ldsm4(sAhib + aoff, ah0, ah1, ah2, ah3);
#pragma unroll
                for (int np = 0; np < 2; np++) {
                    uint32_t boff = (uint32_t)(((jw + np * 16 + lrow) * 264 + ks * 16 + lcol) << 1);
                    uint32_t b0, b1, b2, b3;
                    ldsm4(sBb + boff, b0, b1, b2, b3);
                    mma16816(d[2 * np],     ah0, ah1, ah2, ah3, b0, b2);
                    mma16816(d[2 * np + 1], ah0, ah1, ah2, ah3, b1, b3);
                }
            }
            float p0 = 0.f, p1 = 0.f;
#pragma unroll
            for (int nt = 0; nt < 4; nt++) {
                p0 += fmaxf(d[nt][0] + b1v[nt][0], 0.f) * w2v[nt][0];
                p0 += fmaxf(d[nt][1] + b1v[nt][1], 0.f) * w2v[nt][1];
                p1 += fmaxf(d[nt][2] + b1v[nt][0], 0.f) * w2v[nt][0];
                p1 += fmaxf(d[nt][3] + b1v[nt][1], 0.f) * w2v[nt][1];
            }
            sPart[(mt * 16 + g) * 17 + w * 4 + tg]     = p0;
            sPart[(mt * 16 + g + 8) * 17 + w * 4 + tg] = p1;
        }
        __syncthreads();

        if (tid < 64) {
            float s = 0.f;
#pragma unroll
            for (int q = 0; q < 16; q++) s += sPart[tid * 17 + q];
            out[row0 + tid] = s + outb;
        }
        __syncthreads();
    }
}

// ---------------- launch ----------------
extern "C" void kernel_launch(void* const* d_in, const int* in_sizes, int n_in,
                              void* d_out, int out_size) {
    (void)in_sizes; (void)n_in; (void)out_size;
    const float* x    = (const float*)d_in[0];
    const float* e1w  = (const float*)d_in[1];
    const float* e1b  = (const float*)d_in[2];
    const float* e2w  = (const float*)d_in[3];
    const float* e2b  = (const float*)d_in[4];
    const float* wih  = (const float*)d_in[5];
    const float* whh  = (const float*)d_in[6];
    const float* d1w  = (const float*)d_in[7];
    const float* d1b  = (const float*)d_in[8];
    const float* d2w  = (const float*)d_in[9];
    const float* d2b  = (const float*)d_in[10];
    float* out = (float*)d_out;

    static bool attr_done = false;
    if (!attr_done) {
        cudaFuncSetAttribute(encoder_kernel, cudaFuncAttributeMaxDynamicSharedMemorySize, ENC_SMEM);
        cudaFuncSetAttribute(lstm_kernel, cudaFuncAttributeMaxDynamicSharedMemorySize, REC_SMEM);
        cudaFuncSetAttribute(decoder_kernel, cudaFuncAttributeMaxDynamicSharedMemorySize, DEC_SMEM);
        attr_done = true;
    }

    prep_kernel<<<662, 256>>>(wih, whh, e2w, e2b, d1w);
    encoder_kernel<<<148, 128, ENC_SMEM>>>(x, e1w, e1b);
    lstm_kernel<<<128, 128, REC_SMEM>>>();
    decoder_kernel<<<148, 128, DEC_SMEM>>>(d1b, d2w, d2b, out);
}

// round 7
// speedup vs baseline: 6.8491x; 1.4672x over previous
#include <cuda_runtime.h>
#include <cuda_fp16.h>
#include <cstdint>

#define Nn 1024
#define Tt 512
#define Hh 128
#define Gg 512
#define NTT (Nn*Tt)
#define WPAD 136

// ---------------- device scratch ----------------
__device__ __half g_xg[(size_t)NTT * Gg];     // 512 MB fp16: xg = F1 @ M^T + bxg
__device__ __half g_hcat[(size_t)NTT * 256];  // 256 MB fp16: relu(h) [row][fw128|bw128]
__device__ __half g_whh_h[512 * WPAD];        // fp16 w_hh [j][k] padded
__device__ __half g_M_h[512 * WPAD];          // fp16 M = wih@e2w  [j][h] padded
__device__ float  g_bxg[512];                 // wih @ b2
__device__ __half g_dec1h[128 * 264];         // fp16 dec1 [o][k] padded (k stride 264)

__device__ __forceinline__ float sigm(float x) { return __fdividef(1.f, 1.f + __expf(-x)); }
__device__ __forceinline__ float tanh_f(float x) {
    return 1.f - __fdividef(2.f, __expf(2.f * x) + 1.f);
}

__device__ __forceinline__ void cp16(void* smem_dst, const void* gsrc) {
    unsigned s = (unsigned)__cvta_generic_to_shared(smem_dst);
    asm volatile("cp.async.ca.shared.global [%0], [%1], 16;" :: "r"(s), "l"(gsrc));
}
__device__ __forceinline__ void cp_commit() { asm volatile("cp.async.commit_group;"); }
__device__ __forceinline__ void cp_wait1()  { asm volatile("cp.async.wait_group 1;"); }
__device__ __forceinline__ void cp_wait0()  { asm volatile("cp.async.wait_group 0;"); }

__device__ __forceinline__ void ldsm4(uint32_t addr, uint32_t& r0, uint32_t& r1,
                                      uint32_t& r2, uint32_t& r3) {
    asm volatile("ldmatrix.sync.aligned.m8n8.x4.shared.b16 {%0,%1,%2,%3}, [%4];"
                 : "=r"(r0), "=r"(r1), "=r"(r2), "=r"(r3) : "r"(addr));
}
__device__ __forceinline__ void mma16816(float* d, uint32_t a0, uint32_t a1, uint32_t a2,
                                         uint32_t a3, uint32_t b0, uint32_t b1) {
    asm volatile(
        "mma.sync.aligned.m16n8k16.row.col.f32.f16.f16.f32 "
        "{%0,%1,%2,%3}, {%4,%5,%6,%7}, {%8,%9}, {%0,%1,%2,%3};"
        : "+f"(d[0]), "+f"(d[1]), "+f"(d[2]), "+f"(d[3])
        : "r"(a0), "r"(a1), "r"(a2), "r"(a3), "r"(b0), "r"(b1));
}

// ---------------- K0: weight prep ----------------
__global__ void prep_kernel(const float* __restrict__ wih, const float* __restrict__ whh,
                            const float* __restrict__ e2w, const float* __restrict__ e2b,
                            const float* __restrict__ dec1) {
    int i = blockIdx.x * blockDim.x + threadIdx.x;
    if (i < 65536) {
        int j = i >> 7, h = i & 127;
        float s = 0.f;
#pragma unroll 4
        for (int o = 0; o < 128; o++) s += wih[j * 128 + o] * e2w[o * 128 + h];
        g_M_h[j * WPAD + h] = __float2half(s);
    } else if (i < 66048) {
        int j = i - 65536;
        float s = 0.f;
#pragma unroll 4
        for (int o = 0; o < 128; o++) s += e2b[o] * wih[j * 128 + o];
        g_bxg[j] = s;
    } else if (i < 135680) {
        int p = i - 66048;
        int j = p / WPAD, k = p % WPAD;
        g_whh_h[p] = (k < 128) ? __float2half(whh[j * 128 + k]) : __float2half(0.f);
    } else if (i < 169472) {
        int p = i - 135680;
        int j = p / 264, k = p % 264;
        g_dec1h[p] = (k < 256) ? __float2half(dec1[j * 256 + k]) : __float2half(0.f);
    }
}

// ---------------- K1: encoder (persistent, tensor-core, fp16 out) ----------------
#define ENC_OFF_AHI 139264
#define ENC_OFF_BXG 156672
#define ENC_OFF_E1W 158720
#define ENC_OFF_E1B 159744
#define ENC_SMEM    160256
__global__ __launch_bounds__(128, 1) void encoder_kernel(
    const float* __restrict__ x, const float* __restrict__ e1w,
    const float* __restrict__ e1b) {
    extern __shared__ char smraw[];
    __half* sM   = (__half*)smraw;
    __half* sAhi = (__half*)(smraw + ENC_OFF_AHI);
    float*  sBxg = (float*)(smraw + ENC_OFF_BXG);
    float*  sE1w = (float*)(smraw + ENC_OFF_E1W);
    float*  sE1b = (float*)(smraw + ENC_OFF_E1B);

    int tid = threadIdx.x, w = tid >> 5, l = tid & 31;

    for (int i = tid; i < 8704; i += 128) cp16(((uint4*)sM) + i, ((const uint4*)g_M_h) + i);
    cp_commit();
    for (int i = tid; i < 512; i += 128) sBxg[i] = g_bxg[i];
    for (int i = tid; i < 256; i += 128) sE1w[i] = e1w[i];
    if (tid < 128) sE1b[tid] = e1b[tid];
    cp_wait0();
    __syncthreads();

    const int lrow = (l & 7) + ((l >> 3) & 1) * 8;
    const int lcol = (l >> 4) * 8;
    const int jw = w * 128;
    const int g = l >> 2, tg = l & 3;
    uint32_t sMb   = (uint32_t)__cvta_generic_to_shared(sM);
    uint32_t sAhib = (uint32_t)__cvta_generic_to_shared(sAhi);

    const int fr = tid >> 1, fh0 = (tid & 1) * 64;

    for (int blk = blockIdx.x; blk < NTT / 64; blk += gridDim.x) {
        int row0 = blk * 64;
        float x0 = x[(size_t)(row0 + fr) * 2];
        float x1 = x[(size_t)(row0 + fr) * 2 + 1];
#pragma unroll
        for (int hh = 0; hh < 64; hh += 2) {
            int h = fh0 + hh;
            float v0 = fmaxf(sE1w[2 * h]     * x0 + sE1w[2 * h + 1] * x1 + sE1b[h], 0.f);
            float v1 = fmaxf(sE1w[2 * h + 2] * x0 + sE1w[2 * h + 3] * x1 + sE1b[h + 1], 0.f);
            *(__half2*)&sAhi[fr * WPAD + h] = __floats2half2_rn(v0, v1);
        }
        __syncthreads();

#pragma unroll
        for (int mt = 0; mt < 4; mt++) {
            float d[16][4];
#pragma unroll
            for (int nt = 0; nt < 16; nt++)
#pragma unroll
                for (int e = 0; e < 4; e++) d[nt][e] = 0.f;
#pragma unroll
            for (int ks = 0; ks < 8; ks++) {
                uint32_t aoff = (uint32_t)(((mt * 16 + lrow) * WPAD + ks * 16 + lcol) << 1);
                uint32_t ah0, ah1, ah2, ah3;
                ldsm4(sAhib + aoff, ah0, ah1, ah2, ah3);
#pragma unroll
                for (int np = 0; np < 8; np++) {
                    uint32_t boff = (uint32_t)(((jw + np * 16 + lrow) * WPAD + ks * 16 + lcol) << 1);
                    uint32_t b0, b1, b2, b3;
                    ldsm4(sMb + boff, b0, b1, b2, b3);
                    mma16816(d[2 * np],     ah0, ah1, ah2, ah3, b0, b2);
                    mma16816(d[2 * np + 1], ah0, ah1, ah2, ah3, b1, b3);
                }
            }
            size_t rb0 = (size_t)(row0 + mt * 16 + g) * 512;
            size_t rb1 = rb0 + (size_t)8 * 512;
#pragma unroll
            for (int nt = 0; nt < 16; nt++) {
                int col = jw + nt * 8 + 2 * tg;
                float b0v = sBxg[col], b1v = sBxg[col + 1];
                *(__half2*)&g_xg[rb0 + col] = __floats2half2_rn(d[nt][0] + b0v, d[nt][1] + b1v);
                *(__half2*)&g_xg[rb1 + col] = __floats2half2_rn(d[nt][2] + b0v, d[nt][3] + b1v);
            }
        }
        __syncthreads();
    }
}

// ---------------- K2: bidirectional LSTM — 256 threads, 8 warps, fp16 h ----------------
// smem: sW [512][136] half (139264 B) | sH[2] x [16][136] half (2 x 4352 B)
#define REC_OFF_H   139264
#define REC_HBUF    4352
#define REC_SMEM    (REC_OFF_H + 2 * REC_HBUF)

__global__ __launch_bounds__(256, 1) void lstm_kernel() {
    extern __shared__ char smraw[];
    __half* sW = (__half*)smraw;

    int tid = threadIdx.x;
    int w = tid >> 5, l = tid & 31;
    int dir = blockIdx.x & 1;
    int n0 = (blockIdx.x >> 1) * 16;

    {
        const uint4* src = (const uint4*)g_whh_h;
        uint4* dst = (uint4*)sW;
        for (int i = tid; i < 8704; i += 256) dst[i] = src[i];
    }
    for (int i = tid; i < 1088; i += 256) ((uint32_t*)(smraw + REC_OFF_H))[i] = 0u;

    const int lrow = (l & 7) + ((l >> 3) & 1) * 8;
    const int lcol = (l >> 4) * 8;
    const int g = l >> 2, tg = l & 3;
    const int wband = w * 16;    // 8 warps x 16 hidden cols

    uint32_t sWb = (uint32_t)__cvta_generic_to_shared(sW);
    uint32_t sHb = (uint32_t)__cvta_generic_to_shared(smraw + REC_OFF_H);

    float c[2][2][2];
#pragma unroll
    for (int r2 = 0; r2 < 2; r2++)
#pragma unroll
        for (int nt = 0; nt < 2; nt++) { c[r2][nt][0] = 0.f; c[r2][nt][1] = 0.f; }

    __syncthreads();

    for (int step = 0; step < 512; step++) {
        int t = dir ? (511 - step) : step;
        uint32_t hcur = sHb + (uint32_t)(step & 1) * REC_HBUF;
        __half* hnxt = (__half*)(smraw + REC_OFF_H + ((step + 1) & 1) * REC_HBUF);

        // prefetch xg (fp16) into registers: [r2][gate][nt]
        __half2 xgv[2][4][2];
#pragma unroll
        for (int r2 = 0; r2 < 2; r2++) {
            size_t rowbase = ((size_t)(n0 + g + r2 * 8) * Tt + t) * 512;
#pragma unroll
            for (int gate = 0; gate < 4; gate++)
#pragma unroll
                for (int nt = 0; nt < 2; nt++) {
                    int col = gate * 128 + wband + nt * 8 + 2 * tg;
                    xgv[r2][gate][nt] = *(const __half2*)&g_xg[rowbase + col];
                }
        }

        // gates = h @ W^T for this warp's (4 gates x 16 cols) band
        float d[4][2][4];
#pragma unroll
        for (int gate = 0; gate < 4; gate++)
#pragma unroll
            for (int nt = 0; nt < 2; nt++)
#pragma unroll
                for (int e = 0; e < 4; e++) d[gate][nt][e] = 0.f;

#pragma unroll
        for (int ks = 0; ks < 8; ks++) {
            int k0 = ks * 16;
            uint32_t ah0, ah1, ah2, ah3;
            ldsm4(hcur + (uint32_t)((lrow * WPAD + k0 + lcol) << 1), ah0, ah1, ah2, ah3);
#pragma unroll
            for (int gate = 0; gate < 4; gate++) {
                int j0 = gate * 128 + wband;
                uint32_t b0, b1, b2, b3;
                ldsm4(sWb + (uint32_t)(((j0 + lrow) * WPAD + k0 + lcol) << 1), b0, b1, b2, b3);
                mma16816(d[gate][0], ah0, ah1, ah2, ah3, b0, b2);
                mma16816(d[gate][1], ah0, ah1, ah2, ah3, b1, b3);
            }
        }

        // in-register activation; write relu(h) fp16 to g_hcat + h fp16 to next buffer
#pragma unroll
        for (int r2 = 0; r2 < 2; r2++) {
            int m = g + r2 * 8;
            size_t grow = ((size_t)(n0 + m) * Tt + t) * 256 + dir * 128;
#pragma unroll
            for (int nt = 0; nt < 2; nt++) {
                int col = wband + nt * 8 + 2 * tg;
                float2 xi = __half22float2(xgv[r2][0][nt]);
                float2 xf = __half22float2(xgv[r2][1][nt]);
                float2 xgg = __half22float2(xgv[r2][2][nt]);
                float2 xo = __half22float2(xgv[r2][3][nt]);
                float hv[2];
#pragma unroll
                for (int e = 0; e < 2; e++) {
                    int fe = r2 * 2 + e;
                    float iv = d[0][nt][fe] + ((const float*)&xi)[e];
                    float fv = d[1][nt][fe] + ((const float*)&xf)[e];
                    float gv = d[2][nt][fe] + ((const float*)&xgg)[e];
                    float ov = d[3][nt][fe] + ((const float*)&xo)[e];
                    float cn = sigm(fv) * c[r2][nt][e] + sigm(iv) * tanh_f(gv);
                    c[r2][nt][e] = cn;
                    hv[e] = sigm(ov) * tanh_f(cn);
                }
                *(__half2*)&hnxt[m * WPAD + col] = __floats2half2_rn(hv[0], hv[1]);
                *(__half2*)&g_hcat[grow + col] =
                    __floats2half2_rn(fmaxf(hv[0], 0.f), fmaxf(hv[1], 0.f));
            }
        }
        __syncthreads();  // next-h buffer complete before next step's ldsm
    }
}

// ---------------- K3: decoder (persistent, tensor-core, direct fp16 tiles) ----------------
#define DEC_OFF_T0  67584
#define DEC_TBUF    33792
#define DEC_OFF_PART (DEC_OFF_T0 + 2 * DEC_TBUF)
#define DEC_SMEM    (DEC_OFF_PART + 64 * 17 * 4)

__device__ __forceinline__ void dec_load_tile(char* smraw, int buf, int blk, int tid) {
    __half* dst = (__half*)(smraw + DEC_OFF_T0 + buf * DEC_TBUF);
    size_t row0 = (size_t)blk * 64;
#pragma unroll
    for (int it = 0; it < 16; it++) {
        int idx = it * 128 + tid;             // 2048 16B-granules
        int r = idx >> 5, ck = idx & 31;      // row, 16B chunk (8 halves)
        cp16(dst + r * 264 + ck * 8, g_hcat + (row0 + r) * 256 + ck * 8);
    }
}

__global__ __launch_bounds__(128, 1) void decoder_kernel(
    const float* __restrict__ d1b, const float* __restrict__ d2w,
    const float* __restrict__ d2b, float* __restrict__ out) {
    extern __shared__ char smraw[];
    __half* sB = (__half*)smraw;
    float* sPart = (float*)(smraw + DEC_OFF_PART);

    int tid = threadIdx.x, w = tid >> 5, l = tid & 31;

    for (int i = tid; i < 4224; i += 128) cp16(((uint4*)sB) + i, ((const uint4*)g_dec1h) + i);
    cp_commit();

    const int lrow = (l & 7) + ((l >> 3) & 1) * 8;
    const int lcol = (l >> 4) * 8;
    const int jw = w * 32;
    const int g = l >> 2, tg = l & 3;
    uint32_t sBb = (uint32_t)__cvta_generic_to_shared(sB);
    uint32_t sTb = (uint32_t)__cvta_generic_to_shared(smraw + DEC_OFF_T0);

    float b1v[4][2], w2v[4][2];
#pragma unroll
    for (int nt = 0; nt < 4; nt++)
#pragma unroll
        for (int e = 0; e < 2; e++) {
            int col = jw + nt * 8 + 2 * tg + e;
            b1v[nt][e] = d1b[col];
            w2v[nt][e] = d2w[col];
        }
    float outb = d2b[0];
    cp_wait0();

    int blk = blockIdx.x;
    int buf = 0;
    dec_load_tile(smraw, buf, blk, tid);
    cp_commit();

    for (; blk < NTT / 64; blk += gridDim.x) {
        int nxt = blk + gridDim.x;
        if (nxt < NTT / 64) {
            dec_load_tile(smraw, buf ^ 1, nxt, tid);
            cp_commit();
            cp_wait1();
        } else {
            cp_wait0();
        }
        __syncthreads();

        uint32_t sAb = sTb + (uint32_t)buf * DEC_TBUF;
        int row0 = blk * 64;
#pragma unroll
        for (int mt = 0; mt < 4; mt++) {
            float d[4][4];
#pragma unroll
            for (int nt = 0; nt < 4; nt++)
#pragma unroll
                for (int e = 0; e < 4; e++) d[nt][e] = 0.f;
#pragma unroll
            for (int ks = 0; ks < 16; ks++) {
                uint32_t aoff = (uint32_t)(((mt * 16 + lrow) * 264 + ks * 16 + lcol) << 1);
                uint32_t ah0, ah1, ah2, ah3;
                ldsm4(sAb + aoff, ah0, ah1, ah2, ah3);
#pragma unroll
                for (int np = 0; np < 2; np++) {
                    uint32_t boff = (uint32_t)(((jw + np * 16 + lrow) * 264 + ks * 16 + lcol) << 1);
                    uint32_t b0, b1, b2, b3;
                    ldsm4(sBb + boff, b0, b1, b2, b3);
                    mma16816(d[2 * np],     ah0, ah1, ah2, ah3, b0, b2);
                    mma16816(d[2 * np + 1], ah0, ah1, ah2, ah3, b1, b3);
                }
            }
            float p0 = 0.f, p1 = 0.f;
#pragma unroll
            for (int nt = 0; nt < 4; nt++) {
                p0 += fmaxf(d[nt][0] + b1v[nt][0], 0.f) * w2v[nt][0];
                p0 += fmaxf(d[nt][1] + b1v[nt][1], 0.f) * w2v[nt][1];
                p1 += fmaxf(d[nt][2] + b1v[nt][0], 0.f) * w2v[nt][0];
                p1 += fmaxf(d[nt][3] + b1v[nt][1], 0.f) * w2v[nt][1];
            }
            sPart[(mt * 16 + g) * 17 + w * 4 + tg]     = p0;
            sPart[(mt * 16 + g + 8) * 17 + w * 4 + tg] = p1;
        }
        __syncthreads();

        if (tid < 64) {
            float s = 0.f;
#pragma unroll
            for (int q = 0; q < 16; q++) s += sPart[tid * 17 + q];
            out[row0 + tid] = s + outb;
        }
        __syncthreads();
        buf ^= 1;
    }
}

// ---------------- launch ----------------
extern "C" void kernel_launch(void* const* d_in, const int* in_sizes, int n_in,
                              void* d_out, int out_size) {
    (void)in_sizes; (void)n_in; (void)out_size;
    const float* x    = (const float*)d_in[0];
    const float* e1w  = (const float*)d_in[1];
    const float* e1b  = (const float*)d_in[2];
    const float* e2w  = (const float*)d_in[3];
    const float* e2b  = (const float*)d_in[4];
    const float* wih  = (const float*)d_in[5];
    const float* whh  = (const float*)d_in[6];
    const float* d1w  = (const float*)d_in[7];
    const float* d1b  = (const float*)d_in[8];
    const float* d2w  = (const float*)d_in[9];
    const float* d2b  = (const float*)d_in[10];
    float* out = (float*)d_out;

    static bool attr_done = false;
    if (!attr_done) {
        cudaFuncSetAttribute(encoder_kernel, cudaFuncAttributeMaxDynamicSharedMemorySize, ENC_SMEM);
        cudaFuncSetAttribute(lstm_kernel, cudaFuncAttributeMaxDynamicSharedMemorySize, REC_SMEM);
        cudaFuncSetAttribute(decoder_kernel, cudaFuncAttributeMaxDynamicSharedMemorySize, DEC_SMEM);
        attr_done = true;
    }

    prep_kernel<<<662, 256>>>(wih, whh, e2w, e2b, d1w);
    encoder_kernel<<<148, 128, ENC_SMEM>>>(x, e1w, e1b);
    lstm_kernel<<<128, 256, REC_SMEM>>>();
    decoder_kernel<<<148, 128, DEC_SMEM>>>(d1b, d2w, d2b, out);
}

// round 8
// speedup vs baseline: 8.3458x; 1.2185x over previous
#include <cuda_runtime.h>
#include <cuda_fp16.h>
#include <cstdint>

#define Nn 1024
#define Tt 512
#define Hh 128
#define Gg 512
#define NTT (Nn*Tt)
#define WPAD 136

// ---------------- device scratch ----------------
__device__ __half g_xg[(size_t)NTT * Gg];     // 512 MB fp16: xg = F1 @ M^T + bxg
__device__ __half g_hcat[(size_t)NTT * 256];  // 256 MB fp16: relu(h) [row][fw128|bw128]
__device__ __half g_whh_h[512 * WPAD];        // fp16 w_hh [j][k] padded
__device__ __half g_M_h[512 * WPAD];          // fp16 M = wih@e2w  [j][h] padded
__device__ float  g_bxg[512];                 // wih @ b2
__device__ __half g_dec1h[128 * 264];         // fp16 dec1 [o][k] padded (k stride 264)

__device__ __forceinline__ float tanh_a(float x) {
    float y; asm("tanh.approx.f32 %0, %1;" : "=f"(y) : "f"(x)); return y;
}
__device__ __forceinline__ float sigm_a(float x) {
    return fmaf(tanh_a(0.5f * x), 0.5f, 0.5f);
}

__device__ __forceinline__ void cp16(void* smem_dst, const void* gsrc) {
    unsigned s = (unsigned)__cvta_generic_to_shared(smem_dst);
    asm volatile("cp.async.ca.shared.global [%0], [%1], 16;" :: "r"(s), "l"(gsrc));
}
__device__ __forceinline__ void cp_commit() { asm volatile("cp.async.commit_group;"); }
__device__ __forceinline__ void cp_wait1()  { asm volatile("cp.async.wait_group 1;"); }
__device__ __forceinline__ void cp_wait0()  { asm volatile("cp.async.wait_group 0;"); }

__device__ __forceinline__ void ldsm4(uint32_t addr, uint32_t& r0, uint32_t& r1,
                                      uint32_t& r2, uint32_t& r3) {
    asm volatile("ldmatrix.sync.aligned.m8n8.x4.shared.b16 {%0,%1,%2,%3}, [%4];"
                 : "=r"(r0), "=r"(r1), "=r"(r2), "=r"(r3) : "r"(addr));
}
__device__ __forceinline__ void mma16816(float* d, uint32_t a0, uint32_t a1, uint32_t a2,
                                         uint32_t a3, uint32_t b0, uint32_t b1) {
    asm volatile(
        "mma.sync.aligned.m16n8k16.row.col.f32.f16.f16.f32 "
        "{%0,%1,%2,%3}, {%4,%5,%6,%7}, {%8,%9}, {%0,%1,%2,%3};"
        : "+f"(d[0]), "+f"(d[1]), "+f"(d[2]), "+f"(d[3])
        : "r"(a0), "r"(a1), "r"(a2), "r"(a3), "r"(b0), "r"(b1));
}

// ---------------- K0: weight prep ----------------
__global__ void prep_kernel(const float* __restrict__ wih, const float* __restrict__ whh,
                            const float* __restrict__ e2w, const float* __restrict__ e2b,
                            const float* __restrict__ dec1) {
    int i = blockIdx.x * blockDim.x + threadIdx.x;
    if (i < 65536) {
        int j = i >> 7, h = i & 127;
        float s = 0.f;
#pragma unroll 4
        for (int o = 0; o < 128; o++) s += wih[j * 128 + o] * e2w[o * 128 + h];
        g_M_h[j * WPAD + h] = __float2half(s);
    } else if (i < 66048) {
        int j = i - 65536;
        float s = 0.f;
#pragma unroll 4
        for (int o = 0; o < 128; o++) s += e2b[o] * wih[j * 128 + o];
        g_bxg[j] = s;
    } else if (i < 135680) {
        int p = i - 66048;
        int j = p / WPAD, k = p % WPAD;
        g_whh_h[p] = (k < 128) ? __float2half(whh[j * 128 + k]) : __float2half(0.f);
    } else if (i < 169472) {
        int p = i - 135680;
        int j = p / 264, k = p % 264;
        g_dec1h[p] = (k < 256) ? __float2half(dec1[j * 256 + k]) : __float2half(0.f);
    }
}

// ---------------- K1: encoder (persistent, tensor-core, fp16 out) — unchanged R7 ----------------
#define ENC_OFF_AHI 139264
#define ENC_OFF_BXG 156672
#define ENC_OFF_E1W 158720
#define ENC_OFF_E1B 159744
#define ENC_SMEM    160256
__global__ __launch_bounds__(128, 1) void encoder_kernel(
    const float* __restrict__ x, const float* __restrict__ e1w,
    const float* __restrict__ e1b) {
    extern __shared__ char smraw[];
    __half* sM   = (__half*)smraw;
    __half* sAhi = (__half*)(smraw + ENC_OFF_AHI);
    float*  sBxg = (float*)(smraw + ENC_OFF_BXG);
    float*  sE1w = (float*)(smraw + ENC_OFF_E1W);
    float*  sE1b = (float*)(smraw + ENC_OFF_E1B);

    int tid = threadIdx.x, w = tid >> 5, l = tid & 31;

    for (int i = tid; i < 8704; i += 128) cp16(((uint4*)sM) + i, ((const uint4*)g_M_h) + i);
    cp_commit();
    for (int i = tid; i < 512; i += 128) sBxg[i] = g_bxg[i];
    for (int i = tid; i < 256; i += 128) sE1w[i] = e1w[i];
    if (tid < 128) sE1b[tid] = e1b[tid];
    cp_wait0();
    __syncthreads();

    const int lrow = (l & 7) + ((l >> 3) & 1) * 8;
    const int lcol = (l >> 4) * 8;
    const int jw = w * 128;
    const int g = l >> 2, tg = l & 3;
    uint32_t sMb   = (uint32_t)__cvta_generic_to_shared(sM);
    uint32_t sAhib = (uint32_t)__cvta_generic_to_shared(sAhi);

    const int fr = tid >> 1, fh0 = (tid & 1) * 64;

    for (int blk = blockIdx.x; blk < NTT / 64; blk += gridDim.x) {
        int row0 = blk * 64;
        float x0 = x[(size_t)(row0 + fr) * 2];
        float x1 = x[(size_t)(row0 + fr) * 2 + 1];
#pragma unroll
        for (int hh = 0; hh < 64; hh += 2) {
            int h = fh0 + hh;
            float v0 = fmaxf(sE1w[2 * h]     * x0 + sE1w[2 * h + 1] * x1 + sE1b[h], 0.f);
            float v1 = fmaxf(sE1w[2 * h + 2] * x0 + sE1w[2 * h + 3] * x1 + sE1b[h + 1], 0.f);
            *(__half2*)&sAhi[fr * WPAD + h] = __floats2half2_rn(v0, v1);
        }
        __syncthreads();

#pragma unroll
        for (int mt = 0; mt < 4; mt++) {
            float d[16][4];
#pragma unroll
            for (int nt = 0; nt < 16; nt++)
#pragma unroll
                for (int e = 0; e < 4; e++) d[nt][e] = 0.f;
#pragma unroll
            for (int ks = 0; ks < 8; ks++) {
                uint32_t aoff = (uint32_t)(((mt * 16 + lrow) * WPAD + ks * 16 + lcol) << 1);
                uint32_t ah0, ah1, ah2, ah3;
                ldsm4(sAhib + aoff, ah0, ah1, ah2, ah3);
#pragma unroll
                for (int np = 0; np < 8; np++) {
                    uint32_t boff = (uint32_t)(((jw + np * 16 + lrow) * WPAD + ks * 16 + lcol) << 1);
                    uint32_t b0, b1, b2, b3;
                    ldsm4(sMb + boff, b0, b1, b2, b3);
                    mma16816(d[2 * np],     ah0, ah1, ah2, ah3, b0, b2);
                    mma16816(d[2 * np + 1], ah0, ah1, ah2, ah3, b1, b3);
                }
            }
            size_t rb0 = (size_t)(row0 + mt * 16 + g) * 512;
            size_t rb1 = rb0 + (size_t)8 * 512;
#pragma unroll
            for (int nt = 0; nt < 16; nt++) {
                int col = jw + nt * 8 + 2 * tg;
                float b0v = sBxg[col], b1v = sBxg[col + 1];
                *(__half2*)&g_xg[rb0 + col] = __floats2half2_rn(d[nt][0] + b0v, d[nt][1] + b1v);
                *(__half2*)&g_xg[rb1 + col] = __floats2half2_rn(d[nt][2] + b0v, d[nt][3] + b1v);
            }
        }
        __syncthreads();
    }
}

// ---------------- K2: bidirectional LSTM — smem-staged xg/relu, tanh.approx ----------------
// smem: sW 139264 | sH 2x4352 | sXG 2x16640 ([16][520] half) | sRelu 2x4352 ([16][136] half)
#define REC_OFF_H    139264
#define REC_HBUF     4352
#define REC_OFF_XG   (REC_OFF_H + 2 * REC_HBUF)          // 147968
#define REC_XGBUF    16640
#define SXG_STRIDE   520
#define REC_OFF_RELU (REC_OFF_XG + 2 * REC_XGBUF)        // 181248
#define REC_RELUBUF  4352
#define REC_SMEM     (REC_OFF_RELU + 2 * REC_RELUBUF)    // 189952

__global__ __launch_bounds__(256, 1) void lstm_kernel() {
    extern __shared__ char smraw[];
    __half* sW = (__half*)smraw;

    int tid = threadIdx.x;
    int w = tid >> 5, l = tid & 31;
    int dir = blockIdx.x & 1;
    int n0 = (blockIdx.x >> 1) * 16;

    {
        const uint4* src = (const uint4*)g_whh_h;
        uint4* dst = (uint4*)sW;
        for (int i = tid; i < 8704; i += 256) dst[i] = src[i];
    }
    for (int i = tid; i < 1088; i += 256) ((uint32_t*)(smraw + REC_OFF_H))[i] = 0u;

    const int lrow = (l & 7) + ((l >> 3) & 1) * 8;
    const int lcol = (l >> 4) * 8;
    const int g = l >> 2, tg = l & 3;
    const int wband = w * 16;    // 8 warps x 16 hidden cols

    uint32_t sWb = (uint32_t)__cvta_generic_to_shared(sW);
    uint32_t sHb = (uint32_t)__cvta_generic_to_shared(smraw + REC_OFF_H);

    // relu-store geometry: thread -> (row, 16B chunk)
    const int sr = tid >> 4, sck = tid & 15;

    float c[2][2][2];
#pragma unroll
    for (int r2 = 0; r2 < 2; r2++)
#pragma unroll
        for (int nt = 0; nt < 2; nt++) { c[r2][nt][0] = 0.f; c[r2][nt][1] = 0.f; }

    // prefetch xg for step 0 into sXG[0]
    {
        int t0 = dir ? 511 : 0;
        __half* dst = (__half*)(smraw + REC_OFF_XG);
#pragma unroll
        for (int it = 0; it < 4; it++) {
            int idx = it * 256 + tid;
            int r = idx >> 6, ck = idx & 63;
            cp16(dst + r * SXG_STRIDE + ck * 8,
                 g_xg + ((size_t)(n0 + r) * Tt + t0) * 512 + ck * 8);
        }
        cp_commit();
    }
    __syncthreads();

    for (int step = 0; step < 512; step++) {
        int t = dir ? (511 - step) : step;

        // 1) coalesced STG of relu(h) for step-1
        if (step > 0) {
            int tp = dir ? (512 - step) : (step - 1);
            const __half* src =
                (const __half*)(smraw + REC_OFF_RELU + ((step + 1) & 1) * REC_RELUBUF);
            uint4 v = *(const uint4*)&src[sr * WPAD + sck * 8];
            *(uint4*)&g_hcat[((size_t)(n0 + sr) * Tt + tp) * 256 + dir * 128 + sck * 8] = v;
        }

        // 2) prefetch xg for step+1
        if (step + 1 < 512) {
            int tn = dir ? (510 - step) : (step + 1);
            __half* dst = (__half*)(smraw + REC_OFF_XG + ((step + 1) & 1) * REC_XGBUF);
#pragma unroll
            for (int it = 0; it < 4; it++) {
                int idx = it * 256 + tid;
                int r = idx >> 6, ck = idx & 63;
                cp16(dst + r * SXG_STRIDE + ck * 8,
                     g_xg + ((size_t)(n0 + r) * Tt + tn) * 512 + ck * 8);
            }
            cp_commit();
        }

        // 3) MMA: gates = h @ W^T for this warp's (4 gates x 16 cols) band
        uint32_t hcur = sHb + (uint32_t)(step & 1) * REC_HBUF;
        float d[4][2][4];
#pragma unroll
        for (int gate = 0; gate < 4; gate++)
#pragma unroll
            for (int nt = 0; nt < 2; nt++)
#pragma unroll
                for (int e = 0; e < 4; e++) d[gate][nt][e] = 0.f;

#pragma unroll
        for (int ks = 0; ks < 8; ks++) {
            int k0 = ks * 16;
            uint32_t ah0, ah1, ah2, ah3;
            ldsm4(hcur + (uint32_t)((lrow * WPAD + k0 + lcol) << 1), ah0, ah1, ah2, ah3);
#pragma unroll
            for (int gate = 0; gate < 4; gate++) {
                int j0 = gate * 128 + wband;
                uint32_t b0, b1, b2, b3;
                ldsm4(sWb + (uint32_t)(((j0 + lrow) * WPAD + k0 + lcol) << 1), b0, b1, b2, b3);
                mma16816(d[gate][0], ah0, ah1, ah2, ah3, b0, b2);
                mma16816(d[gate][1], ah0, ah1, ah2, ah3, b1, b3);
            }
        }

        // 4) wait for this step's xg, make visible
        if (step + 1 < 512) cp_wait1(); else cp_wait0();
        __syncthreads();

        // 5) activation (registers + conflict-free LDS from sXG)
        const __half* sxg = (const __half*)(smraw + REC_OFF_XG + (step & 1) * REC_XGBUF);
        __half* hnxt = (__half*)(smraw + REC_OFF_H + ((step + 1) & 1) * REC_HBUF);
        __half* srel = (__half*)(smraw + REC_OFF_RELU + (step & 1) * REC_RELUBUF);

#pragma unroll
        for (int r2 = 0; r2 < 2; r2++) {
            int m = g + r2 * 8;
#pragma unroll
            for (int nt = 0; nt < 2; nt++) {
                int col = wband + nt * 8 + 2 * tg;
                float2 xi  = __half22float2(*(const __half2*)&sxg[m * SXG_STRIDE + col]);
                float2 xf  = __half22float2(*(const __half2*)&sxg[m * SXG_STRIDE + 128 + col]);
                float2 xgg = __half22float2(*(const __half2*)&sxg[m * SXG_STRIDE + 256 + col]);
                float2 xo  = __half22float2(*(const __half2*)&sxg[m * SXG_STRIDE + 384 + col]);
                float hv[2];
#pragma unroll
                for (int e = 0; e < 2; e++) {
                    int fe = r2 * 2 + e;
                    float iv = d[0][nt][fe] + ((const float*)&xi)[e];
                    float fv = d[1][nt][fe] + ((const float*)&xf)[e];
                    float gv = d[2][nt][fe] + ((const float*)&xgg)[e];
                    float ov = d[3][nt][fe] + ((const float*)&xo)[e];
                    float cn = sigm_a(fv) * c[r2][nt][e] + sigm_a(iv) * tanh_a(gv);
                    c[r2][nt][e] = cn;
                    hv[e] = sigm_a(ov) * tanh_a(cn);
                }
                *(__half2*)&hnxt[m * WPAD + col] = __floats2half2_rn(hv[0], hv[1]);
                *(__half2*)&srel[m * WPAD + col] =
                    __floats2half2_rn(fmaxf(hv[0], 0.f), fmaxf(hv[1], 0.f));
            }
        }
        __syncthreads();  // hnxt + srel visible for next iteration
    }

    // final relu tile (step 511)
    {
        int tp = dir ? 0 : 511;
        const __half* src = (const __half*)(smraw + REC_OFF_RELU + 1 * REC_RELUBUF);
        uint4 v = *(const uint4*)&src[sr * WPAD + sck * 8];
        *(uint4*)&g_hcat[((size_t)(n0 + sr) * Tt + tp) * 256 + dir * 128 + sck * 8] = v;
    }
}

// ---------------- K3: decoder (persistent, tensor-core, direct fp16 tiles) — unchanged R7 ----------------
#define DEC_OFF_T0  67584
#define DEC_TBUF    33792
#define DEC_OFF_PART (DEC_OFF_T0 + 2 * DEC_TBUF)
#define DEC_SMEM    (DEC_OFF_PART + 64 * 17 * 4)

__device__ __forceinline__ void dec_load_tile(char* smraw, int buf, int blk, int tid) {
    __half* dst = (__half*)(smraw + DEC_OFF_T0 + buf * DEC_TBUF);
    size_t row0 = (size_t)blk * 64;
#pragma unroll
    for (int it = 0; it < 16; it++) {
        int idx = it * 128 + tid;
        int r = idx >> 5, ck = idx & 31;
        cp16(dst + r * 264 + ck * 8, g_hcat + (row0 + r) * 256 + ck * 8);
    }
}

__global__ __launch_bounds__(128, 1) void decoder_kernel(
    const float* __restrict__ d1b, const float* __restrict__ d2w,
    const float* __restrict__ d2b, float* __restrict__ out) {
    extern __shared__ char smraw[];
    __half* sB = (__half*)smraw;
    float* sPart = (float*)(smraw + DEC_OFF_PART);

    int tid = threadIdx.x, w = tid >> 5, l = tid & 31;

    for (int i = tid; i < 4224; i += 128) cp16(((uint4*)sB) + i, ((const uint4*)g_dec1h) + i);
    cp_commit();

    const int lrow = (l & 7) + ((l >> 3) & 1) * 8;
    const int lcol = (l >> 4) * 8;
    const int jw = w * 32;
    const int g = l >> 2, tg = l & 3;
    uint32_t sBb = (uint32_t)__cvta_generic_to_shared(sB);
    uint32_t sTb = (uint32_t)__cvta_generic_to_shared(smraw + DEC_OFF_T0);

    float b1v[4][2], w2v[4][2];
#pragma unroll
    for (int nt = 0; nt < 4; nt++)
#pragma unroll
        for (int e = 0; e < 2; e++) {
            int col = jw + nt * 8 + 2 * tg + e;
            b1v[nt][e] = d1b[col];
            w2v[nt][e] = d2w[col];
        }
    float outb = d2b[0];
    cp_wait0();

    int blk = blockIdx.x;
    int buf = 0;
    dec_load_tile(smraw, buf, blk, tid);
    cp_commit();

    for (; blk < NTT / 64; blk += gridDim.x) {
        int nxt = blk + gridDim.x;
        if (nxt < NTT / 64) {
            dec_load_tile(smraw, buf ^ 1, nxt, tid);
            cp_commit();
            cp_wait1();
        } else {
            cp_wait0();
        }
        __syncthreads();

        uint32_t sAb = sTb + (uint32_t)buf * DEC_TBUF;
        int row0 = blk * 64;
#pragma unroll
        for (int mt = 0; mt < 4; mt++) {
            float d[4][4];
#pragma unroll
            for (int nt = 0; nt < 4; nt++)
#pragma unroll
                for (int e = 0; e < 4; e++) d[nt][e] = 0.f;
#pragma unroll
            for (int ks = 0; ks < 16; ks++) {
                uint32_t aoff = (uint32_t)(((mt * 16 + lrow) * 264 + ks * 16 + lcol) << 1);
                uint32_t ah0, ah1, ah2, ah3;
                ldsm4(sAb + aoff, ah0, ah1, ah2, ah3);
#pragma unroll
                for (int np = 0; np < 2; np++) {
                    uint32_t boff = (uint32_t)(((jw + np * 16 + lrow) * 264 + ks * 16 + lcol) << 1);
                    uint32_t b0, b1, b2, b3;
                    ldsm4(sBb + boff, b0, b1, b2, b3);
                    mma16816(d[2 * np],     ah0, ah1, ah2, ah3, b0, b2);
                    mma16816(d[2 * np + 1], ah0, ah1, ah2, ah3, b1, b3);
                }
            }
            float p0 = 0.f, p1 = 0.f;
#pragma unroll
            for (int nt = 0; nt < 4; nt++) {
                p0 += fmaxf(d[nt][0] + b1v[nt][0], 0.f) * w2v[nt][0];
                p0 += fmaxf(d[nt][1] + b1v[nt][1], 0.f) * w2v[nt][1];
                p1 += fmaxf(d[nt][2] + b1v[nt][0], 0.f) * w2v[nt][0];
                p1 += fmaxf(d[nt][3] + b1v[nt][1], 0.f) * w2v[nt][1];
            }
            sPart[(mt * 16 + g) * 17 + w * 4 + tg]     = p0;
            sPart[(mt * 16 + g + 8) * 17 + w * 4 + tg] = p1;
        }
        __syncthreads();

        if (tid < 64) {
            float s = 0.f;
#pragma unroll
            for (int q = 0; q < 16; q++) s += sPart[tid * 17 + q];
            out[row0 + tid] = s + outb;
        }
        __syncthreads();
        buf ^= 1;
    }
}

// ---------------- launch ----------------
extern "C" void kernel_launch(void* const* d_in, const int* in_sizes, int n_in,
                              void* d_out, int out_size) {
    (void)in_sizes; (void)n_in; (void)out_size;
    const float* x    = (const float*)d_in[0];
    const float* e1w  = (const float*)d_in[1];
    const float* e1b  = (const float*)d_in[2];
    const float* e2w  = (const float*)d_in[3];
    const float* e2b  = (const float*)d_in[4];
    const float* wih  = (const float*)d_in[5];
    const float* whh  = (const float*)d_in[6];
    const float* d1w  = (const float*)d_in[7];
    const float* d1b  = (const float*)d_in[8];
    const float* d2w  = (const float*)d_in[9];
    const float* d2b  = (const float*)d_in[10];
    float* out = (float*)d_out;

    static bool attr_done = false;
    if (!attr_done) {
        cudaFuncSetAttribute(encoder_kernel, cudaFuncAttributeMaxDynamicSharedMemorySize, ENC_SMEM);
        cudaFuncSetAttribute(lstm_kernel, cudaFuncAttributeMaxDynamicSharedMemorySize, REC_SMEM);
        cudaFuncSetAttribute(decoder_kernel, cudaFuncAttributeMaxDynamicSharedMemorySize, DEC_SMEM);
        attr_done = true;
    }

    prep_kernel<<<662, 256>>>(wih, whh, e2w, e2b, d1w);
    encoder_kernel<<<148, 128, ENC_SMEM>>>(x, e1w, e1b);
    lstm_kernel<<<128, 256, REC_SMEM>>>();
    decoder_kernel<<<148, 128, DEC_SMEM>>>(d1b, d2w, d2b, out);
}

// round 9
// speedup vs baseline: 10.9764x; 1.3152x over previous
#include <cuda_runtime.h>
#include <cuda_fp16.h>
#include <cstdint>

#define Nn 1024
#define Tt 512
#define Hh 128
#define Gg 512
#define NTT (Nn*Tt)
#define WPAD 136

// ---------------- device scratch ----------------
__device__ __half g_xg[(size_t)NTT * Gg];     // 512 MB fp16: xg = F1 @ M^T + bxg
__device__ __half g_hcat[(size_t)NTT * 256];  // 256 MB fp16: relu(h) [row][fw128|bw128]
__device__ __half g_whh_h[512 * WPAD];        // fp16 w_hh [j][k] padded
__device__ __half g_M_h[512 * WPAD];          // fp16 M = wih@e2w  [j][h] padded
__device__ float  g_bxg[512];                 // wih @ b2
__device__ __half g_dec1h[128 * 264];         // fp16 dec1 [o][k] padded (k stride 264)

__device__ __forceinline__ float tanh_a(float x) {
    float y; asm("tanh.approx.f32 %0, %1;" : "=f"(y) : "f"(x)); return y;
}
__device__ __forceinline__ float sigm_a(float x) {
    return fmaf(tanh_a(0.5f * x), 0.5f, 0.5f);
}

__device__ __forceinline__ void cp16(void* smem_dst, const void* gsrc) {
    unsigned s = (unsigned)__cvta_generic_to_shared(smem_dst);
    asm volatile("cp.async.ca.shared.global [%0], [%1], 16;" :: "r"(s), "l"(gsrc));
}
__device__ __forceinline__ void cp_commit() { asm volatile("cp.async.commit_group;"); }
__device__ __forceinline__ void cp_wait1()  { asm volatile("cp.async.wait_group 1;"); }
__device__ __forceinline__ void cp_wait0()  { asm volatile("cp.async.wait_group 0;"); }

__device__ __forceinline__ void ldsm4(uint32_t addr, uint32_t& r0, uint32_t& r1,
                                      uint32_t& r2, uint32_t& r3) {
    asm volatile("ldmatrix.sync.aligned.m8n8.x4.shared.b16 {%0,%1,%2,%3}, [%4];"
                 : "=r"(r0), "=r"(r1), "=r"(r2), "=r"(r3) : "r"(addr));
}
__device__ __forceinline__ void mma16816(float* d, uint32_t a0, uint32_t a1, uint32_t a2,
                                         uint32_t a3, uint32_t b0, uint32_t b1) {
    asm volatile(
        "mma.sync.aligned.m16n8k16.row.col.f32.f16.f16.f32 "
        "{%0,%1,%2,%3}, {%4,%5,%6,%7}, {%8,%9}, {%0,%1,%2,%3};"
        : "+f"(d[0]), "+f"(d[1]), "+f"(d[2]), "+f"(d[3])
        : "r"(a0), "r"(a1), "r"(a2), "r"(a3), "r"(b0), "r"(b1));
}

// ---------------- K0: weight prep ----------------
__global__ void prep_kernel(const float* __restrict__ wih, const float* __restrict__ whh,
                            const float* __restrict__ e2w, const float* __restrict__ e2b,
                            const float* __restrict__ dec1) {
    int i = blockIdx.x * blockDim.x + threadIdx.x;
    if (i < 65536) {
        int j = i >> 7, h = i & 127;
        float s = 0.f;
#pragma unroll 4
        for (int o = 0; o < 128; o++) s += wih[j * 128 + o] * e2w[o * 128 + h];
        g_M_h[j * WPAD + h] = __float2half(s);
    } else if (i < 66048) {
        int j = i - 65536;
        float s = 0.f;
#pragma unroll 4
        for (int o = 0; o < 128; o++) s += e2b[o] * wih[j * 128 + o];
        g_bxg[j] = s;
    } else if (i < 135680) {
        int p = i - 66048;
        int j = p / WPAD, k = p % WPAD;
        g_whh_h[p] = (k < 128) ? __float2half(whh[j * 128 + k]) : __float2half(0.f);
    } else if (i < 169472) {
        int p = i - 135680;
        int j = p / 264, k = p % 264;
        g_dec1h[p] = (k < 256) ? __float2half(dec1[j * 256 + k]) : __float2half(0.f);
    }
}

// ---------------- K1: encoder (persistent, tensor-core, 256 threads) ----------------
#define ENC_OFF_AHI 139264
#define ENC_OFF_BXG 156672
#define ENC_OFF_E1W 158720
#define ENC_OFF_E1B 159744
#define ENC_SMEM    160256
__global__ __launch_bounds__(256, 1) void encoder_kernel(
    const float* __restrict__ x, const float* __restrict__ e1w,
    const float* __restrict__ e1b) {
    extern __shared__ char smraw[];
    __half* sM   = (__half*)smraw;
    __half* sAhi = (__half*)(smraw + ENC_OFF_AHI);
    float*  sBxg = (float*)(smraw + ENC_OFF_BXG);
    float*  sE1w = (float*)(smraw + ENC_OFF_E1W);
    float*  sE1b = (float*)(smraw + ENC_OFF_E1B);

    int tid = threadIdx.x, w = tid >> 5, l = tid & 31;

    for (int i = tid; i < 8704; i += 256) cp16(((uint4*)sM) + i, ((const uint4*)g_M_h) + i);
    cp_commit();
    for (int i = tid; i < 512; i += 256) sBxg[i] = g_bxg[i];
    if (tid < 256) sE1w[tid] = e1w[tid];
    if (tid < 128) sE1b[tid] = e1b[tid];
    cp_wait0();
    __syncthreads();

    const int lrow = (l & 7) + ((l >> 3) & 1) * 8;
    const int lcol = (l >> 4) * 8;
    const int jw = w * 64;               // 8 warps x 64 gate-cols
    const int g = l >> 2, tg = l & 3;
    uint32_t sMb   = (uint32_t)__cvta_generic_to_shared(sM);
    uint32_t sAhib = (uint32_t)__cvta_generic_to_shared(sAhi);

    const int fr = tid >> 2, fh0 = (tid & 3) * 32;

    for (int blk = blockIdx.x; blk < NTT / 64; blk += gridDim.x) {
        int row0 = blk * 64;
        float x0 = x[(size_t)(row0 + fr) * 2];
        float x1 = x[(size_t)(row0 + fr) * 2 + 1];
#pragma unroll
        for (int hh = 0; hh < 32; hh += 2) {
            int h = fh0 + hh;
            float v0 = fmaxf(sE1w[2 * h]     * x0 + sE1w[2 * h + 1] * x1 + sE1b[h], 0.f);
            float v1 = fmaxf(sE1w[2 * h + 2] * x0 + sE1w[2 * h + 3] * x1 + sE1b[h + 1], 0.f);
            *(__half2*)&sAhi[fr * WPAD + h] = __floats2half2_rn(v0, v1);
        }
        __syncthreads();

#pragma unroll
        for (int mt = 0; mt < 4; mt++) {
            float d[8][4];
#pragma unroll
            for (int nt = 0; nt < 8; nt++)
#pragma unroll
                for (int e = 0; e < 4; e++) d[nt][e] = 0.f;
#pragma unroll
            for (int ks = 0; ks < 8; ks++) {
                uint32_t aoff = (uint32_t)(((mt * 16 + lrow) * WPAD + ks * 16 + lcol) << 1);
                uint32_t ah0, ah1, ah2, ah3;
                ldsm4(sAhib + aoff, ah0, ah1, ah2, ah3);
#pragma unroll
                for (int np = 0; np < 4; np++) {
                    uint32_t boff = (uint32_t)(((jw + np * 16 + lrow) * WPAD + ks * 16 + lcol) << 1);
                    uint32_t b0, b1, b2, b3;
                    ldsm4(sMb + boff, b0, b1, b2, b3);
                    mma16816(d[2 * np],     ah0, ah1, ah2, ah3, b0, b2);
                    mma16816(d[2 * np + 1], ah0, ah1, ah2, ah3, b1, b3);
                }
            }
            size_t rb0 = (size_t)(row0 + mt * 16 + g) * 512;
            size_t rb1 = rb0 + (size_t)8 * 512;
#pragma unroll
            for (int nt = 0; nt < 8; nt++) {
                int col = jw + nt * 8 + 2 * tg;
                float b0v = sBxg[col], b1v = sBxg[col + 1];
                *(__half2*)&g_xg[rb0 + col] = __floats2half2_rn(d[nt][0] + b0v, d[nt][1] + b1v);
                *(__half2*)&g_xg[rb1 + col] = __floats2half2_rn(d[nt][2] + b0v, d[nt][3] + b1v);
            }
        }
        __syncthreads();
    }
}

// ---------------- K2: bidirectional LSTM — 3-buffer xg, ONE barrier per step ----------------
// smem: sW 139264 | sH 2x4352 | sXG 3x16640 ([16][520] half) | sRelu 2x4352
#define REC_OFF_H    139264
#define REC_HBUF     4352
#define REC_OFF_XG   (REC_OFF_H + 2 * REC_HBUF)          // 147968
#define REC_XGBUF    16640
#define SXG_STRIDE   520
#define REC_OFF_RELU (REC_OFF_XG + 3 * REC_XGBUF)        // 197888
#define REC_RELUBUF  4352
#define REC_SMEM     (REC_OFF_RELU + 2 * REC_RELUBUF)    // 206592

__device__ __forceinline__ void lstm_xg_load(char* smraw, int buf, int n0, int t, int tid) {
    __half* dst = (__half*)(smraw + REC_OFF_XG + buf * REC_XGBUF);
#pragma unroll
    for (int it = 0; it < 4; it++) {
        int idx = it * 256 + tid;
        int r = idx >> 6, ck = idx & 63;
        cp16(dst + r * SXG_STRIDE + ck * 8,
             g_xg + ((size_t)(n0 + r) * Tt + t) * 512 + ck * 8);
    }
}

__global__ __launch_bounds__(256, 1) void lstm_kernel() {
    extern __shared__ char smraw[];
    __half* sW = (__half*)smraw;

    int tid = threadIdx.x;
    int w = tid >> 5, l = tid & 31;
    int dir = blockIdx.x & 1;
    int n0 = (blockIdx.x >> 1) * 16;

    {
        const uint4* src = (const uint4*)g_whh_h;
        uint4* dst = (uint4*)sW;
        for (int i = tid; i < 8704; i += 256) dst[i] = src[i];
    }
    for (int i = tid; i < 1088; i += 256) ((uint32_t*)(smraw + REC_OFF_H))[i] = 0u;

    const int lrow = (l & 7) + ((l >> 3) & 1) * 8;
    const int lcol = (l >> 4) * 8;
    const int g = l >> 2, tg = l & 3;
    const int wband = w * 16;    // 8 warps x 16 hidden cols

    uint32_t sWb = (uint32_t)__cvta_generic_to_shared(sW);
    uint32_t sHb = (uint32_t)__cvta_generic_to_shared(smraw + REC_OFF_H);

    const int sr = tid >> 4, sck = tid & 15;   // relu STG geometry

    float c[2][2][2];
#pragma unroll
    for (int r2 = 0; r2 < 2; r2++)
#pragma unroll
        for (int nt = 0; nt < 2; nt++) { c[r2][nt][0] = 0.f; c[r2][nt][1] = 0.f; }

    // prologue: prefetch xg for steps 0 and 1; drain step 0's group
    lstm_xg_load(smraw, 0, n0, dir ? 511 : 0, tid);
    cp_commit();
    lstm_xg_load(smraw, 1, n0, dir ? 510 : 1, tid);
    cp_commit();
    cp_wait1();
    __syncthreads();   // W, h0, sXG[0] all visible

    for (int step = 0; step < 512; step++) {
        int t = dir ? (511 - step) : step;

        // 1) coalesced STG of relu(h) for step-1
        if (step > 0) {
            int tp = dir ? (512 - step) : (step - 1);
            const __half* src =
                (const __half*)(smraw + REC_OFF_RELU + ((step + 1) & 1) * REC_RELUBUF);
            uint4 v = *(const uint4*)&src[sr * WPAD + sck * 8];
            *(uint4*)&g_hcat[((size_t)(n0 + sr) * Tt + tp) * 256 + dir * 128 + sck * 8] = v;
        }

        // 2) prefetch xg for step+2 (buffer was last read in iteration step-1)
        if (step + 2 < 512) {
            int tn = dir ? (509 - step) : (step + 2);
            lstm_xg_load(smraw, (step + 2) % 3, n0, tn, tid);
        }
        cp_commit();   // uniform group count even when empty

        // 3) MMA: gates = h @ W^T for this warp's (4 gates x 16 cols) band
        uint32_t hcur = sHb + (uint32_t)(step & 1) * REC_HBUF;
        float d[4][2][4];
#pragma unroll
        for (int gate = 0; gate < 4; gate++)
#pragma unroll
            for (int nt = 0; nt < 2; nt++)
#pragma unroll
                for (int e = 0; e < 4; e++) d[gate][nt][e] = 0.f;

#pragma unroll
        for (int ks = 0; ks < 8; ks++) {
            int k0 = ks * 16;
            uint32_t ah0, ah1, ah2, ah3;
            ldsm4(hcur + (uint32_t)((lrow * WPAD + k0 + lcol) << 1), ah0, ah1, ah2, ah3);
#pragma unroll
            for (int gate = 0; gate < 4; gate++) {
                int j0 = gate * 128 + wband;
                uint32_t b0, b1, b2, b3;
                ldsm4(sWb + (uint32_t)(((j0 + lrow) * WPAD + k0 + lcol) << 1), b0, b1, b2, b3);
                mma16816(d[gate][0], ah0, ah1, ah2, ah3, b0, b2);
                mma16816(d[gate][1], ah0, ah1, ah2, ah3, b1, b3);
            }
        }

        // 4) activation: sXG[step%3] already drained+visible (prev iteration's wait+barrier)
        const __half* sxg = (const __half*)(smraw + REC_OFF_XG + (step % 3) * REC_XGBUF);
        __half* hnxt = (__half*)(smraw + REC_OFF_H + ((step + 1) & 1) * REC_HBUF);
        __half* srel = (__half*)(smraw + REC_OFF_RELU + (step & 1) * REC_RELUBUF);

#pragma unroll
        for (int r2 = 0; r2 < 2; r2++) {
            int m = g + r2 * 8;
#pragma unroll
            for (int nt = 0; nt < 2; nt++) {
                int col = wband + nt * 8 + 2 * tg;
                float2 xi  = __half22float2(*(const __half2*)&sxg[m * SXG_STRIDE + col]);
                float2 xf  = __half22float2(*(const __half2*)&sxg[m * SXG_STRIDE + 128 + col]);
                float2 xgg = __half22float2(*(const __half2*)&sxg[m * SXG_STRIDE + 256 + col]);
                float2 xo  = __half22float2(*(const __half2*)&sxg[m * SXG_STRIDE + 384 + col]);
                float hv[2];
#pragma unroll
                for (int e = 0; e < 2; e++) {
                    int fe = r2 * 2 + e;
                    float iv = d[0][nt][fe] + ((const float*)&xi)[e];
                    float fv = d[1][nt][fe] + ((const float*)&xf)[e];
                    float gv = d[2][nt][fe] + ((const float*)&xgg)[e];
                    float ov = d[3][nt][fe] + ((const float*)&xo)[e];
                    float cn = sigm_a(fv) * c[r2][nt][e] + sigm_a(iv) * tanh_a(gv);
                    c[r2][nt][e] = cn;
                    hv[e] = sigm_a(ov) * tanh_a(cn);
                }
                *(__half2*)&hnxt[m * WPAD + col] = __floats2half2_rn(hv[0], hv[1]);
                *(__half2*)&srel[m * WPAD + col] =
                    __floats2half2_rn(fmaxf(hv[0], 0.f), fmaxf(hv[1], 0.f));
            }
        }

        // 5) drain step+1's cp group, then the single per-step barrier
        cp_wait1();
        __syncthreads();
    }

    // final relu tile (step 511)
    {
        int tp = dir ? 0 : 511;
        const __half* src = (const __half*)(smraw + REC_OFF_RELU + 1 * REC_RELUBUF);
        uint4 v = *(const uint4*)&src[sr * WPAD + sck * 8];
        *(uint4*)&g_hcat[((size_t)(n0 + sr) * Tt + tp) * 256 + dir * 128 + sck * 8] = v;
    }
}

// ---------------- K3: decoder (persistent, tensor-core, direct fp16 tiles) — unchanged ----------------
#define DEC_OFF_T0  67584
#define DEC_TBUF    33792
#define DEC_OFF_PART (DEC_OFF_T0 + 2 * DEC_TBUF)
#define DEC_SMEM    (DEC_OFF_PART + 64 * 17 * 4)

__device__ __forceinline__ void dec_load_tile(char* smraw, int buf, int blk, int tid) {
    __half* dst = (__half*)(smraw + DEC_OFF_T0 + buf * DEC_TBUF);
    size_t row0 = (size_t)blk * 64;
#pragma unroll
    for (int it = 0; it < 16; it++) {
        int idx = it * 128 + tid;
        int r = idx >> 5, ck = idx & 31;
        cp16(dst + r * 264 + ck * 8, g_hcat + (row0 + r) * 256 + ck * 8);
    }
}

__global__ __launch_bounds__(128, 1) void decoder_kernel(
    const float* __restrict__ d1b, const float* __restrict__ d2w,
    const float* __restrict__ d2b, float* __restrict__ out) {
    extern __shared__ char smraw[];
    __half* sB = (__half*)smraw;
    float* sPart = (float*)(smraw + DEC_OFF_PART);

    int tid = threadIdx.x, w = tid >> 5, l = tid & 31;

    for (int i = tid; i < 4224; i += 128) cp16(((uint4*)sB) + i, ((const uint4*)g_dec1h) + i);
    cp_commit();

    const int lrow = (l & 7) + ((l >> 3) & 1) * 8;
    const int lcol = (l >> 4) * 8;
    const int jw = w * 32;
    const int g = l >> 2, tg = l & 3;
    uint32_t sBb = (uint32_t)__cvta_generic_to_shared(sB);
    uint32_t sTb = (uint32_t)__cvta_generic_to_shared(smraw + DEC_OFF_T0);

    float b1v[4][2], w2v[4][2];
#pragma unroll
    for (int nt = 0; nt < 4; nt++)
#pragma unroll
        for (int e = 0; e < 2; e++) {
            int col = jw + nt * 8 + 2 * tg + e;
            b1v[nt][e] = d1b[col];
            w2v[nt][e] = d2w[col];
        }
    float outb = d2b[0];
    cp_wait0();

    int blk = blockIdx.x;
    int buf = 0;
    dec_load_tile(smraw, buf, blk, tid);
    cp_commit();

    for (; blk < NTT / 64; blk += gridDim.x) {
        int nxt = blk + gridDim.x;
        if (nxt < NTT / 64) {
            dec_load_tile(smraw, buf ^ 1, nxt, tid);
            cp_commit();
            cp_wait1();
        } else {
            cp_wait0();
        }
        __syncthreads();

        uint32_t sAb = sTb + (uint32_t)buf * DEC_TBUF;
        int row0 = blk * 64;
#pragma unroll
        for (int mt = 0; mt < 4; mt++) {
            float d[4][4];
#pragma unroll
            for (int nt = 0; nt < 4; nt++)
#pragma unroll
                for (int e = 0; e < 4; e++) d[nt][e] = 0.f;
#pragma unroll
            for (int ks = 0; ks < 16; ks++) {
                uint32_t aoff = (uint32_t)(((mt * 16 + lrow) * 264 + ks * 16 + lcol) << 1);
                uint32_t ah0, ah1, ah2, ah3;
                ldsm4(sAb + aoff, ah0, ah1, ah2, ah3);
#pragma unroll
                for (int np = 0; np < 2; np++) {
                    uint32_t boff = (uint32_t)(((jw + np * 16 + lrow) * 264 + ks * 16 + lcol) << 1);
                    uint32_t b0, b1, b2, b3;
                    ldsm4(sBb + boff, b0, b1, b2, b3);
                    mma16816(d[2 * np],     ah0, ah1, ah2, ah3, b0, b2);
                    mma16816(d[2 * np + 1], ah0, ah1, ah2, ah3, b1, b3);
                }
            }
            float p0 = 0.f, p1 = 0.f;
#pragma unroll
            for (int nt = 0; nt < 4; nt++) {
                p0 += fmaxf(d[nt][0] + b1v[nt][0], 0.f) * w2v[nt][0];
                p0 += fmaxf(d[nt][1] + b1v[nt][1], 0.f) * w2v[nt][1];
                p1 += fmaxf(d[nt][2] + b1v[nt][0], 0.f) * w2v[nt][0];
                p1 += fmaxf(d[nt][3] + b1v[nt][1], 0.f) * w2v[nt][1];
            }
            sPart[(mt * 16 + g) * 17 + w * 4 + tg]     = p0;
            sPart[(mt * 16 + g + 8) * 17 + w * 4 + tg] = p1;
        }
        __syncthreads();

        if (tid < 64) {
            float s = 0.f;
#pragma unroll
            for (int q = 0; q < 16; q++) s += sPart[tid * 17 + q];
            out[row0 + tid] = s + outb;
        }
        __syncthreads();
        buf ^= 1;
    }
}

// ---------------- launch ----------------
extern "C" void kernel_launch(void* const* d_in, const int* in_sizes, int n_in,
                              void* d_out, int out_size) {
    (void)in_sizes; (void)n_in; (void)out_size;
    const float* x    = (const float*)d_in[0];
    const float* e1w  = (const float*)d_in[1];
    const float* e1b  = (const float*)d_in[2];
    const float* e2w  = (const float*)d_in[3];
    const float* e2b  = (const float*)d_in[4];
    const float* wih  = (const float*)d_in[5];
    const float* whh  = (const float*)d_in[6];
    const float* d1w  = (const float*)d_in[7];
    const float* d1b  = (const float*)d_in[8];
    const float* d2w  = (const float*)d_in[9];
    const float* d2b  = (const float*)d_in[10];
    float* out = (float*)d_out;

    static bool attr_done = false;
    if (!attr_done) {
        cudaFuncSetAttribute(encoder_kernel, cudaFuncAttributeMaxDynamicSharedMemorySize, ENC_SMEM);
        cudaFuncSetAttribute(lstm_kernel, cudaFuncAttributeMaxDynamicSharedMemorySize, REC_SMEM);
        cudaFuncSetAttribute(decoder_kernel, cudaFuncAttributeMaxDynamicSharedMemorySize, DEC_SMEM);
        attr_done = true;
    }

    prep_kernel<<<662, 256>>>(wih, whh, e2w, e2b, d1w);
    encoder_kernel<<<148, 256, ENC_SMEM>>>(x, e1w, e1b);
    lstm_kernel<<<128, 256, REC_SMEM>>>();
    decoder_kernel<<<148, 128, DEC_SMEM>>>(d1b, d2w, d2b, out);
}

// round 10
// speedup vs baseline: 12.3608x; 1.1261x over previous
#include <cuda_runtime.h>
#include <cuda_fp16.h>
#include <cstdint>

#define Nn 1024
#define Tt 512
#define Hh 128
#define Gg 512
#define NTT (Nn*Tt)
#define WPAD 136

// ---------------- device scratch ----------------
__device__ __half g_xg[(size_t)NTT * Gg];     // 512 MB fp16: xg = F1 @ M^T + bxg
__device__ __half g_hcat[(size_t)NTT * 256];  // 256 MB fp16: relu(h) [row][fw128|bw128]
__device__ __half g_whh_h[512 * WPAD];        // fp16 w_hh [j][k] padded
__device__ __half g_M_h[512 * WPAD];          // fp16 M = wih@e2w  [j][h] padded
__device__ float  g_bxg[512];                 // wih @ b2
__device__ __half g_dec1h[128 * 264];         // fp16 dec1 [o][k] padded (k stride 264)

__device__ __forceinline__ float tanh_a(float x) {
    float y; asm("tanh.approx.f32 %0, %1;" : "=f"(y) : "f"(x)); return y;
}
__device__ __forceinline__ float sigm_a(float x) {
    return fmaf(tanh_a(0.5f * x), 0.5f, 0.5f);
}

__device__ __forceinline__ void cp16(void* smem_dst, const void* gsrc) {
    unsigned s = (unsigned)__cvta_generic_to_shared(smem_dst);
    asm volatile("cp.async.ca.shared.global [%0], [%1], 16;" :: "r"(s), "l"(gsrc));
}
__device__ __forceinline__ void cp_commit() { asm volatile("cp.async.commit_group;"); }
__device__ __forceinline__ void cp_wait1()  { asm volatile("cp.async.wait_group 1;"); }
__device__ __forceinline__ void cp_wait0()  { asm volatile("cp.async.wait_group 0;"); }

__device__ __forceinline__ void ldsm4(uint32_t addr, uint32_t& r0, uint32_t& r1,
                                      uint32_t& r2, uint32_t& r3) {
    asm volatile("ldmatrix.sync.aligned.m8n8.x4.shared.b16 {%0,%1,%2,%3}, [%4];"
                 : "=r"(r0), "=r"(r1), "=r"(r2), "=r"(r3) : "r"(addr));
}
__device__ __forceinline__ void mma16816(float* d, uint32_t a0, uint32_t a1, uint32_t a2,
                                         uint32_t a3, uint32_t b0, uint32_t b1) {
    asm volatile(
        "mma.sync.aligned.m16n8k16.row.col.f32.f16.f16.f32 "
        "{%0,%1,%2,%3}, {%4,%5,%6,%7}, {%8,%9}, {%0,%1,%2,%3};"
        : "+f"(d[0]), "+f"(d[1]), "+f"(d[2]), "+f"(d[3])
        : "r"(a0), "r"(a1), "r"(a2), "r"(a3), "r"(b0), "r"(b1));
}

// ---------------- K0: weight prep ----------------
__global__ void prep_kernel(const float* __restrict__ wih, const float* __restrict__ whh,
                            const float* __restrict__ e2w, const float* __restrict__ e2b,
                            const float* __restrict__ dec1) {
    int i = blockIdx.x * blockDim.x + threadIdx.x;
    if (i < 65536) {
        int j = i >> 7, h = i & 127;
        float s = 0.f;
#pragma unroll 4
        for (int o = 0; o < 128; o++) s += wih[j * 128 + o] * e2w[o * 128 + h];
        g_M_h[j * WPAD + h] = __float2half(s);
    } else if (i < 66048) {
        int j = i - 65536;
        float s = 0.f;
#pragma unroll 4
        for (int o = 0; o < 128; o++) s += e2b[o] * wih[j * 128 + o];
        g_bxg[j] = s;
    } else if (i < 135680) {
        int p = i - 66048;
        int j = p / WPAD, k = p % WPAD;
        g_whh_h[p] = (k < 128) ? __float2half(whh[j * 128 + k]) : __float2half(0.f);
    } else if (i < 169472) {
        int p = i - 135680;
        int j = p / 264, k = p % 264;
        g_dec1h[p] = (k < 256) ? __float2half(dec1[j * 256 + k]) : __float2half(0.f);
    }
}

// ---------------- K1: encoder (persistent, tensor-core, 256 threads) — unchanged R9 ----------------
#define ENC_OFF_AHI 139264
#define ENC_OFF_BXG 156672
#define ENC_OFF_E1W 158720
#define ENC_OFF_E1B 159744
#define ENC_SMEM    160256
__global__ __launch_bounds__(256, 1) void encoder_kernel(
    const float* __restrict__ x, const float* __restrict__ e1w,
    const float* __restrict__ e1b) {
    extern __shared__ char smraw[];
    __half* sM   = (__half*)smraw;
    __half* sAhi = (__half*)(smraw + ENC_OFF_AHI);
    float*  sBxg = (float*)(smraw + ENC_OFF_BXG);
    float*  sE1w = (float*)(smraw + ENC_OFF_E1W);
    float*  sE1b = (float*)(smraw + ENC_OFF_E1B);

    int tid = threadIdx.x, w = tid >> 5, l = tid & 31;

    for (int i = tid; i < 8704; i += 256) cp16(((uint4*)sM) + i, ((const uint4*)g_M_h) + i);
    cp_commit();
    for (int i = tid; i < 512; i += 256) sBxg[i] = g_bxg[i];
    if (tid < 256) sE1w[tid] = e1w[tid];
    if (tid < 128) sE1b[tid] = e1b[tid];
    cp_wait0();
    __syncthreads();

    const int lrow = (l & 7) + ((l >> 3) & 1) * 8;
    const int lcol = (l >> 4) * 8;
    const int jw = w * 64;               // 8 warps x 64 gate-cols
    const int g = l >> 2, tg = l & 3;
    uint32_t sMb   = (uint32_t)__cvta_generic_to_shared(sM);
    uint32_t sAhib = (uint32_t)__cvta_generic_to_shared(sAhi);

    const int fr = tid >> 2, fh0 = (tid & 3) * 32;

    for (int blk = blockIdx.x; blk < NTT / 64; blk += gridDim.x) {
        int row0 = blk * 64;
        float x0 = x[(size_t)(row0 + fr) * 2];
        float x1 = x[(size_t)(row0 + fr) * 2 + 1];
#pragma unroll
        for (int hh = 0; hh < 32; hh += 2) {
            int h = fh0 + hh;
            float v0 = fmaxf(sE1w[2 * h]     * x0 + sE1w[2 * h + 1] * x1 + sE1b[h], 0.f);
            float v1 = fmaxf(sE1w[2 * h + 2] * x0 + sE1w[2 * h + 3] * x1 + sE1b[h + 1], 0.f);
            *(__half2*)&sAhi[fr * WPAD + h] = __floats2half2_rn(v0, v1);
        }
        __syncthreads();

#pragma unroll
        for (int mt = 0; mt < 4; mt++) {
            float d[8][4];
#pragma unroll
            for (int nt = 0; nt < 8; nt++)
#pragma unroll
                for (int e = 0; e < 4; e++) d[nt][e] = 0.f;
#pragma unroll
            for (int ks = 0; ks < 8; ks++) {
                uint32_t aoff = (uint32_t)(((mt * 16 + lrow) * WPAD + ks * 16 + lcol) << 1);
                uint32_t ah0, ah1, ah2, ah3;
                ldsm4(sAhib + aoff, ah0, ah1, ah2, ah3);
#pragma unroll
                for (int np = 0; np < 4; np++) {
                    uint32_t boff = (uint32_t)(((jw + np * 16 + lrow) * WPAD + ks * 16 + lcol) << 1);
                    uint32_t b0, b1, b2, b3;
                    ldsm4(sMb + boff, b0, b1, b2, b3);
                    mma16816(d[2 * np],     ah0, ah1, ah2, ah3, b0, b2);
                    mma16816(d[2 * np + 1], ah0, ah1, ah2, ah3, b1, b3);
                }
            }
            size_t rb0 = (size_t)(row0 + mt * 16 + g) * 512;
            size_t rb1 = rb0 + (size_t)8 * 512;
#pragma unroll
            for (int nt = 0; nt < 8; nt++) {
                int col = jw + nt * 8 + 2 * tg;
                float b0v = sBxg[col], b1v = sBxg[col + 1];
                *(__half2*)&g_xg[rb0 + col] = __floats2half2_rn(d[nt][0] + b0v, d[nt][1] + b1v);
                *(__half2*)&g_xg[rb1 + col] = __floats2half2_rn(d[nt][2] + b0v, d[nt][3] + b1v);
            }
        }
        __syncthreads();
    }
}

// ---------------- K2: bidirectional LSTM — W fragments resident in registers ----------------
// smem: sW 139264 | sH 2x4352 | sXG 3x16640 ([16][520] half) | sRelu 2x4352
#define REC_OFF_H    139264
#define REC_HBUF     4352
#define REC_OFF_XG   (REC_OFF_H + 2 * REC_HBUF)          // 147968
#define REC_XGBUF    16640
#define SXG_STRIDE   520
#define REC_OFF_RELU (REC_OFF_XG + 3 * REC_XGBUF)        // 197888
#define REC_RELUBUF  4352
#define REC_SMEM     (REC_OFF_RELU + 2 * REC_RELUBUF)    // 206592

__device__ __forceinline__ void lstm_xg_load(char* smraw, int buf, int n0, int t, int tid) {
    __half* dst = (__half*)(smraw + REC_OFF_XG + buf * REC_XGBUF);
#pragma unroll
    for (int it = 0; it < 4; it++) {
        int idx = it * 256 + tid;
        int r = idx >> 6, ck = idx & 63;
        cp16(dst + r * SXG_STRIDE + ck * 8,
             g_xg + ((size_t)(n0 + r) * Tt + t) * 512 + ck * 8);
    }
}

__global__ __launch_bounds__(256, 1) void lstm_kernel() {
    extern __shared__ char smraw[];
    __half* sW = (__half*)smraw;

    int tid = threadIdx.x;
    int w = tid >> 5, l = tid & 31;
    int dir = blockIdx.x & 1;
    int n0 = (blockIdx.x >> 1) * 16;

    {
        const uint4* src = (const uint4*)g_whh_h;
        uint4* dst = (uint4*)sW;
        for (int i = tid; i < 8704; i += 256) dst[i] = src[i];
    }
    for (int i = tid; i < 1088; i += 256) ((uint32_t*)(smraw + REC_OFF_H))[i] = 0u;

    const int lrow = (l & 7) + ((l >> 3) & 1) * 8;
    const int lcol = (l >> 4) * 8;
    const int g = l >> 2, tg = l & 3;
    const int wband = w * 16;    // 8 warps x 16 hidden cols

    uint32_t sWb = (uint32_t)__cvta_generic_to_shared(sW);
    uint32_t sHb = (uint32_t)__cvta_generic_to_shared(smraw + REC_OFF_H);

    const int sr = tid >> 4, sck = tid & 15;   // relu STG geometry

    float c[2][2][2];
#pragma unroll
    for (int r2 = 0; r2 < 2; r2++)
#pragma unroll
        for (int nt = 0; nt < 2; nt++) { c[r2][nt][0] = 0.f; c[r2][nt][1] = 0.f; }

    // prologue: prefetch xg for steps 0 and 1; drain step 0's group
    lstm_xg_load(smraw, 0, n0, dir ? 511 : 0, tid);
    cp_commit();
    lstm_xg_load(smraw, 1, n0, dir ? 510 : 1, tid);
    cp_commit();
    cp_wait1();
    __syncthreads();   // W, h0, sXG[0] all visible

    // hoist ALL W_hh fragments into registers (loop-invariant): [gate][ks][4]
    uint32_t bf[4][8][4];
#pragma unroll
    for (int ks = 0; ks < 8; ks++) {
        int k0 = ks * 16;
#pragma unroll
        for (int gate = 0; gate < 4; gate++) {
            int j0 = gate * 128 + wband;
            ldsm4(sWb + (uint32_t)(((j0 + lrow) * WPAD + k0 + lcol) << 1),
                  bf[gate][ks][0], bf[gate][ks][1], bf[gate][ks][2], bf[gate][ks][3]);
        }
    }

    for (int step = 0; step < 512; step++) {
        int t = dir ? (511 - step) : step;

        // 1) coalesced STG of relu(h) for step-1
        if (step > 0) {
            int tp = dir ? (512 - step) : (step - 1);
            const __half* src =
                (const __half*)(smraw + REC_OFF_RELU + ((step + 1) & 1) * REC_RELUBUF);
            uint4 v = *(const uint4*)&src[sr * WPAD + sck * 8];
            *(uint4*)&g_hcat[((size_t)(n0 + sr) * Tt + tp) * 256 + dir * 128 + sck * 8] = v;
        }

        // 2) prefetch xg for step+2 (buffer was last read in iteration step-1)
        if (step + 2 < 512) {
            int tn = dir ? (509 - step) : (step + 2);
            lstm_xg_load(smraw, (step + 2) % 3, n0, tn, tid);
        }
        cp_commit();   // uniform group count even when empty

        // 3) MMA: gates = h @ W^T; B operands live in registers
        uint32_t hcur = sHb + (uint32_t)(step & 1) * REC_HBUF;
        float d[4][2][4];
#pragma unroll
        for (int gate = 0; gate < 4; gate++)
#pragma unroll
            for (int nt = 0; nt < 2; nt++)
#pragma unroll
                for (int e = 0; e < 4; e++) d[gate][nt][e] = 0.f;

#pragma unroll
        for (int ks = 0; ks < 8; ks++) {
            int k0 = ks * 16;
            uint32_t ah0, ah1, ah2, ah3;
            ldsm4(hcur + (uint32_t)((lrow * WPAD + k0 + lcol) << 1), ah0, ah1, ah2, ah3);
#pragma unroll
            for (int gate = 0; gate < 4; gate++) {
                mma16816(d[gate][0], ah0, ah1, ah2, ah3, bf[gate][ks][0], bf[gate][ks][2]);
                mma16816(d[gate][1], ah0, ah1, ah2, ah3, bf[gate][ks][1], bf[gate][ks][3]);
            }
        }

        // 4) activation: sXG[step%3] already drained+visible
        const __half* sxg = (const __half*)(smraw + REC_OFF_XG + (step % 3) * REC_XGBUF);
        __half* hnxt = (__half*)(smraw + REC_OFF_H + ((step + 1) & 1) * REC_HBUF);
        __half* srel = (__half*)(smraw + REC_OFF_RELU + (step & 1) * REC_RELUBUF);

#pragma unroll
        for (int r2 = 0; r2 < 2; r2++) {
            int m = g + r2 * 8;
#pragma unroll
            for (int nt = 0; nt < 2; nt++) {
                int col = wband + nt * 8 + 2 * tg;
                float2 xi  = __half22float2(*(const __half2*)&sxg[m * SXG_STRIDE + col]);
                float2 xf  = __half22float2(*(const __half2*)&sxg[m * SXG_STRIDE + 128 + col]);
                float2 xgg = __half22float2(*(const __half2*)&sxg[m * SXG_STRIDE + 256 + col]);
                float2 xo  = __half22float2(*(const __half2*)&sxg[m * SXG_STRIDE + 384 + col]);
                float hv[2];
#pragma unroll
                for (int e = 0; e < 2; e++) {
                    int fe = r2 * 2 + e;
                    float iv = d[0][nt][fe] + ((const float*)&xi)[e];
                    float fv = d[1][nt][fe] + ((const float*)&xf)[e];
                    float gv = d[2][nt][fe] + ((const float*)&xgg)[e];
                    float ov = d[3][nt][fe] + ((const float*)&xo)[e];
                    float cn = sigm_a(fv) * c[r2][nt][e] + sigm_a(iv) * tanh_a(gv);
                    c[r2][nt][e] = cn;
                    hv[e] = sigm_a(ov) * tanh_a(cn);
                }
                *(__half2*)&hnxt[m * WPAD + col] = __floats2half2_rn(hv[0], hv[1]);
                *(__half2*)&srel[m * WPAD + col] =
                    __floats2half2_rn(fmaxf(hv[0], 0.f), fmaxf(hv[1], 0.f));
            }
        }

        // 5) drain step+1's cp group, then the single per-step barrier
        cp_wait1();
        __syncthreads();
    }

    // final relu tile (step 511)
    {
        int tp = dir ? 0 : 511;
        const __half* src = (const __half*)(smraw + REC_OFF_RELU + 1 * REC_RELUBUF);
        uint4 v = *(const uint4*)&src[sr * WPAD + sck * 8];
        *(uint4*)&g_hcat[((size_t)(n0 + sr) * Tt + tp) * 256 + dir * 128 + sck * 8] = v;
    }
}

// ---------------- K3: decoder (persistent, tensor-core, direct fp16 tiles) — unchanged ----------------
#define DEC_OFF_T0  67584
#define DEC_TBUF    33792
#define DEC_OFF_PART (DEC_OFF_T0 + 2 * DEC_TBUF)
#define DEC_SMEM    (DEC_OFF_PART + 64 * 17 * 4)

__device__ __forceinline__ void dec_load_tile(char* smraw, int buf, int blk, int tid) {
    __half* dst = (__half*)(smraw + DEC_OFF_T0 + buf * DEC_TBUF);
    size_t row0 = (size_t)blk * 64;
#pragma unroll
    for (int it = 0; it < 16; it++) {
        int idx = it * 128 + tid;
        int r = idx >> 5, ck = idx & 31;
        cp16(dst + r * 264 + ck * 8, g_hcat + (row0 + r) * 256 + ck * 8);
    }
}

__global__ __launch_bounds__(128, 1) void decoder_kernel(
    const float* __restrict__ d1b, const float* __restrict__ d2w,
    const float* __restrict__ d2b, float* __restrict__ out) {
    extern __shared__ char smraw[];
    __half* sB = (__half*)smraw;
    float* sPart = (float*)(smraw + DEC_OFF_PART);

    int tid = threadIdx.x, w = tid >> 5, l = tid & 31;

    for (int i = tid; i < 4224; i += 128) cp16(((uint4*)sB) + i, ((const uint4*)g_dec1h) + i);
    cp_commit();

    const int lrow = (l & 7) + ((l >> 3) & 1) * 8;
    const int lcol = (l >> 4) * 8;
    const int jw = w * 32;
    const int g = l >> 2, tg = l & 3;
    uint32_t sBb = (uint32_t)__cvta_generic_to_shared(sB);
    uint32_t sTb = (uint32_t)__cvta_generic_to_shared(smraw + DEC_OFF_T0);

    float b1v[4][2], w2v[4][2];
#pragma unroll
    for (int nt = 0; nt < 4; nt++)
#pragma unroll
        for (int e = 0; e < 2; e++) {
            int col = jw + nt * 8 + 2 * tg + e;
            b1v[nt][e] = d1b[col];
            w2v[nt][e] = d2w[col];
        }
    float outb = d2b[0];
    cp_wait0();

    int blk = blockIdx.x;
    int buf = 0;
    dec_load_tile(smraw, buf, blk, tid);
    cp_commit();

    for (; blk < NTT / 64; blk += gridDim.x) {
        int nxt = blk + gridDim.x;
        if (nxt < NTT / 64) {
            dec_load_tile(smraw, buf ^ 1, nxt, tid);
            cp_commit();
            cp_wait1();
        } else {
            cp_wait0();
        }
        __syncthreads();

        uint32_t sAb = sTb + (uint32_t)buf * DEC_TBUF;
        int row0 = blk * 64;
#pragma unroll
        for (int mt = 0; mt < 4; mt++) {
            float d[4][4];
#pragma unroll
            for (int nt = 0; nt < 4; nt++)
#pragma unroll
                for (int e = 0; e < 4; e++) d[nt][e] = 0.f;
#pragma unroll
            for (int ks = 0; ks < 16; ks++) {
                uint32_t aoff = (uint32_t)(((mt * 16 + lrow) * 264 + ks * 16 + lcol) << 1);
                uint32_t ah0, ah1, ah2, ah3;
                ldsm4(sAb + aoff, ah0, ah1, ah2, ah3);
#pragma unroll
                for (int np = 0; np < 2; np++) {
                    uint32_t boff = (uint32_t)(((jw + np * 16 + lrow) * 264 + ks * 16 + lcol) << 1);
                    uint32_t b0, b1, b2, b3;
                    ldsm4(sBb + boff, b0, b1, b2, b3);
                    mma16816(d[2 * np],     ah0, ah1, ah2, ah3, b0, b2);
                    mma16816(d[2 * np + 1], ah0, ah1, ah2, ah3, b1, b3);
                }
            }
            float p0 = 0.f, p1 = 0.f;
#pragma unroll
            for (int nt = 0; nt < 4; nt++) {
                p0 += fmaxf(d[nt][0] + b1v[nt][0], 0.f) * w2v[nt][0];
                p0 += fmaxf(d[nt][1] + b1v[nt][1], 0.f) * w2v[nt][1];
                p1 += fmaxf(d[nt][2] + b1v[nt][0], 0.f) * w2v[nt][0];
                p1 += fmaxf(d[nt][3] + b1v[nt][1], 0.f) * w2v[nt][1];
            }
            sPart[(mt * 16 + g) * 17 + w * 4 + tg]     = p0;
            sPart[(mt * 16 + g + 8) * 17 + w * 4 + tg] = p1;
        }
        __syncthreads();

        if (tid < 64) {
            float s = 0.f;
#pragma unroll
            for (int q = 0; q < 16; q++) s += sPart[tid * 17 + q];
            out[row0 + tid] = s + outb;
        }
        __syncthreads();
        buf ^= 1;
    }
}

// ---------------- launch ----------------
extern "C" void kernel_launch(void* const* d_in, const int* in_sizes, int n_in,
                              void* d_out, int out_size) {
    (void)in_sizes; (void)n_in; (void)out_size;
    const float* x    = (const float*)d_in[0];
    const float* e1w  = (const float*)d_in[1];
    const float* e1b  = (const float*)d_in[2];
    const float* e2w  = (const float*)d_in[3];
    const float* e2b  = (const float*)d_in[4];
    const float* wih  = (const float*)d_in[5];
    const float* whh  = (const float*)d_in[6];
    const float* d1w  = (const float*)d_in[7];
    const float* d1b  = (const float*)d_in[8];
    const float* d2w  = (const float*)d_in[9];
    const float* d2b  = (const float*)d_in[10];
    float* out = (float*)d_out;

    static bool attr_done = false;
    if (!attr_done) {
        cudaFuncSetAttribute(encoder_kernel, cudaFuncAttributeMaxDynamicSharedMemorySize, ENC_SMEM);
        cudaFuncSetAttribute(lstm_kernel, cudaFuncAttributeMaxDynamicSharedMemorySize, REC_SMEM);
        cudaFuncSetAttribute(decoder_kernel, cudaFuncAttributeMaxDynamicSharedMemorySize, DEC_SMEM);
        attr_done = true;
    }

    prep_kernel<<<662, 256>>>(wih, whh, e2w, e2b, d1w);
    encoder_kernel<<<148, 256, ENC_SMEM>>>(x, e1w, e1b);
    lstm_kernel<<<128, 256, REC_SMEM>>>();
    decoder_kernel<<<148, 128, DEC_SMEM>>>(d1b, d2w, d2b, out);
}

// round 11
// speedup vs baseline: 12.6171x; 1.0207x over previous
#include <cuda_runtime.h>
#include <cuda_fp16.h>
#include <cstdint>

#define Nn 1024
#define Tt 512
#define Hh 128
#define Gg 512
#define NTT (Nn*Tt)
#define WPAD 136

// ---------------- device scratch ----------------
__device__ __half g_xg[(size_t)NTT * Gg];     // 512 MB fp16: xg = F1 @ M^T + bxg
__device__ __half g_hcat[(size_t)NTT * 256];  // 256 MB fp16: relu(h) [row][fw128|bw128]
__device__ __half g_whh_h[512 * WPAD];        // fp16 w_hh [j][k] padded
__device__ __half g_M_h[512 * WPAD];          // fp16 M = wih@e2w  [j][h] padded
__device__ float  g_bxg[512];                 // wih @ b2
__device__ __half g_dec1h[128 * 264];         // fp16 dec1 [o][k] padded (k stride 264)

__device__ __forceinline__ float tanh_a(float x) {
    float y; asm("tanh.approx.f32 %0, %1;" : "=f"(y) : "f"(x)); return y;
}
__device__ __forceinline__ float sigm_a(float x) {
    return fmaf(tanh_a(0.5f * x), 0.5f, 0.5f);
}

__device__ __forceinline__ void cp16(void* smem_dst, const void* gsrc) {
    unsigned s = (unsigned)__cvta_generic_to_shared(smem_dst);
    asm volatile("cp.async.ca.shared.global [%0], [%1], 16;" :: "r"(s), "l"(gsrc));
}
__device__ __forceinline__ void cp_commit() { asm volatile("cp.async.commit_group;"); }
__device__ __forceinline__ void cp_wait1()  { asm volatile("cp.async.wait_group 1;"); }
__device__ __forceinline__ void cp_wait0()  { asm volatile("cp.async.wait_group 0;"); }

__device__ __forceinline__ void ldsm4(uint32_t addr, uint32_t& r0, uint32_t& r1,
                                      uint32_t& r2, uint32_t& r3) {
    asm volatile("ldmatrix.sync.aligned.m8n8.x4.shared.b16 {%0,%1,%2,%3}, [%4];"
                 : "=r"(r0), "=r"(r1), "=r"(r2), "=r"(r3) : "r"(addr));
}
__device__ __forceinline__ void mma16816(float* d, uint32_t a0, uint32_t a1, uint32_t a2,
                                         uint32_t a3, uint32_t b0, uint32_t b1) {
    asm volatile(
        "mma.sync.aligned.m16n8k16.row.col.f32.f16.f16.f32 "
        "{%0,%1,%2,%3}, {%4,%5,%6,%7}, {%8,%9}, {%0,%1,%2,%3};"
        : "+f"(d[0]), "+f"(d[1]), "+f"(d[2]), "+f"(d[3])
        : "r"(a0), "r"(a1), "r"(a2), "r"(a3), "r"(b0), "r"(b1));
}

// ---------------- K0: weight prep ----------------
__global__ void prep_kernel(const float* __restrict__ wih, const float* __restrict__ whh,
                            const float* __restrict__ e2w, const float* __restrict__ e2b,
                            const float* __restrict__ dec1) {
    int i = blockIdx.x * blockDim.x + threadIdx.x;
    if (i < 65536) {
        int j = i >> 7, h = i & 127;
        float s = 0.f;
#pragma unroll 4
        for (int o = 0; o < 128; o++) s += wih[j * 128 + o] * e2w[o * 128 + h];
        g_M_h[j * WPAD + h] = __float2half(s);
    } else if (i < 66048) {
        int j = i - 65536;
        float s = 0.f;
#pragma unroll 4
        for (int o = 0; o < 128; o++) s += e2b[o] * wih[j * 128 + o];
        g_bxg[j] = s;
    } else if (i < 135680) {
        int p = i - 66048;
        int j = p / WPAD, k = p % WPAD;
        g_whh_h[p] = (k < 128) ? __float2half(whh[j * 128 + k]) : __float2half(0.f);
    } else if (i < 169472) {
        int p = i - 135680;
        int j = p / 264, k = p % 264;
        g_dec1h[p] = (k < 256) ? __float2half(dec1[j * 256 + k]) : __float2half(0.f);
    }
}

// ---------------- K1: encoder (persistent, tensor-core, 256 threads) — unchanged ----------------
#define ENC_OFF_AHI 139264
#define ENC_OFF_BXG 156672
#define ENC_OFF_E1W 158720
#define ENC_OFF_E1B 159744
#define ENC_SMEM    160256
__global__ __launch_bounds__(256, 1) void encoder_kernel(
    const float* __restrict__ x, const float* __restrict__ e1w,
    const float* __restrict__ e1b) {
    extern __shared__ char smraw[];
    __half* sM   = (__half*)smraw;
    __half* sAhi = (__half*)(smraw + ENC_OFF_AHI);
    float*  sBxg = (float*)(smraw + ENC_OFF_BXG);
    float*  sE1w = (float*)(smraw + ENC_OFF_E1W);
    float*  sE1b = (float*)(smraw + ENC_OFF_E1B);

    int tid = threadIdx.x, w = tid >> 5, l = tid & 31;

    for (int i = tid; i < 8704; i += 256) cp16(((uint4*)sM) + i, ((const uint4*)g_M_h) + i);
    cp_commit();
    for (int i = tid; i < 512; i += 256) sBxg[i] = g_bxg[i];
    if (tid < 256) sE1w[tid] = e1w[tid];
    if (tid < 128) sE1b[tid] = e1b[tid];
    cp_wait0();
    __syncthreads();

    const int lrow = (l & 7) + ((l >> 3) & 1) * 8;
    const int lcol = (l >> 4) * 8;
    const int jw = w * 64;
    const int g = l >> 2, tg = l & 3;
    uint32_t sMb   = (uint32_t)__cvta_generic_to_shared(sM);
    uint32_t sAhib = (uint32_t)__cvta_generic_to_shared(sAhi);

    const int fr = tid >> 2, fh0 = (tid & 3) * 32;

    for (int blk = blockIdx.x; blk < NTT / 64; blk += gridDim.x) {
        int row0 = blk * 64;
        float x0 = x[(size_t)(row0 + fr) * 2];
        float x1 = x[(size_t)(row0 + fr) * 2 + 1];
#pragma unroll
        for (int hh = 0; hh < 32; hh += 2) {
            int h = fh0 + hh;
            float v0 = fmaxf(sE1w[2 * h]     * x0 + sE1w[2 * h + 1] * x1 + sE1b[h], 0.f);
            float v1 = fmaxf(sE1w[2 * h + 2] * x0 + sE1w[2 * h + 3] * x1 + sE1b[h + 1], 0.f);
            *(__half2*)&sAhi[fr * WPAD + h] = __floats2half2_rn(v0, v1);
        }
        __syncthreads();

#pragma unroll
        for (int mt = 0; mt < 4; mt++) {
            float d[8][4];
#pragma unroll
            for (int nt = 0; nt < 8; nt++)
#pragma unroll
                for (int e = 0; e < 4; e++) d[nt][e] = 0.f;
#pragma unroll
            for (int ks = 0; ks < 8; ks++) {
                uint32_t aoff = (uint32_t)(((mt * 16 + lrow) * WPAD + ks * 16 + lcol) << 1);
                uint32_t ah0, ah1, ah2, ah3;
                ldsm4(sAhib + aoff, ah0, ah1, ah2, ah3);
#pragma unroll
                for (int np = 0; np < 4; np++) {
                    uint32_t boff = (uint32_t)(((jw + np * 16 + lrow) * WPAD + ks * 16 + lcol) << 1);
                    uint32_t b0, b1, b2, b3;
                    ldsm4(sMb + boff, b0, b1, b2, b3);
                    mma16816(d[2 * np],     ah0, ah1, ah2, ah3, b0, b2);
                    mma16816(d[2 * np + 1], ah0, ah1, ah2, ah3, b1, b3);
                }
            }
            size_t rb0 = (size_t)(row0 + mt * 16 + g) * 512;
            size_t rb1 = rb0 + (size_t)8 * 512;
#pragma unroll
            for (int nt = 0; nt < 8; nt++) {
                int col = jw + nt * 8 + 2 * tg;
                float b0v = sBxg[col], b1v = sBxg[col + 1];
                *(__half2*)&g_xg[rb0 + col] = __floats2half2_rn(d[nt][0] + b0v, d[nt][1] + b1v);
                *(__half2*)&g_xg[rb1 + col] = __floats2half2_rn(d[nt][2] + b0v, d[nt][3] + b1v);
            }
        }
        __syncthreads();
    }
}

// ---------------- K2: bidirectional LSTM — 512 threads, 16 warps, reg-resident W ----------------
// smem: sW 139264 | sH 2x4352 | sXG 3x16640 ([16][520] half) | sRelu 2x4352
#define REC_OFF_H    139264
#define REC_HBUF     4352
#define REC_OFF_XG   (REC_OFF_H + 2 * REC_HBUF)          // 147968
#define REC_XGBUF    16640
#define SXG_STRIDE   520
#define REC_OFF_RELU (REC_OFF_XG + 3 * REC_XGBUF)        // 197888
#define REC_RELUBUF  4352
#define REC_SMEM     (REC_OFF_RELU + 2 * REC_RELUBUF)    // 206592

__device__ __forceinline__ void lstm_xg_load(char* smraw, int buf, int n0, int t, int tid) {
    __half* dst = (__half*)(smraw + REC_OFF_XG + buf * REC_XGBUF);
#pragma unroll
    for (int it = 0; it < 2; it++) {
        int idx = it * 512 + tid;
        int r = idx >> 6, ck = idx & 63;
        cp16(dst + r * SXG_STRIDE + ck * 8,
             g_xg + ((size_t)(n0 + r) * Tt + t) * 512 + ck * 8);
    }
}

__global__ __launch_bounds__(512, 1) void lstm_kernel() {
    extern __shared__ char smraw[];
    __half* sW = (__half*)smraw;

    int tid = threadIdx.x;
    int w = tid >> 5, l = tid & 31;
    int dir = blockIdx.x & 1;
    int n0 = (blockIdx.x >> 1) * 16;

    {
        const uint4* src = (const uint4*)g_whh_h;
        uint4* dst = (uint4*)sW;
        for (int i = tid; i < 8704; i += 512) dst[i] = src[i];
    }
    for (int i = tid; i < 1088; i += 512) ((uint32_t*)(smraw + REC_OFF_H))[i] = 0u;

    const int lrow = (l & 7) + ((l >> 3) & 1) * 8;
    const int lcol = (l >> 4) * 8;
    const int g = l >> 2, tg = l & 3;
    const int wband = w * 8;     // 16 warps x 8 hidden cols

    uint32_t sWb = (uint32_t)__cvta_generic_to_shared(sW);
    uint32_t sHb = (uint32_t)__cvta_generic_to_shared(smraw + REC_OFF_H);

    const int sr = tid >> 5, sck = tid & 31;   // relu STG: 16 rows x 32 8B-chunks

    float c[2][2];
#pragma unroll
    for (int r2 = 0; r2 < 2; r2++) { c[r2][0] = 0.f; c[r2][1] = 0.f; }

    // prologue: prefetch xg for steps 0 and 1
    lstm_xg_load(smraw, 0, n0, dir ? 511 : 0, tid);
    cp_commit();
    lstm_xg_load(smraw, 1, n0, dir ? 510 : 1, tid);
    cp_commit();
    cp_wait1();
    __syncthreads();   // W, h0, sXG[0] all visible

    // hoist W_hh fragments: warp's 8-col band = half of a 16-col ldsm4 pair
    // pair base covers cols [(w>>1)*16, +16); even warp keeps (r0,r2), odd keeps (r1,r3)
    uint32_t bf[4][8][2];
#pragma unroll
    for (int ks = 0; ks < 8; ks++) {
        int k0 = ks * 16;
#pragma unroll
        for (int gate = 0; gate < 4; gate++) {
            int j0p = gate * 128 + (w >> 1) * 16;
            uint32_t r0, r1, r2, r3;
            ldsm4(sWb + (uint32_t)(((j0p + lrow) * WPAD + k0 + lcol) << 1), r0, r1, r2, r3);
            if (w & 1) { bf[gate][ks][0] = r1; bf[gate][ks][1] = r3; }
            else       { bf[gate][ks][0] = r0; bf[gate][ks][1] = r2; }
        }
    }

    for (int step = 0; step < 512; step++) {
        int t = dir ? (511 - step) : step;

        // 1) coalesced STG of relu(h) for step-1 (16 rows x 256B, 8B per thread)
        if (step > 0) {
            int tp = dir ? (512 - step) : (step - 1);
            const __half* src =
                (const __half*)(smraw + REC_OFF_RELU + ((step + 1) & 1) * REC_RELUBUF);
            uint2 v = *(const uint2*)&src[sr * WPAD + sck * 4];
            *(uint2*)&g_hcat[((size_t)(n0 + sr) * Tt + tp) * 256 + dir * 128 + sck * 4] = v;
        }

        // 2) prefetch xg for step+2
        if (step + 2 < 512) {
            int tn = dir ? (509 - step) : (step + 2);
            lstm_xg_load(smraw, (step + 2) % 3, n0, tn, tid);
        }
        cp_commit();   // uniform group count even when empty

        // 3) MMA: gates = h @ W^T; B in registers; 8-col band per warp
        uint32_t hcur = sHb + (uint32_t)(step & 1) * REC_HBUF;
        float d[4][4];
#pragma unroll
        for (int gate = 0; gate < 4; gate++)
#pragma unroll
            for (int e = 0; e < 4; e++) d[gate][e] = 0.f;

#pragma unroll
        for (int ks = 0; ks < 8; ks++) {
            int k0 = ks * 16;
            uint32_t ah0, ah1, ah2, ah3;
            ldsm4(hcur + (uint32_t)((lrow * WPAD + k0 + lcol) << 1), ah0, ah1, ah2, ah3);
#pragma unroll
            for (int gate = 0; gate < 4; gate++)
                mma16816(d[gate], ah0, ah1, ah2, ah3, bf[gate][ks][0], bf[gate][ks][1]);
        }

        // 4) activation: 4 units per thread (rows g, g+8; cols wband+2tg, +1)
        const __half* sxg = (const __half*)(smraw + REC_OFF_XG + (step % 3) * REC_XGBUF);
        __half* hnxt = (__half*)(smraw + REC_OFF_H + ((step + 1) & 1) * REC_HBUF);
        __half* srel = (__half*)(smraw + REC_OFF_RELU + (step & 1) * REC_RELUBUF);

#pragma unroll
        for (int r2 = 0; r2 < 2; r2++) {
            int m = g + r2 * 8;
            int col = wband + 2 * tg;
            float2 xi  = __half22float2(*(const __half2*)&sxg[m * SXG_STRIDE + col]);
            float2 xf  = __half22float2(*(const __half2*)&sxg[m * SXG_STRIDE + 128 + col]);
            float2 xgg = __half22float2(*(const __half2*)&sxg[m * SXG_STRIDE + 256 + col]);
            float2 xo  = __half22float2(*(const __half2*)&sxg[m * SXG_STRIDE + 384 + col]);
            float hv[2];
#pragma unroll
            for (int e = 0; e < 2; e++) {
                int fe = r2 * 2 + e;
                float iv = d[0][fe] + ((const float*)&xi)[e];
                float fv = d[1][fe] + ((const float*)&xf)[e];
                float gv = d[2][fe] + ((const float*)&xgg)[e];
                float ov = d[3][fe] + ((const float*)&xo)[e];
                float cn = sigm_a(fv) * c[r2][e] + sigm_a(iv) * tanh_a(gv);
                c[r2][e] = cn;
                hv[e] = sigm_a(ov) * tanh_a(cn);
            }
            *(__half2*)&hnxt[m * WPAD + col] = __floats2half2_rn(hv[0], hv[1]);
            *(__half2*)&srel[m * WPAD + col] =
                __floats2half2_rn(fmaxf(hv[0], 0.f), fmaxf(hv[1], 0.f));
        }

        // 5) drain step+1's cp group, then the single per-step barrier
        cp_wait1();
        __syncthreads();
    }

    // final relu tile (step 511)
    {
        int tp = dir ? 0 : 511;
        const __half* src = (const __half*)(smraw + REC_OFF_RELU + 1 * REC_RELUBUF);
        uint2 v = *(const uint2*)&src[sr * WPAD + sck * 4];
        *(uint2*)&g_hcat[((size_t)(n0 + sr) * Tt + tp) * 256 + dir * 128 + sck * 4] = v;
    }
}

// ---------------- K3: decoder (persistent, tensor-core, direct fp16 tiles) — unchanged ----------------
#define DEC_OFF_T0  67584
#define DEC_TBUF    33792
#define DEC_OFF_PART (DEC_OFF_T0 + 2 * DEC_TBUF)
#define DEC_SMEM    (DEC_OFF_PART + 64 * 17 * 4)

__device__ __forceinline__ void dec_load_tile(char* smraw, int buf, int blk, int tid) {
    __half* dst = (__half*)(smraw + DEC_OFF_T0 + buf * DEC_TBUF);
    size_t row0 = (size_t)blk * 64;
#pragma unroll
    for (int it = 0; it < 16; it++) {
        int idx = it * 128 + tid;
        int r = idx >> 5, ck = idx & 31;
        cp16(dst + r * 264 + ck * 8, g_hcat + (row0 + r) * 256 + ck * 8);
    }
}

__global__ __launch_bounds__(128, 1) void decoder_kernel(
    const float* __restrict__ d1b, const float* __restrict__ d2w,
    const float* __restrict__ d2b, float* __restrict__ out) {
    extern __shared__ char smraw[];
    __half* sB = (__half*)smraw;
    float* sPart = (float*)(smraw + DEC_OFF_PART);

    int tid = threadIdx.x, w = tid >> 5, l = tid & 31;

    for (int i = tid; i < 4224; i += 128) cp16(((uint4*)sB) + i, ((const uint4*)g_dec1h) + i);
    cp_commit();

    const int lrow = (l & 7) + ((l >> 3) & 1) * 8;
    const int lcol = (l >> 4) * 8;
    const int jw = w * 32;
    const int g = l >> 2, tg = l & 3;
    uint32_t sBb = (uint32_t)__cvta_generic_to_shared(sB);
    uint32_t sTb = (uint32_t)__cvta_generic_to_shared(smraw + DEC_OFF_T0);

    float b1v[4][2], w2v[4][2];
#pragma unroll
    for (int nt = 0; nt < 4; nt++)
#pragma unroll
        for (int e = 0; e < 2; e++) {
            int col = jw + nt * 8 + 2 * tg + e;
            b1v[nt][e] = d1b[col];
            w2v[nt][e] = d2w[col];
        }
    float outb = d2b[0];
    cp_wait0();

    int blk = blockIdx.x;
    int buf = 0;
    dec_load_tile(smraw, buf, blk, tid);
    cp_commit();

    for (; blk < NTT / 64; blk += gridDim.x) {
        int nxt = blk + gridDim.x;
        if (nxt < NTT / 64) {
            dec_load_tile(smraw, buf ^ 1, nxt, tid);
            cp_commit();
            cp_wait1();
        } else {
            cp_wait0();
        }
        __syncthreads();

        uint32_t sAb = sTb + (uint32_t)buf * DEC_TBUF;
        int row0 = blk * 64;
#pragma unroll
        for (int mt = 0; mt < 4; mt++) {
            float d[4][4];
#pragma unroll
            for (int nt = 0; nt < 4; nt++)
#pragma unroll
                for (int e = 0; e < 4; e++) d[nt][e] = 0.f;
#pragma unroll
            for (int ks = 0; ks < 16; ks++) {
                uint32_t aoff = (uint32_t)(((mt * 16 + lrow) * 264 + ks * 16 + lcol) << 1);
                uint32_t ah0, ah1, ah2, ah3;
                ldsm4(sAb + aoff, ah0, ah1, ah2, ah3);
#pragma unroll
                for (int np = 0; np < 2; np++) {
                    uint32_t boff = (uint32_t)(((jw + np * 16 + lrow) * 264 + ks * 16 + lcol) << 1);
                    uint32_t b0, b1, b2, b3;
                    ldsm4(sBb + boff, b0, b1, b2, b3);
                    mma16816(d[2 * np],     ah0, ah1, ah2, ah3, b0, b2);
                    mma16816(d[2 * np + 1], ah0, ah1, ah2, ah3, b1, b3);
                }
            }
            float p0 = 0.f, p1 = 0.f;
#pragma unroll
            for (int nt = 0; nt < 4; nt++) {
                p0 += fmaxf(d[nt][0] + b1v[nt][0], 0.f) * w2v[nt][0];
                p0 += fmaxf(d[nt][1] + b1v[nt][1], 0.f) * w2v[nt][1];
                p1 += fmaxf(d[nt][2] + b1v[nt][0], 0.f) * w2v[nt][0];
                p1 += fmaxf(d[nt][3] + b1v[nt][1], 0.f) * w2v[nt][1];
            }
            sPart[(mt * 16 + g) * 17 + w * 4 + tg]     = p0;
            sPart[(mt * 16 + g + 8) * 17 + w * 4 + tg] = p1;
        }
        __syncthreads();

        if (tid < 64) {
            float s = 0.f;
#pragma unroll
            for (int q = 0; q < 16; q++) s += sPart[tid * 17 + q];
            out[row0 + tid] = s + outb;
        }
        __syncthreads();
        buf ^= 1;
    }
}

// ---------------- launch ----------------
extern "C" void kernel_launch(void* const* d_in, const int* in_sizes, int n_in,
                              void* d_out, int out_size) {
    (void)in_sizes; (void)n_in; (void)out_size;
    const float* x    = (const float*)d_in[0];
    const float* e1w  = (const float*)d_in[1];
    const float* e1b  = (const float*)d_in[2];
    const float* e2w  = (const float*)d_in[3];
    const float* e2b  = (const float*)d_in[4];
    const float* wih  = (const float*)d_in[5];
    const float* whh  = (const float*)d_in[6];
    const float* d1w  = (const float*)d_in[7];
    const float* d1b  = (const float*)d_in[8];
    const float* d2w  = (const float*)d_in[9];
    const float* d2b  = (const float*)d_in[10];
    float* out = (float*)d_out;

    static bool attr_done = false;
    if (!attr_done) {
        cudaFuncSetAttribute(encoder_kernel, cudaFuncAttributeMaxDynamicSharedMemorySize, ENC_SMEM);
        cudaFuncSetAttribute(lstm_kernel, cudaFuncAttributeMaxDynamicSharedMemorySize, REC_SMEM);
        cudaFuncSetAttribute(decoder_kernel, cudaFuncAttributeMaxDynamicSharedMemorySize, DEC_SMEM);
        attr_done = true;
    }

    prep_kernel<<<662, 256>>>(wih, whh, e2w, e2b, d1w);
    encoder_kernel<<<148, 256, ENC_SMEM>>>(x, e1w, e1b);
    lstm_kernel<<<128, 512, REC_SMEM>>>();
    decoder_kernel<<<148, 128, DEC_SMEM>>>(d1b, d2w, d2b, out);
}